// round 1
// baseline (speedup 1.0000x reference)
#include <cuda_runtime.h>
#include <math.h>

// Problem dims
#define B_SZ 128
#define L_SZ 16
#define N_SZ 20000
#define HIN  512
#define H_SZ 1024
#define HT   128
#define G4   4096   // 4*H
#define ML   2048   // B*L

// ---------------- scratch (device globals; no cudaMalloc allowed) -----------
__device__ float g_vd[ML * HIN];        // 4 MB
__device__ float g_inputs[ML * HIN];    // 4 MB
__device__ float g_xg[ML * G4];         // 32 MB: xg[(b*16+l)*4096 + g]
__device__ float g_gates[B_SZ * G4];    // 2 MB
__device__ float g_h[B_SZ * H_SZ];
__device__ float g_c[B_SZ * H_SZ];
__device__ float g_u[HIN];
__device__ float g_ub[HIN];
__device__ float g_bias[G4];            // b_ih + b_hh

// ---------------- prep: fold time-embed + biases ---------------------------
__global__ void prep_kernel(const float* __restrict__ Wvt,
                            const float* __restrict__ wtw,
                            const float* __restrict__ wtb,
                            const float* __restrict__ bih,
                            const float* __restrict__ bhh) {
    int i = blockIdx.x * blockDim.x + threadIdx.x;
    if (i < HIN) {
        const float* row = Wvt + (size_t)i * (HIN + HT) + HIN;
        float u = 0.f, ub = 0.f;
        #pragma unroll 4
        for (int j = 0; j < HT; j++) {
            float w = row[j];
            u  += w * wtw[j];
            ub += w * wtb[j];
        }
        g_u[i]  = u;
        g_ub[i] = ub;
    } else if (i < HIN + G4) {
        int g = i - HIN;
        g_bias[g] = bih[g] + bhh[g];
    }
}

// ---------------- generic NT SGEMM: C[m,n] = sum_k A[m,k]*B[n,k] + epilogue -
// Epilogue terms (any may be null):
//   bias[n], srow[m]*ucol[n], eadd[m*estride + n]
template<int BM, int BN, int BK, int TM, int TN>
__global__ void sgemm_nt(const float* __restrict__ A, int lda,
                         const float* __restrict__ Bm, int ldb,
                         float* __restrict__ C, int ldc, int K,
                         const float* __restrict__ bias,
                         const float* __restrict__ srow,
                         const float* __restrict__ ucol,
                         const float* __restrict__ eadd, int estride)
{
    constexpr int NT = (BM / TM) * (BN / TN);     // threads per block
    constexpr int RA = BM * BK / NT;              // A regs staged per thread
    constexpr int RB = BN * BK / NT;              // B regs staged per thread

    __shared__ float As[BK][BM + 1];
    __shared__ float Bs[BK][BN + 1];

    const int tid = threadIdx.x;
    const int m0  = blockIdx.y * BM;
    const int n0  = blockIdx.x * BN;
    const int tx  = tid % (BN / TN);
    const int ty  = tid / (BN / TN);

    float acc[TM][TN];
    #pragma unroll
    for (int i = 0; i < TM; i++)
        #pragma unroll
        for (int j = 0; j < TN; j++) acc[i][j] = 0.f;

    float ra[RA], rb[RB];

    // prologue fetch (k0 = 0)
    #pragma unroll
    for (int q = 0; q < RA; q++) {
        int i = tid + q * NT; int r = i / BK, kk = i % BK;
        ra[q] = A[(size_t)(m0 + r) * lda + kk];
    }
    #pragma unroll
    for (int q = 0; q < RB; q++) {
        int i = tid + q * NT; int r = i / BK, kk = i % BK;
        rb[q] = Bm[(size_t)(n0 + r) * ldb + kk];
    }

    for (int k0 = 0; k0 < K; k0 += BK) {
        // commit staged regs to smem
        #pragma unroll
        for (int q = 0; q < RA; q++) {
            int i = tid + q * NT; int r = i / BK, kk = i % BK;
            As[kk][r] = ra[q];
        }
        #pragma unroll
        for (int q = 0; q < RB; q++) {
            int i = tid + q * NT; int r = i / BK, kk = i % BK;
            Bs[kk][r] = rb[q];
        }
        __syncthreads();

        // prefetch next tile (overlaps with compute below)
        int kn = k0 + BK;
        if (kn < K) {
            #pragma unroll
            for (int q = 0; q < RA; q++) {
                int i = tid + q * NT; int r = i / BK, kk = i % BK;
                ra[q] = A[(size_t)(m0 + r) * lda + kn + kk];
            }
            #pragma unroll
            for (int q = 0; q < RB; q++) {
                int i = tid + q * NT; int r = i / BK, kk = i % BK;
                rb[q] = Bm[(size_t)(n0 + r) * ldb + kn + kk];
            }
        }

        // compute
        #pragma unroll
        for (int kk = 0; kk < BK; kk++) {
            float a[TM], bb[TN];
            #pragma unroll
            for (int i = 0; i < TM; i++) a[i] = As[kk][ty * TM + i];
            #pragma unroll
            for (int j = 0; j < TN; j++) bb[j] = Bs[kk][tx * TN + j];
            #pragma unroll
            for (int i = 0; i < TM; i++)
                #pragma unroll
                for (int j = 0; j < TN; j++)
                    acc[i][j] += a[i] * bb[j];
        }
        __syncthreads();
    }

    // epilogue
    #pragma unroll
    for (int i = 0; i < TM; i++) {
        int m = m0 + ty * TM + i;
        #pragma unroll
        for (int j = 0; j < TN; j++) {
            int n = n0 + tx * TN + j;
            float v = acc[i][j];
            if (bias) v += bias[n];
            if (srow) v += srow[m] * ucol[n];
            if (eadd) v += eadd[(size_t)m * estride + n];
            C[(size_t)m * ldc + n] = v;
        }
    }
}

// ---------------- LSTM elementwise update ----------------------------------
// gates layout per row (stride rstride): [i(0..H) | f(H..2H) | g(2H..3H) | o(3H..4H)]
__global__ void lstm_update(const float* __restrict__ gsrc, int rstride, int first)
{
    int idx = blockIdx.x * blockDim.x + threadIdx.x;  // 0 .. 128*1024-1
    int b = idx >> 10;
    int j = idx & (H_SZ - 1);
    const float* row = gsrc + (size_t)b * rstride;
    float xi = row[j];
    float xf = row[H_SZ + j];
    float xg = row[2 * H_SZ + j];
    float xo = row[3 * H_SZ + j];
    float ig = 1.f / (1.f + expf(-xi));
    float fg = 1.f / (1.f + expf(-xf));
    float gg = tanhf(xg);
    float og = 1.f / (1.f + expf(-xo));
    float c = first ? (ig * gg) : (fg * g_c[idx] + ig * gg);
    g_c[idx] = c;
    g_h[idx] = og * tanhf(c);
}

// ---------------- final linear head ----------------------------------------
__global__ void pred_kernel(const float* __restrict__ lw,
                            const float* __restrict__ lb,
                            float* __restrict__ out)
{
    int b = blockIdx.x;
    int tid = threadIdx.x;   // 128 threads
    const float* hr = g_h + (size_t)b * H_SZ;
    float s = 0.f;
    for (int k = tid; k < H_SZ; k += 128) s += hr[k] * lw[k];
    __shared__ float red[128];
    red[tid] = s;
    __syncthreads();
    for (int off = 64; off > 0; off >>= 1) {
        if (tid < off) red[tid] += red[tid + off];
        __syncthreads();
    }
    if (tid == 0) out[b] = red[0] + lb[0];
}

// ---------------- launch ----------------------------------------------------
extern "C" void kernel_launch(void* const* d_in, const int* in_sizes, int n_in,
                              void* d_out, int out_size)
{
    const float* v   = (const float*)d_in[0];   // [128,16,20000]
    const float* t   = (const float*)d_in[1];   // [128,16]
    const float* Wd  = (const float*)d_in[2];   // [512,20000]
    const float* wtw = (const float*)d_in[3];   // [128,1]
    const float* wtb = (const float*)d_in[4];   // [128]
    const float* Wvt = (const float*)d_in[5];   // [512,640]
    const float* Wih = (const float*)d_in[6];   // [4096,512]
    const float* Whh = (const float*)d_in[7];   // [4096,1024]
    const float* bih = (const float*)d_in[8];   // [4096]
    const float* bhh = (const float*)d_in[9];   // [4096]
    const float* lw  = (const float*)d_in[10];  // [1,1024]
    const float* lb  = (const float*)d_in[11];  // [1]
    float* out = (float*)d_out;                 // [128,1]

    // resolve device-global scratch addresses
    float *p_vd, *p_inputs, *p_xg, *p_gates, *p_h, *p_u, *p_ub, *p_bias;
    cudaGetSymbolAddress((void**)&p_vd, g_vd);
    cudaGetSymbolAddress((void**)&p_inputs, g_inputs);
    cudaGetSymbolAddress((void**)&p_xg, g_xg);
    cudaGetSymbolAddress((void**)&p_gates, g_gates);
    cudaGetSymbolAddress((void**)&p_h, g_h);
    cudaGetSymbolAddress((void**)&p_u, g_u);
    cudaGetSymbolAddress((void**)&p_ub, g_ub);
    cudaGetSymbolAddress((void**)&p_bias, g_bias);

    // 0) fold time-embed projection + combined bias
    prep_kernel<<<(HIN + G4 + 255) / 256, 256>>>(Wvt, wtw, wtb, bih, bhh);

    // 1) vd[2048,512] = v @ W_down^T   (K = 20000) — the big one
    sgemm_nt<128, 64, 8, 8, 4><<<dim3(HIN / 64, ML / 128), 256>>>(
        v, N_SZ, Wd, N_SZ, p_vd, HIN, N_SZ,
        nullptr, nullptr, nullptr, nullptr, 0);

    // 2) inputs[2048,512] = vd @ W_vt[:, :512]^T + t[m]*u[n] + ub[n]
    sgemm_nt<128, 64, 8, 8, 4><<<dim3(HIN / 64, ML / 128), 256>>>(
        p_vd, HIN, Wvt, HIN + HT, p_inputs, HIN, HIN,
        p_ub, t, p_u, nullptr, 0);

    // 3) xg[2048,4096] = inputs @ W_ih^T + (b_ih + b_hh)
    sgemm_nt<128, 64, 8, 8, 4><<<dim3(G4 / 64, ML / 128), 256>>>(
        p_inputs, HIN, Wih, HIN, p_xg, G4, HIN,
        p_bias, nullptr, nullptr, nullptr, 0);

    // 4) LSTM scan over L=16 steps.
    // Step 0: h=c=0 -> gates are exactly the xg row (no GEMM; c0 never read).
    lstm_update<<<(B_SZ * H_SZ) / 256, 256>>>(p_xg /* l=0 base */, L_SZ * G4, 1);
    for (int l = 1; l < L_SZ; l++) {
        // gates[128,4096] = h @ W_hh^T + xg[:, l, :]
        sgemm_nt<128, 32, 8, 8, 2><<<dim3(G4 / 32, 1), 256>>>(
            p_h, H_SZ, Whh, H_SZ, p_gates, G4, H_SZ,
            nullptr, nullptr, nullptr, p_xg + (size_t)l * G4, L_SZ * G4);
        lstm_update<<<(B_SZ * H_SZ) / 256, 256>>>(p_gates, G4, 0);
    }

    // 5) pred[b] = h @ lin_w^T + lin_b
    pred_kernel<<<B_SZ, 128>>>(lw, lb, out);
}

// round 2
// speedup vs baseline: 1.4488x; 1.4488x over previous
#include <cuda_runtime.h>
#include <math.h>

// Problem dims
#define B_SZ 128
#define L_SZ 16
#define N_SZ 20000
#define HIN  512
#define H_SZ 1024
#define HT   128
#define G4   4096   // 4*H
#define ML   2048   // B*L
#define KSPLIT 5
#define KCHUNK (N_SZ / KSPLIT)   // 4000

// ---------------- scratch (device globals; no cudaMalloc allowed) -----------
__device__ float g_vd[ML * HIN];            // 4 MB
__device__ float g_inputs[ML * HIN];        // 4 MB
__device__ float g_xg[ML * G4];             // 32 MB  xg[(b*16+l)*4096 + g]
__device__ float g_split[KSPLIT * ML * HIN];// 20 MB  split-K partials
__device__ float g_h[2 * B_SZ * H_SZ];      // double-buffered h
__device__ float g_c[B_SZ * H_SZ];
__device__ float g_u[HIN];
__device__ float g_ub[HIN];
__device__ float g_bias[G4];                // b_ih + b_hh

// ---------------- prep: fold time-embed + biases ---------------------------
__global__ void prep_kernel(const float* __restrict__ Wvt,
                            const float* __restrict__ wtw,
                            const float* __restrict__ wtb,
                            const float* __restrict__ bih,
                            const float* __restrict__ bhh) {
    int i = blockIdx.x * blockDim.x + threadIdx.x;
    if (i < HIN) {
        const float* row = Wvt + (size_t)i * (HIN + HT) + HIN;
        float u = 0.f, ub = 0.f;
        #pragma unroll 4
        for (int j = 0; j < HT; j++) {
            float w = row[j];
            u  += w * wtw[j];
            ub += w * wtb[j];
        }
        g_u[i]  = u;
        g_ub[i] = ub;
    } else if (i < HIN + G4) {
        int g = i - HIN;
        g_bias[g] = bih[g] + bhh[g];
    }
}

// ---------------- vectorized NT SGEMM --------------------------------------
// C[m,n] = sum_k A[m,k]*B[n,k]  (+ optional bias[n] + srow[m]*ucol[n])
// Split-K via blockIdx.z: A,B advance z*K elements along k; C advances z*zCStride.
// Requires: M%BM==0, N%BN==0, K%BK==0, lda/ldb/ldc %4==0, TM%4==0, TN%2==0.
template<int BM, int BN, int BK, int TM, int TN>
__global__ void __launch_bounds__((BM / TM) * (BN / TN))
sgemm_v2(const float* __restrict__ A, int lda,
         const float* __restrict__ Bm, int ldb,
         float* __restrict__ C, int ldc, int K,
         size_t zCStride,
         const float* __restrict__ bias,
         const float* __restrict__ srow,
         const float* __restrict__ ucol)
{
    constexpr int NT = (BM / TM) * (BN / TN);
    constexpr int RA = BM * BK / (4 * NT);   // float4 loads per thread (A)
    constexpr int RB = BN * BK / (4 * NT);   // float4 loads per thread (B)
    constexpr int KQ = BK / 4;               // float4 groups per row

    __shared__ float As[BK][BM + 4];
    __shared__ float Bs[BK][BN + 4];

    const int tid = threadIdx.x;
    const int m0  = blockIdx.y * BM;
    const int n0  = blockIdx.x * BN;
    const int tx  = tid % (BN / TN);
    const int ty  = tid / (BN / TN);

    A  += (size_t)blockIdx.z * K;           // split-K chunk offset (within rows)
    Bm += (size_t)blockIdx.z * K;
    C  += (size_t)blockIdx.z * zCStride;

    float acc[TM][TN];
    #pragma unroll
    for (int i = 0; i < TM; i++)
        #pragma unroll
        for (int j = 0; j < TN; j++) acc[i][j] = 0.f;

    float4 ra[RA], rb[RB];

    // prologue fetch (k0 = 0)
    #pragma unroll
    for (int q = 0; q < RA; q++) {
        int i = tid + q * NT; int r = i / KQ, kq = i % KQ;
        ra[q] = *reinterpret_cast<const float4*>(A + (size_t)(m0 + r) * lda + 4 * kq);
    }
    #pragma unroll
    for (int q = 0; q < RB; q++) {
        int i = tid + q * NT; int r = i / KQ, kq = i % KQ;
        rb[q] = *reinterpret_cast<const float4*>(Bm + (size_t)(n0 + r) * ldb + 4 * kq);
    }

    for (int k0 = 0; k0 < K; k0 += BK) {
        #pragma unroll
        for (int q = 0; q < RA; q++) {
            int i = tid + q * NT; int r = i / KQ, kq = i % KQ;
            As[4 * kq + 0][r] = ra[q].x; As[4 * kq + 1][r] = ra[q].y;
            As[4 * kq + 2][r] = ra[q].z; As[4 * kq + 3][r] = ra[q].w;
        }
        #pragma unroll
        for (int q = 0; q < RB; q++) {
            int i = tid + q * NT; int r = i / KQ, kq = i % KQ;
            Bs[4 * kq + 0][r] = rb[q].x; Bs[4 * kq + 1][r] = rb[q].y;
            Bs[4 * kq + 2][r] = rb[q].z; Bs[4 * kq + 3][r] = rb[q].w;
        }
        __syncthreads();

        int kn = k0 + BK;
        if (kn < K) {
            #pragma unroll
            for (int q = 0; q < RA; q++) {
                int i = tid + q * NT; int r = i / KQ, kq = i % KQ;
                ra[q] = *reinterpret_cast<const float4*>(A + (size_t)(m0 + r) * lda + kn + 4 * kq);
            }
            #pragma unroll
            for (int q = 0; q < RB; q++) {
                int i = tid + q * NT; int r = i / KQ, kq = i % KQ;
                rb[q] = *reinterpret_cast<const float4*>(Bm + (size_t)(n0 + r) * ldb + kn + 4 * kq);
            }
        }

        #pragma unroll
        for (int kk = 0; kk < BK; kk++) {
            float a[TM], b[TN];
            #pragma unroll
            for (int i4 = 0; i4 < TM; i4 += 4) {
                float4 t = *reinterpret_cast<const float4*>(&As[kk][ty * TM + i4]);
                a[i4] = t.x; a[i4 + 1] = t.y; a[i4 + 2] = t.z; a[i4 + 3] = t.w;
            }
            if constexpr (TN % 4 == 0) {
                #pragma unroll
                for (int j4 = 0; j4 < TN; j4 += 4) {
                    float4 t = *reinterpret_cast<const float4*>(&Bs[kk][tx * TN + j4]);
                    b[j4] = t.x; b[j4 + 1] = t.y; b[j4 + 2] = t.z; b[j4 + 3] = t.w;
                }
            } else {
                #pragma unroll
                for (int j = 0; j < TN; j++) b[j] = Bs[kk][tx * TN + j];
            }
            #pragma unroll
            for (int i = 0; i < TM; i++)
                #pragma unroll
                for (int j = 0; j < TN; j++)
                    acc[i][j] += a[i] * b[j];
        }
        __syncthreads();
    }

    // epilogue (vectorized stores)
    #pragma unroll
    for (int i = 0; i < TM; i++) {
        int m = m0 + ty * TM + i;
        float vr[TN];
        #pragma unroll
        for (int j = 0; j < TN; j++) {
            int n = n0 + tx * TN + j;
            float v = acc[i][j];
            if (bias) v += bias[n];
            if (srow) v += srow[m] * ucol[n];
            vr[j] = v;
        }
        float* crow = C + (size_t)m * ldc + n0 + tx * TN;
        if constexpr (TN % 4 == 0) {
            #pragma unroll
            for (int j4 = 0; j4 < TN; j4 += 4) {
                float4 t; t.x = vr[j4]; t.y = vr[j4 + 1]; t.z = vr[j4 + 2]; t.w = vr[j4 + 3];
                *reinterpret_cast<float4*>(crow + j4) = t;
            }
        } else {
            #pragma unroll
            for (int j = 0; j < TN; j++) crow[j] = vr[j];
        }
    }
}

// ---------------- split-K reduction -----------------------------------------
__global__ void reduce_split(float* __restrict__ dst)
{
    int idx = blockIdx.x * blockDim.x + threadIdx.x;   // 0 .. ML*HIN-1
    float s = 0.f;
    #pragma unroll
    for (int z = 0; z < KSPLIT; z++) s += g_split[(size_t)z * ML * HIN + idx];
    dst[idx] = s;
}

// ---------------- initial LSTM update (h=c=0 -> gates = xg row) -------------
__global__ void lstm_update0(const float* __restrict__ gsrc, float* __restrict__ hout)
{
    int idx = blockIdx.x * blockDim.x + threadIdx.x;  // 0 .. 128*1024-1
    int b = idx >> 10;
    int j = idx & (H_SZ - 1);
    const float* row = gsrc + (size_t)b * (L_SZ * G4);
    float xi = row[j];
    float xf = row[H_SZ + j];          (void)xf;   // f gate unused when c0 = 0
    float xg = row[2 * H_SZ + j];
    float xo = row[3 * H_SZ + j];
    float ig = 1.f / (1.f + expf(-xi));
    float gg = tanhf(xg);
    float og = 1.f / (1.f + expf(-xo));
    float c = ig * gg;
    g_c[idx] = c;
    hout[idx] = og * tanhf(c);
}

// ---------------- fused LSTM step: gates GEMM + nonlinearity + state update -
// grid = 128 CTAs, each handles 8 h-indices (j0..j0+7) across all 4 gates.
// gate columns in-tile: c in [0,32): g = c>>3, jj = c&7.
__global__ void __launch_bounds__(256)
lstm_step(const float* __restrict__ hin, float* __restrict__ hout,
          const float* __restrict__ Whh, const float* __restrict__ xgl)
{
    __shared__ float As[16][128 + 4];
    __shared__ float Bs[16][32 + 4];
    __shared__ float sg[128][33];

    const int tid = threadIdx.x;
    const int j0  = blockIdx.x * 8;
    const int tx  = tid & 15;   // 16 groups of TN=2 cols
    const int ty  = tid >> 4;   // 16 groups of TM=8 rows

    float acc[8][2];
    #pragma unroll
    for (int i = 0; i < 8; i++) { acc[i][0] = 0.f; acc[i][1] = 0.f; }

    float4 ra[2], rb;
    const int bc = tid >> 2, bkq = tid & 3;          // for tid<128: B loader
    const float* brow = Whh + ((size_t)((bc >> 3) << 10) + j0 + (bc & 7)) * H_SZ;

    // prologue
    #pragma unroll
    for (int q = 0; q < 2; q++) {
        int i = tid + q * 256; int r = i >> 2, kq = i & 3;
        ra[q] = *reinterpret_cast<const float4*>(hin + (size_t)r * H_SZ + 4 * kq);
    }
    if (tid < 128) rb = *reinterpret_cast<const float4*>(brow + 4 * bkq);

    for (int k0 = 0; k0 < H_SZ; k0 += 16) {
        #pragma unroll
        for (int q = 0; q < 2; q++) {
            int i = tid + q * 256; int r = i >> 2, kq = i & 3;
            As[4 * kq + 0][r] = ra[q].x; As[4 * kq + 1][r] = ra[q].y;
            As[4 * kq + 2][r] = ra[q].z; As[4 * kq + 3][r] = ra[q].w;
        }
        if (tid < 128) {
            Bs[4 * bkq + 0][bc] = rb.x; Bs[4 * bkq + 1][bc] = rb.y;
            Bs[4 * bkq + 2][bc] = rb.z; Bs[4 * bkq + 3][bc] = rb.w;
        }
        __syncthreads();

        int kn = k0 + 16;
        if (kn < H_SZ) {
            #pragma unroll
            for (int q = 0; q < 2; q++) {
                int i = tid + q * 256; int r = i >> 2, kq = i & 3;
                ra[q] = *reinterpret_cast<const float4*>(hin + (size_t)r * H_SZ + kn + 4 * kq);
            }
            if (tid < 128) rb = *reinterpret_cast<const float4*>(brow + kn + 4 * bkq);
        }

        #pragma unroll
        for (int kk = 0; kk < 16; kk++) {
            const float4* ap = reinterpret_cast<const float4*>(&As[kk][ty * 8]);
            float4 a0 = ap[0], a1 = ap[1];
            float b0 = Bs[kk][tx * 2], b1 = Bs[kk][tx * 2 + 1];
            float av[8] = {a0.x, a0.y, a0.z, a0.w, a1.x, a1.y, a1.z, a1.w};
            #pragma unroll
            for (int i = 0; i < 8; i++) {
                acc[i][0] += av[i] * b0;
                acc[i][1] += av[i] * b1;
            }
        }
        __syncthreads();
    }

    // stage pre-activations (+ xg) in smem
    #pragma unroll
    for (int i = 0; i < 8; i++) {
        int m = ty * 8 + i;
        #pragma unroll
        for (int j = 0; j < 2; j++) {
            int c = tx * 2 + j;
            int g = c >> 3, jj = c & 7;
            sg[m][c] = acc[i][j] +
                       xgl[(size_t)m * (L_SZ * G4) + (g << 10) + j0 + jj];
        }
    }
    __syncthreads();

    // cell update: 4 cells per thread
    #pragma unroll
    for (int q = 0; q < 4; q++) {
        int cell = tid + q * 256;          // 0..1023
        int m = cell >> 3, jj = cell & 7;
        float xi = sg[m][jj];
        float xf = sg[m][8 + jj];
        float xgv = sg[m][16 + jj];
        float xo = sg[m][24 + jj];
        float ig = 1.f / (1.f + expf(-xi));
        float fg = 1.f / (1.f + expf(-xf));
        float gg = tanhf(xgv);
        float og = 1.f / (1.f + expf(-xo));
        int gi = (m << 10) + j0 + jj;
        float cv = fg * g_c[gi] + ig * gg;
        g_c[gi] = cv;
        hout[gi] = og * tanhf(cv);
    }
}

// ---------------- final linear head ----------------------------------------
__global__ void pred_kernel(const float* __restrict__ hfin,
                            const float* __restrict__ lw,
                            const float* __restrict__ lb,
                            float* __restrict__ out)
{
    int b = blockIdx.x;
    int tid = threadIdx.x;   // 128 threads
    const float* hr = hfin + (size_t)b * H_SZ;
    float s = 0.f;
    for (int k = tid; k < H_SZ; k += 128) s += hr[k] * lw[k];
    __shared__ float red[128];
    red[tid] = s;
    __syncthreads();
    for (int off = 64; off > 0; off >>= 1) {
        if (tid < off) red[tid] += red[tid + off];
        __syncthreads();
    }
    if (tid == 0) out[b] = red[0] + lb[0];
}

// ---------------- launch ----------------------------------------------------
extern "C" void kernel_launch(void* const* d_in, const int* in_sizes, int n_in,
                              void* d_out, int out_size)
{
    const float* v   = (const float*)d_in[0];   // [128,16,20000]
    const float* t   = (const float*)d_in[1];   // [128,16]
    const float* Wd  = (const float*)d_in[2];   // [512,20000]
    const float* wtw = (const float*)d_in[3];   // [128,1]
    const float* wtb = (const float*)d_in[4];   // [128]
    const float* Wvt = (const float*)d_in[5];   // [512,640]
    const float* Wih = (const float*)d_in[6];   // [4096,512]
    const float* Whh = (const float*)d_in[7];   // [4096,1024]
    const float* bih = (const float*)d_in[8];   // [4096]
    const float* bhh = (const float*)d_in[9];   // [4096]
    const float* lw  = (const float*)d_in[10];  // [1,1024]
    const float* lb  = (const float*)d_in[11];  // [1]
    float* out = (float*)d_out;                 // [128,1]

    float *p_vd, *p_inputs, *p_xg, *p_split, *p_h, *p_u, *p_ub, *p_bias;
    cudaGetSymbolAddress((void**)&p_vd, g_vd);
    cudaGetSymbolAddress((void**)&p_inputs, g_inputs);
    cudaGetSymbolAddress((void**)&p_xg, g_xg);
    cudaGetSymbolAddress((void**)&p_split, g_split);
    cudaGetSymbolAddress((void**)&p_h, g_h);
    cudaGetSymbolAddress((void**)&p_u, g_u);
    cudaGetSymbolAddress((void**)&p_ub, g_ub);
    cudaGetSymbolAddress((void**)&p_bias, g_bias);

    // 0) fold time-embed projection + combined bias
    prep_kernel<<<(HIN + G4 + 255) / 256, 256>>>(Wvt, wtw, wtb, bih, bhh);

    // 1) split-K GEMM: partials[z] = v[:, zK:(z+1)K] @ W_down[:, zK:(z+1)K]^T
    sgemm_v2<128, 128, 16, 8, 8><<<dim3(HIN / 128, ML / 128, KSPLIT), 256>>>(
        v, N_SZ, Wd, N_SZ, p_split, HIN, KCHUNK,
        (size_t)ML * HIN, nullptr, nullptr, nullptr);
    reduce_split<<<(ML * HIN) / 256, 256>>>(p_vd);

    // 2) inputs = vd @ W_vt[:, :512]^T + t[m]*u[n] + ub[n]
    sgemm_v2<64, 64, 16, 8, 4><<<dim3(HIN / 64, ML / 64, 1), 128>>>(
        p_vd, HIN, Wvt, HIN + HT, p_inputs, HIN, HIN,
        0, p_ub, t, p_u);

    // 3) xg = inputs @ W_ih^T + (b_ih + b_hh)
    sgemm_v2<128, 128, 16, 8, 8><<<dim3(G4 / 128, ML / 128, 1), 256>>>(
        p_inputs, HIN, Wih, HIN, p_xg, G4, HIN,
        0, p_bias, nullptr, nullptr);

    // 4) LSTM scan: h after step l lives in buffer (l&1)
    lstm_update0<<<(B_SZ * H_SZ) / 256, 256>>>(p_xg, p_h /* buf0 */);
    for (int l = 1; l < L_SZ; l++) {
        const float* hin = p_h + (size_t)((l + 1) & 1) * B_SZ * H_SZ;
        float* hout      = p_h + (size_t)(l & 1) * B_SZ * H_SZ;
        lstm_step<<<H_SZ / 8, 256>>>(hin, hout, Whh, p_xg + (size_t)l * G4);
    }

    // 5) pred[b] = h @ lin_w^T + lin_b   (final h in buf1, since L-1=15 is odd)
    pred_kernel<<<B_SZ, 128>>>(p_h + (size_t)B_SZ * H_SZ, lw, lb, out);
}

// round 4
// speedup vs baseline: 2.9675x; 2.0483x over previous
#include <cuda_runtime.h>
#include <cuda_bf16.h>
#include <cstdint>
#include <math.h>

// ---------------- dims ------------------------------------------------------
#define B_SZ 128
#define L_SZ 16
#define N_SZ 20000
#define KPAD 20096          // divisible by 32, 64
#define HIN  512
#define H_SZ 1024
#define G4   4096
#define ML   2048
#define KSPLIT 2
#define KCHUNK (KPAD / KSPLIT)   // 10048 = 314 * 32

// ---------------- device global scratch ------------------------------------
__device__ __nv_bfloat16 g_vh[(size_t)ML * KPAD];
__device__ __nv_bfloat16 g_vl[(size_t)ML * KPAD];
__device__ __nv_bfloat16 g_wdh[(size_t)HIN * KPAD];
__device__ __nv_bfloat16 g_wdl[(size_t)HIN * KPAD];
__device__ float g_split[KSPLIT * ML * HIN];
__device__ __nv_bfloat16 g_vdh[ML * HIN];
__device__ __nv_bfloat16 g_vdl[ML * HIN];
__device__ __nv_bfloat16 g_wvth[HIN * HIN];
__device__ __nv_bfloat16 g_wvtl[HIN * HIN];
__device__ __nv_bfloat16 g_ih[ML * HIN];
__device__ __nv_bfloat16 g_il[ML * HIN];
__device__ __nv_bfloat16 g_wihh[G4 * HIN];
__device__ __nv_bfloat16 g_wihl[G4 * HIN];
__device__ __nv_bfloat16 g_whhh[(size_t)G4 * H_SZ];
__device__ __nv_bfloat16 g_whhl[(size_t)G4 * H_SZ];
__device__ float g_xg[(size_t)ML * G4];               // permuted gate cols
__device__ __nv_bfloat16 g_hh[2 * B_SZ * H_SZ];
__device__ __nv_bfloat16 g_hl[2 * B_SZ * H_SZ];
__device__ float g_h[B_SZ * H_SZ];
__device__ float g_c[B_SZ * H_SZ];
__device__ float g_u[HIN];
__device__ float g_ub[HIN];
__device__ float g_biasp[G4];

// ---------------- helpers ---------------------------------------------------
__device__ __forceinline__ uint32_t smem_u32(const void* p) {
    uint32_t a;
    asm("{ .reg .u64 t; cvta.to.shared.u64 t, %1; cvt.u32.u64 %0, t; }" : "=r"(a) : "l"(p));
    return a;
}
__device__ __forceinline__ void cp_async16(uint32_t dst, const void* src) {
    asm volatile("cp.async.cg.shared.global [%0], [%1], 16;" :: "r"(dst), "l"(src));
}
__device__ __forceinline__ void cp_commit() {
    asm volatile("cp.async.commit_group;" ::: "memory");
}
__device__ __forceinline__ void cp_wait2() {
    asm volatile("cp.async.wait_group 2;" ::: "memory");
}
__device__ __forceinline__ void ldsm4(uint32_t* r, uint32_t addr) {
    asm volatile("ldmatrix.sync.aligned.m8n8.x4.shared.b16 {%0,%1,%2,%3}, [%4];"
        : "=r"(r[0]), "=r"(r[1]), "=r"(r[2]), "=r"(r[3]) : "r"(addr));
}
__device__ __forceinline__ void mma16816(float* c, const uint32_t* a, const uint32_t* b) {
    asm volatile("mma.sync.aligned.m16n8k16.row.col.f32.bf16.bf16.f32 "
        "{%0,%1,%2,%3}, {%4,%5,%6,%7}, {%8,%9}, {%0,%1,%2,%3};"
        : "+f"(c[0]), "+f"(c[1]), "+f"(c[2]), "+f"(c[3])
        : "r"(a[0]), "r"(a[1]), "r"(a[2]), "r"(a[3]), "r"(b[0]), "r"(b[1]));
}
__device__ __forceinline__ float sigf(float x) { return 1.f / (1.f + expf(-x)); }
__device__ __forceinline__ void split_bf16(float x, __nv_bfloat16& hi, __nv_bfloat16& lo) {
    hi = __float2bfloat16(x);
    lo = __float2bfloat16(x - __bfloat162float(hi));
}

// smem tile: [rows][32] bf16, 64B rows; 16B chunk c of row r goes to
// byte offset r*64 + ((c*16) ^ (((r>>1)&3)<<4))  -> 8 distinct 16B slots per
// 8-row group: conflict-free for ldmatrix and the cp.async stores.

// ---------------- tensor-core GEMM via mma.sync -----------------------------
// C[M,N] = (Ah+Al)[M,K] @ (Bh+Bl)[N,K]^T  (3-term bf16 split, fp32 accum)
// MODE 0: fp32 partial to C + z*zstride (split-K over blockIdx.z)
// MODE 1: += srow[m]*ucol[n] + bias[n]; bf16-split out to Ch/Cl
// MODE 2: += bias[n]; fp32 out
// MODE 3: fused LSTM step (gate-permuted cols), updates cstate/hout/hh/hl
template<int BM, int BN, int WM, int WN, int MODE>
__global__ void __launch_bounds__((BM / WM) * (BN / WN) * 32)
mma_gemm(const __nv_bfloat16* __restrict__ Ah, const __nv_bfloat16* __restrict__ Al, int lda,
         const __nv_bfloat16* __restrict__ Bh, const __nv_bfloat16* __restrict__ Bl, int ldb,
         int K,
         float* __restrict__ C, int ldc, size_t zstride,
         const float* __restrict__ bias,
         const float* __restrict__ srow, const float* __restrict__ ucol,
         __nv_bfloat16* __restrict__ Ch, __nv_bfloat16* __restrict__ Cl,
         const float* __restrict__ xgl, int xstride,
         float* __restrict__ cstate, float* __restrict__ hout,
         __nv_bfloat16* __restrict__ hhout, __nv_bfloat16* __restrict__ hlout)
{
    constexpr int NT = (BM / WM) * (BN / WN) * 32;
    constexpr int MF = WM / 16;
    constexpr int NF = WN / 8;
    constexpr int STAGE = (2 * BM + 2 * BN) * 64;    // bytes per stage
    constexpr int CHA = BM * 4;                       // 16B chunks per A array
    constexpr int CHB = BN * 4;
    constexpr int CHT = 2 * CHA + 2 * CHB;

    extern __shared__ char smem[];
    const uint32_t sbase = smem_u32(smem);
    const int tid  = threadIdx.x;
    const int lane = tid & 31;
    const int warp = tid >> 5;
    const int wm0 = (warp / (BN / WN)) * WM;
    const int wn0 = (warp % (BN / WN)) * WN;
    const int m0 = blockIdx.y * BM;
    const int n0 = blockIdx.x * BN;

    if (MODE == 0) {
        Ah += (size_t)blockIdx.z * K;  Al += (size_t)blockIdx.z * K;
        Bh += (size_t)blockIdx.z * K;  Bl += (size_t)blockIdx.z * K;
        C  += (size_t)blockIdx.z * zstride;
    }

    float acc[MF][NF][4];
    #pragma unroll
    for (int i = 0; i < MF; i++)
        #pragma unroll
        for (int j = 0; j < NF; j++)
            #pragma unroll
            for (int q = 0; q < 4; q++) acc[i][j][q] = 0.f;

    auto load_stage = [&](int kt, int s) {
        const int k0 = kt * 32;
        const uint32_t tb = sbase + s * STAGE;
        #pragma unroll
        for (int q = 0; q < CHT / NT; q++) {
            const int i = tid + q * NT;
            const __nv_bfloat16* src;
            int toff, rr;
            if (i < CHA) {
                rr = i >> 2; src = Ah + (size_t)(m0 + rr) * lda; toff = 0;
            } else if (i < 2 * CHA) {
                int j = i - CHA; rr = j >> 2;
                src = Al + (size_t)(m0 + rr) * lda; toff = BM * 64;
            } else if (i < 2 * CHA + CHB) {
                int j = i - 2 * CHA; rr = j >> 2;
                src = Bh + (size_t)(n0 + rr) * ldb; toff = 2 * BM * 64;
            } else {
                int j = i - 2 * CHA - CHB; rr = j >> 2;
                src = Bl + (size_t)(n0 + rr) * ldb; toff = 2 * BM * 64 + BN * 64;
            }
            const int c = i & 3;
            uint32_t dst = tb + toff + rr * 64 + ((c * 16) ^ (((rr >> 1) & 3) << 4));
            cp_async16(dst, src + k0 + c * 8);
        }
    };

    const int KT = K >> 5;
    load_stage(0, 0); cp_commit();
    load_stage(1, 1); cp_commit();

    const int li  = lane & 15;
    const int khb = (lane >> 4) << 4;              // k-half byte offset
    const int swz = ((li >> 1) & 3) << 4;

    for (int kt = 0; kt < KT; kt++) {
        const int s = kt % 3;
        if (kt + 2 < KT) load_stage(kt + 2, (kt + 2) % 3);
        cp_commit();
        cp_wait2();
        __syncthreads();

        const uint32_t tA  = sbase + s * STAGE;
        const uint32_t tAl = tA + BM * 64;
        const uint32_t tBh = tA + 2 * BM * 64;
        const uint32_t tBl = tBh + BN * 64;

        #pragma unroll
        for (int kk = 0; kk < 2; kk++) {
            const int cb = kk * 32;
            const uint32_t coff = (uint32_t)((cb + khb) ^ swz);
            uint32_t ah[MF][4], al_[MF][4];
            #pragma unroll
            for (int mf = 0; mf < MF; mf++) {
                uint32_t ro = (wm0 + mf * 16 + li) * 64 + coff;
                ldsm4(ah[mf],  tA  + ro);
                ldsm4(al_[mf], tAl + ro);
            }
            uint32_t bh[NF][2], bl[NF][2];
            #pragma unroll
            for (int nf2 = 0; nf2 < NF / 2; nf2++) {
                uint32_t ro = (wn0 + nf2 * 16 + li) * 64 + coff;
                uint32_t t[4];
                ldsm4(t, tBh + ro);
                bh[2 * nf2][0] = t[0]; bh[2 * nf2][1] = t[2];
                bh[2 * nf2 + 1][0] = t[1]; bh[2 * nf2 + 1][1] = t[3];
                ldsm4(t, tBl + ro);
                bl[2 * nf2][0] = t[0]; bl[2 * nf2][1] = t[2];
                bl[2 * nf2 + 1][0] = t[1]; bl[2 * nf2 + 1][1] = t[3];
            }
            #pragma unroll
            for (int mf = 0; mf < MF; mf++)
                #pragma unroll
                for (int nf = 0; nf < NF; nf++) {
                    mma16816(acc[mf][nf], ah[mf],  bh[nf]);
                    mma16816(acc[mf][nf], ah[mf],  bl[nf]);
                    mma16816(acc[mf][nf], al_[mf], bh[nf]);
                }
        }
        __syncthreads();
    }

    // ---- epilogue ----
    if (MODE == 3) {
        // thread holds, per (mf, qsel, rowhalf): 4 gates of one cell
        #pragma unroll
        for (int mf = 0; mf < MF; mf++) {
            #pragma unroll
            for (int qsel = 0; qsel < NF / 2; qsel++) {
                const int nb = n0 + wn0 + qsel * 16;
                const int a  = lane & 3;
                const int j  = 4 * (nb >> 4) + a;
                #pragma unroll
                for (int i = 0; i < 2; i++) {
                    const int m = m0 + wm0 + mf * 16 + (lane >> 2) + 8 * i;
                    const float* xrow = xgl + (size_t)m * xstride;
                    float2 xif = *reinterpret_cast<const float2*>(xrow + nb + 2 * a);
                    float2 xgo = *reinterpret_cast<const float2*>(xrow + nb + 8 + 2 * a);
                    float xi = acc[mf][2 * qsel][2 * i]         + xif.x;
                    float xf = acc[mf][2 * qsel][2 * i + 1]     + xif.y;
                    float xg = acc[mf][2 * qsel + 1][2 * i]     + xgo.x;
                    float xo = acc[mf][2 * qsel + 1][2 * i + 1] + xgo.y;
                    float ig = sigf(xi), fg = sigf(xf);
                    float gg = tanhf(xg), og = sigf(xo);
                    const int gi = (m << 10) + j;
                    float cv = fg * cstate[gi] + ig * gg;
                    cstate[gi] = cv;
                    float hv = og * tanhf(cv);
                    hout[gi] = hv;
                    __nv_bfloat16 hi, lo; split_bf16(hv, hi, lo);
                    hhout[gi] = hi; hlout[gi] = lo;
                }
            }
        }
    } else {
        // stage warp tile in smem (reuse pipeline smem), then coalesced out
        float* st = reinterpret_cast<float*>(smem) + warp * (WM * 33);
        #pragma unroll
        for (int mf = 0; mf < MF; mf++)
            #pragma unroll
            for (int nf = 0; nf < NF; nf++)
                #pragma unroll
                for (int i = 0; i < 2; i++) {
                    int r = mf * 16 + (lane >> 2) + 8 * i;
                    int c = nf * 8 + 2 * (lane & 3);
                    st[r * 33 + c]     = acc[mf][nf][2 * i];
                    st[r * 33 + c + 1] = acc[mf][nf][2 * i + 1];
                }
        __syncwarp();
        #pragma unroll
        for (int rr = lane; rr < WM; rr += 32) {
            const int m = m0 + wm0 + rr;
            const int nbase = n0 + wn0;
            if (MODE == 1) {
                const float tm = srow[m];
                #pragma unroll
                for (int c = 0; c < WN; c += 2) {
                    int n = nbase + c;
                    float v0 = st[rr * 33 + c]     + tm * ucol[n]     + bias[n];
                    float v1 = st[rr * 33 + c + 1] + tm * ucol[n + 1] + bias[n + 1];
                    __nv_bfloat16 h0, l0, h1, l1;
                    split_bf16(v0, h0, l0); split_bf16(v1, h1, l1);
                    __nv_bfloat162 ph; ph.x = h0; ph.y = h1;
                    __nv_bfloat162 pl; pl.x = l0; pl.y = l1;
                    *reinterpret_cast<__nv_bfloat162*>(Ch + (size_t)m * ldc + n) = ph;
                    *reinterpret_cast<__nv_bfloat162*>(Cl + (size_t)m * ldc + n) = pl;
                }
            } else {
                #pragma unroll
                for (int c4 = 0; c4 < WN; c4 += 4) {
                    float4 v;
                    v.x = st[rr * 33 + c4];
                    v.y = st[rr * 33 + c4 + 1];
                    v.z = st[rr * 33 + c4 + 2];
                    v.w = st[rr * 33 + c4 + 3];
                    if (MODE == 2) {
                        int n = nbase + c4;
                        v.x += bias[n]; v.y += bias[n + 1];
                        v.z += bias[n + 2]; v.w += bias[n + 3];
                    }
                    *reinterpret_cast<float4*>(C + (size_t)m * ldc + nbase + c4) = v;
                }
            }
        }
    }
}

// ---------------- small kernels ---------------------------------------------
__global__ void conv_split(const float* __restrict__ src, int C, int srcld, int Cp,
                           __nv_bfloat16* __restrict__ dh, __nv_bfloat16* __restrict__ dl)
{
    int c = blockIdx.x * 256 + threadIdx.x;
    int r = blockIdx.y;
    if (c >= Cp) return;
    float x = (c < C) ? src[(size_t)r * srcld + c] : 0.f;
    __nv_bfloat16 hi, lo; split_bf16(x, hi, lo);
    size_t o = (size_t)r * Cp + c;
    dh[o] = hi; dl[o] = lo;
}

// gate permutation: new row r -> orig = gate*1024 + cell,
//   gate = ((r>>3)&1)*2 + (r&1),  cell = 4*(r>>4) + ((r>>1)&3)
__global__ void conv_perm_split(const float* __restrict__ src, int cols,
                                __nv_bfloat16* __restrict__ dh, __nv_bfloat16* __restrict__ dl)
{
    int c = blockIdx.x * 256 + threadIdx.x;
    int r = blockIdx.y;
    int gate = ((r >> 3) & 1) * 2 + (r & 1);
    int cell = 4 * (r >> 4) + ((r >> 1) & 3);
    int orig = gate * 1024 + cell;
    float x = src[(size_t)orig * cols + c];
    __nv_bfloat16 hi, lo; split_bf16(x, hi, lo);
    size_t o = (size_t)r * cols + c;
    dh[o] = hi; dl[o] = lo;
}

__global__ void prep_kernel(const float* __restrict__ Wvt,
                            const float* __restrict__ wtw,
                            const float* __restrict__ wtb,
                            const float* __restrict__ bih,
                            const float* __restrict__ bhh)
{
    int i = blockIdx.x * blockDim.x + threadIdx.x;
    if (i < HIN) {
        const float* row = Wvt + (size_t)i * (HIN + 128) + HIN;
        float u = 0.f, ub = 0.f;
        #pragma unroll 4
        for (int j = 0; j < 128; j++) { float w = row[j]; u += w * wtw[j]; ub += w * wtb[j]; }
        g_u[i] = u; g_ub[i] = ub;
    } else if (i < HIN + G4) {
        int r = i - HIN;
        int gate = ((r >> 3) & 1) * 2 + (r & 1);
        int cell = 4 * (r >> 4) + ((r >> 1) & 3);
        g_biasp[r] = bih[gate * 1024 + cell] + bhh[gate * 1024 + cell];
    }
}

__global__ void reduce_conv(void)
{
    int idx = blockIdx.x * 256 + threadIdx.x;
    float s = g_split[idx] + g_split[ML * HIN + idx];
    __nv_bfloat16 hi, lo; split_bf16(s, hi, lo);
    g_vdh[idx] = hi; g_vdl[idx] = lo;
}

// LSTM step 0 (h=c=0): gates = permuted xg row l=0
__global__ void lstm_step0(void)
{
    int idx = blockIdx.x * 256 + threadIdx.x;     // m*1024 + j
    int m = idx >> 10, j = idx & (H_SZ - 1);
    int q = j >> 2, a = j & 3;
    const float* xrow = g_xg + (size_t)m * (L_SZ * G4);
    float xi = xrow[(q << 4) + 2 * a];
    float xg = xrow[(q << 4) + 8 + 2 * a];
    float xo = xrow[(q << 4) + 8 + 2 * a + 1];
    float c = sigf(xi) * tanhf(xg);
    g_c[idx] = c;
    float hv = sigf(xo) * tanhf(c);
    __nv_bfloat16 hi, lo; split_bf16(hv, hi, lo);
    g_hh[idx] = hi; g_hl[idx] = lo;               // buffer 0
}

__global__ void pred_kernel(const float* __restrict__ lw,
                            const float* __restrict__ lb,
                            float* __restrict__ out)
{
    int b = blockIdx.x, tid = threadIdx.x;
    const float* hr = g_h + (size_t)b * H_SZ;
    float s = 0.f;
    for (int k = tid; k < H_SZ; k += 128) s += hr[k] * lw[k];
    __shared__ float red[128];
    red[tid] = s; __syncthreads();
    for (int off = 64; off > 0; off >>= 1) {
        if (tid < off) red[tid] += red[tid + off];
        __syncthreads();
    }
    if (tid == 0) out[b] = red[0] + lb[0];
}

// ---------------- launch -----------------------------------------------------
#define SMEM_BIG  ((2 * 128 + 2 * 128) * 64 * 3)   // 98304
#define SMEM_LSTM ((2 * 64 + 2 * 64) * 64 * 3)     // 49152

extern "C" void kernel_launch(void* const* d_in, const int* in_sizes, int n_in,
                              void* d_out, int out_size)
{
    const float* v   = (const float*)d_in[0];
    const float* t   = (const float*)d_in[1];
    const float* Wd  = (const float*)d_in[2];
    const float* wtw = (const float*)d_in[3];
    const float* wtb = (const float*)d_in[4];
    const float* Wvt = (const float*)d_in[5];
    const float* Wih = (const float*)d_in[6];
    const float* Whh = (const float*)d_in[7];
    const float* bih = (const float*)d_in[8];
    const float* bhh = (const float*)d_in[9];
    const float* lw  = (const float*)d_in[10];
    const float* lb  = (const float*)d_in[11];
    float* out = (float*)d_out;

    __nv_bfloat16 *p_vh, *p_vl, *p_wdh, *p_wdl, *p_vdh, *p_vdl, *p_wvth, *p_wvtl;
    __nv_bfloat16 *p_ih, *p_il, *p_wihh, *p_wihl, *p_whhh, *p_whhl, *p_hh, *p_hl;
    float *p_split, *p_xg, *p_h, *p_c, *p_u, *p_ub, *p_biasp;
    cudaGetSymbolAddress((void**)&p_vh, g_vh);     cudaGetSymbolAddress((void**)&p_vl, g_vl);
    cudaGetSymbolAddress((void**)&p_wdh, g_wdh);   cudaGetSymbolAddress((void**)&p_wdl, g_wdl);
    cudaGetSymbolAddress((void**)&p_vdh, g_vdh);   cudaGetSymbolAddress((void**)&p_vdl, g_vdl);
    cudaGetSymbolAddress((void**)&p_wvth, g_wvth); cudaGetSymbolAddress((void**)&p_wvtl, g_wvtl);
    cudaGetSymbolAddress((void**)&p_ih, g_ih);     cudaGetSymbolAddress((void**)&p_il, g_il);
    cudaGetSymbolAddress((void**)&p_wihh, g_wihh); cudaGetSymbolAddress((void**)&p_wihl, g_wihl);
    cudaGetSymbolAddress((void**)&p_whhh, g_whhh); cudaGetSymbolAddress((void**)&p_whhl, g_whhl);
    cudaGetSymbolAddress((void**)&p_hh, g_hh);     cudaGetSymbolAddress((void**)&p_hl, g_hl);
    cudaGetSymbolAddress((void**)&p_split, g_split);
    cudaGetSymbolAddress((void**)&p_xg, g_xg);
    cudaGetSymbolAddress((void**)&p_h, g_h);       cudaGetSymbolAddress((void**)&p_c, g_c);
    cudaGetSymbolAddress((void**)&p_u, g_u);       cudaGetSymbolAddress((void**)&p_ub, g_ub);
    cudaGetSymbolAddress((void**)&p_biasp, g_biasp);

    cudaFuncSetAttribute(mma_gemm<128, 128, 64, 32, 0>, cudaFuncAttributeMaxDynamicSharedMemorySize, SMEM_BIG);
    cudaFuncSetAttribute(mma_gemm<128, 128, 64, 32, 1>, cudaFuncAttributeMaxDynamicSharedMemorySize, SMEM_BIG);
    cudaFuncSetAttribute(mma_gemm<128, 128, 64, 32, 2>, cudaFuncAttributeMaxDynamicSharedMemorySize, SMEM_BIG);
    cudaFuncSetAttribute(mma_gemm<64, 64, 32, 32, 3>,   cudaFuncAttributeMaxDynamicSharedMemorySize, SMEM_LSTM);

    // prep + converts
    prep_kernel<<<(HIN + G4 + 255) / 256, 256>>>(Wvt, wtw, wtb, bih, bhh);
    conv_split<<<dim3((KPAD + 255) / 256, ML), 256>>>(v, N_SZ, N_SZ, KPAD, p_vh, p_vl);
    conv_split<<<dim3((KPAD + 255) / 256, HIN), 256>>>(Wd, N_SZ, N_SZ, KPAD, p_wdh, p_wdl);
    conv_split<<<dim3(2, HIN), 256>>>(Wvt, HIN, HIN + 128, HIN, p_wvth, p_wvtl);
    conv_perm_split<<<dim3(2, G4), 256>>>(Wih, HIN, p_wihh, p_wihl);
    conv_perm_split<<<dim3(4, G4), 256>>>(Whh, H_SZ, p_whhh, p_whhl);

    // GEMM1 (split-K): partials = v @ W_down^T
    mma_gemm<128, 128, 64, 32, 0><<<dim3(HIN / 128, ML / 128, KSPLIT), 256, SMEM_BIG>>>(
        p_vh, p_vl, KPAD, p_wdh, p_wdl, KPAD, KCHUNK,
        p_split, HIN, (size_t)ML * HIN,
        nullptr, nullptr, nullptr, nullptr, nullptr,
        nullptr, 0, nullptr, nullptr, nullptr, nullptr);
    reduce_conv<<<(ML * HIN) / 256, 256>>>();

    // GEMM2: inputs = vd @ Wvt_s^T + t[m]*u[n] + ub[n]  -> bf16 split
    mma_gemm<128, 128, 64, 32, 1><<<dim3(HIN / 128, ML / 128), 256, SMEM_BIG>>>(
        p_vdh, p_vdl, HIN, p_wvth, p_wvtl, HIN, HIN,
        nullptr, HIN, 0, p_ub, t, p_u, p_ih, p_il,
        nullptr, 0, nullptr, nullptr, nullptr, nullptr);

    // GEMM3: xg = inputs @ Wih_perm^T + bias_perm (gate-permuted cols)
    mma_gemm<128, 128, 64, 32, 2><<<dim3(G4 / 128, ML / 128), 256, SMEM_BIG>>>(
        p_ih, p_il, HIN, p_wihh, p_wihl, HIN, HIN,
        p_xg, G4, 0, p_biasp, nullptr, nullptr, nullptr, nullptr,
        nullptr, 0, nullptr, nullptr, nullptr, nullptr);

    // LSTM scan
    lstm_step0<<<(B_SZ * H_SZ) / 256, 256>>>();
    for (int l = 1; l < L_SZ; l++) {
        size_t bin  = (size_t)((l + 1) & 1) * B_SZ * H_SZ;
        size_t bout = (size_t)(l & 1) * B_SZ * H_SZ;
        mma_gemm<64, 64, 32, 32, 3><<<dim3(G4 / 64, B_SZ / 64), 128, SMEM_LSTM>>>(
            p_hh + bin, p_hl + bin, H_SZ, p_whhh, p_whhl, H_SZ, H_SZ,
            nullptr, 0, 0, nullptr, nullptr, nullptr, nullptr, nullptr,
            p_xg + (size_t)l * G4, L_SZ * G4, p_c, p_h,
            p_hh + bout, p_hl + bout);
    }

    pred_kernel<<<B_SZ, 128>>>(lw, lb, out);
}

// round 5
// speedup vs baseline: 3.3131x; 1.1164x over previous
#include <cuda_runtime.h>
#include <cuda_bf16.h>
#include <cstdint>
#include <math.h>

// ---------------- dims ------------------------------------------------------
#define B_SZ 128
#define L_SZ 16
#define N_SZ 20000
#define KPAD 20096          // divisible by 32, 64, 4*32
#define HIN  512
#define H_SZ 1024
#define G4   4096
#define ML   2048
#define KSPLIT 4
#define KCHUNK (KPAD / KSPLIT)   // 5024 = 157 * 32

// ---------------- device global scratch ------------------------------------
__device__ __nv_bfloat16 g_vh[(size_t)ML * KPAD];
__device__ __nv_bfloat16 g_vl[(size_t)ML * KPAD];
__device__ __nv_bfloat16 g_wdh[(size_t)HIN * KPAD];
__device__ __nv_bfloat16 g_wdl[(size_t)HIN * KPAD];
__device__ float g_split[KSPLIT * ML * HIN];
__device__ __nv_bfloat16 g_vdh[ML * HIN];
__device__ __nv_bfloat16 g_vdl[ML * HIN];
__device__ __nv_bfloat16 g_wvth[HIN * HIN];
__device__ __nv_bfloat16 g_wvtl[HIN * HIN];
__device__ __nv_bfloat16 g_ih[ML * HIN];
__device__ __nv_bfloat16 g_il[ML * HIN];
__device__ __nv_bfloat16 g_wihh[G4 * HIN];
__device__ __nv_bfloat16 g_wihl[G4 * HIN];
__device__ __nv_bfloat16 g_whhh[(size_t)G4 * H_SZ];
__device__ __nv_bfloat16 g_whhl[(size_t)G4 * H_SZ];
__device__ float g_xg[(size_t)ML * G4];               // permuted gate cols
__device__ __nv_bfloat16 g_hh[2 * B_SZ * H_SZ];
__device__ __nv_bfloat16 g_hl[2 * B_SZ * H_SZ];
__device__ float g_h[B_SZ * H_SZ];
__device__ float g_c[B_SZ * H_SZ];
__device__ float g_u[HIN];
__device__ float g_ub[HIN];
__device__ float g_biasp[G4];
__device__ unsigned g_bar;

// ---------------- helpers ---------------------------------------------------
__device__ __forceinline__ uint32_t smem_u32(const void* p) {
    uint32_t a;
    asm("{ .reg .u64 t; cvta.to.shared.u64 t, %1; cvt.u32.u64 %0, t; }" : "=r"(a) : "l"(p));
    return a;
}
__device__ __forceinline__ void cp_async16(uint32_t dst, const void* src) {
    asm volatile("cp.async.cg.shared.global [%0], [%1], 16;" :: "r"(dst), "l"(src));
}
__device__ __forceinline__ void cp_commit() {
    asm volatile("cp.async.commit_group;" ::: "memory");
}
__device__ __forceinline__ void cp_wait2() {
    asm volatile("cp.async.wait_group 2;" ::: "memory");
}
__device__ __forceinline__ void ldsm4(uint32_t* r, uint32_t addr) {
    asm volatile("ldmatrix.sync.aligned.m8n8.x4.shared.b16 {%0,%1,%2,%3}, [%4];"
        : "=r"(r[0]), "=r"(r[1]), "=r"(r[2]), "=r"(r[3]) : "r"(addr));
}
__device__ __forceinline__ void mma16816(float* c, const uint32_t* a, const uint32_t* b) {
    asm volatile("mma.sync.aligned.m16n8k16.row.col.f32.bf16.bf16.f32 "
        "{%0,%1,%2,%3}, {%4,%5,%6,%7}, {%8,%9}, {%0,%1,%2,%3};"
        : "+f"(c[0]), "+f"(c[1]), "+f"(c[2]), "+f"(c[3])
        : "r"(a[0]), "r"(a[1]), "r"(a[2]), "r"(a[3]), "r"(b[0]), "r"(b[1]));
}
__device__ __forceinline__ float sigf(float x) { return 1.f / (1.f + expf(-x)); }
__device__ __forceinline__ void split_bf16(float x, __nv_bfloat16& hi, __nv_bfloat16& lo) {
    hi = __float2bfloat16(x);
    lo = __float2bfloat16(x - __bfloat162float(hi));
}

// smem tile: [rows][32] bf16, 64B rows; 16B chunk c of row r at
// byte offset r*64 + ((c*16) ^ (((r>>1)&3)<<4)): conflict-free.

// ---------------- tensor-core GEMM via mma.sync -----------------------------
// MODE 0: fp32 partial to C + z*zstride (split-K over blockIdx.z)
// MODE 1: += srow[m]*ucol[n] + bias[n]; bf16-split out to Ch/Cl
// MODE 2: += bias[n]; fp32 out
template<int BM, int BN, int WM, int WN, int MODE>
__global__ void __launch_bounds__((BM / WM) * (BN / WN) * 32)
mma_gemm(const __nv_bfloat16* __restrict__ Ah, const __nv_bfloat16* __restrict__ Al, int lda,
         const __nv_bfloat16* __restrict__ Bh, const __nv_bfloat16* __restrict__ Bl, int ldb,
         int K,
         float* __restrict__ C, int ldc, size_t zstride,
         const float* __restrict__ bias,
         const float* __restrict__ srow, const float* __restrict__ ucol,
         __nv_bfloat16* __restrict__ Ch, __nv_bfloat16* __restrict__ Cl)
{
    constexpr int NT = (BM / WM) * (BN / WN) * 32;
    constexpr int MF = WM / 16;
    constexpr int NF = WN / 8;
    constexpr int STAGE = (2 * BM + 2 * BN) * 64;
    constexpr int CHA = BM * 4;
    constexpr int CHB = BN * 4;
    constexpr int CHT = 2 * CHA + 2 * CHB;

    extern __shared__ char smem[];
    const uint32_t sbase = smem_u32(smem);
    const int tid  = threadIdx.x;
    const int lane = tid & 31;
    const int warp = tid >> 5;
    const int wm0 = (warp / (BN / WN)) * WM;
    const int wn0 = (warp % (BN / WN)) * WN;
    const int m0 = blockIdx.y * BM;
    const int n0 = blockIdx.x * BN;

    if (MODE == 0) {
        Ah += (size_t)blockIdx.z * K;  Al += (size_t)blockIdx.z * K;
        Bh += (size_t)blockIdx.z * K;  Bl += (size_t)blockIdx.z * K;
        C  += (size_t)blockIdx.z * zstride;
    }

    float acc[MF][NF][4];
    #pragma unroll
    for (int i = 0; i < MF; i++)
        #pragma unroll
        for (int j = 0; j < NF; j++)
            #pragma unroll
            for (int q = 0; q < 4; q++) acc[i][j][q] = 0.f;

    auto load_stage = [&](int kt, int s) {
        const int k0 = kt * 32;
        const uint32_t tb = sbase + s * STAGE;
        #pragma unroll
        for (int q = 0; q < CHT / NT; q++) {
            const int i = tid + q * NT;
            const __nv_bfloat16* src;
            int toff, rr;
            if (i < CHA) {
                rr = i >> 2; src = Ah + (size_t)(m0 + rr) * lda; toff = 0;
            } else if (i < 2 * CHA) {
                int j = i - CHA; rr = j >> 2;
                src = Al + (size_t)(m0 + rr) * lda; toff = BM * 64;
            } else if (i < 2 * CHA + CHB) {
                int j = i - 2 * CHA; rr = j >> 2;
                src = Bh + (size_t)(n0 + rr) * ldb; toff = 2 * BM * 64;
            } else {
                int j = i - 2 * CHA - CHB; rr = j >> 2;
                src = Bl + (size_t)(n0 + rr) * ldb; toff = 2 * BM * 64 + BN * 64;
            }
            const int c = i & 3;
            uint32_t dst = tb + toff + rr * 64 + ((c * 16) ^ (((rr >> 1) & 3) << 4));
            cp_async16(dst, src + k0 + c * 8);
        }
    };

    const int KT = K >> 5;
    load_stage(0, 0); cp_commit();
    load_stage(1, 1); cp_commit();

    const int li  = lane & 15;
    const int khb = (lane >> 4) << 4;
    const int swz = ((li >> 1) & 3) << 4;

    for (int kt = 0; kt < KT; kt++) {
        const int s = kt % 3;
        if (kt + 2 < KT) load_stage(kt + 2, (kt + 2) % 3);
        cp_commit();
        cp_wait2();
        __syncthreads();

        const uint32_t tA  = sbase + s * STAGE;
        const uint32_t tAl = tA + BM * 64;
        const uint32_t tBh = tA + 2 * BM * 64;
        const uint32_t tBl = tBh + BN * 64;

        #pragma unroll
        for (int kk = 0; kk < 2; kk++) {
            const int cb = kk * 32;
            const uint32_t coff = (uint32_t)((cb + khb) ^ swz);
            uint32_t ah[MF][4], al_[MF][4];
            #pragma unroll
            for (int mf = 0; mf < MF; mf++) {
                uint32_t ro = (wm0 + mf * 16 + li) * 64 + coff;
                ldsm4(ah[mf],  tA  + ro);
                ldsm4(al_[mf], tAl + ro);
            }
            uint32_t bh[NF][2], bl[NF][2];
            #pragma unroll
            for (int nf2 = 0; nf2 < NF / 2; nf2++) {
                uint32_t ro = (wn0 + nf2 * 16 + li) * 64 + coff;
                uint32_t t[4];
                ldsm4(t, tBh + ro);
                bh[2 * nf2][0] = t[0]; bh[2 * nf2][1] = t[2];
                bh[2 * nf2 + 1][0] = t[1]; bh[2 * nf2 + 1][1] = t[3];
                ldsm4(t, tBl + ro);
                bl[2 * nf2][0] = t[0]; bl[2 * nf2][1] = t[2];
                bl[2 * nf2 + 1][0] = t[1]; bl[2 * nf2 + 1][1] = t[3];
            }
            #pragma unroll
            for (int mf = 0; mf < MF; mf++)
                #pragma unroll
                for (int nf = 0; nf < NF; nf++) {
                    mma16816(acc[mf][nf], ah[mf],  bh[nf]);
                    mma16816(acc[mf][nf], ah[mf],  bl[nf]);
                    mma16816(acc[mf][nf], al_[mf], bh[nf]);
                }
        }
        __syncthreads();
    }

    // ---- epilogue: stage warp tile in smem, coalesced out ----
    float* st = reinterpret_cast<float*>(smem) + warp * (WM * 33);
    #pragma unroll
    for (int mf = 0; mf < MF; mf++)
        #pragma unroll
        for (int nf = 0; nf < NF; nf++)
            #pragma unroll
            for (int i = 0; i < 2; i++) {
                int r = mf * 16 + (lane >> 2) + 8 * i;
                int c = nf * 8 + 2 * (lane & 3);
                st[r * 33 + c]     = acc[mf][nf][2 * i];
                st[r * 33 + c + 1] = acc[mf][nf][2 * i + 1];
            }
    __syncwarp();
    #pragma unroll
    for (int rr = lane; rr < WM; rr += 32) {
        const int m = m0 + wm0 + rr;
        const int nbase = n0 + wn0;
        if (MODE == 1) {
            const float tm = srow[m];
            #pragma unroll
            for (int c = 0; c < WN; c += 2) {
                int n = nbase + c;
                float v0 = st[rr * 33 + c]     + tm * ucol[n]     + bias[n];
                float v1 = st[rr * 33 + c + 1] + tm * ucol[n + 1] + bias[n + 1];
                __nv_bfloat16 h0, l0, h1, l1;
                split_bf16(v0, h0, l0); split_bf16(v1, h1, l1);
                __nv_bfloat162 ph; ph.x = h0; ph.y = h1;
                __nv_bfloat162 pl; pl.x = l0; pl.y = l1;
                *reinterpret_cast<__nv_bfloat162*>(Ch + (size_t)m * ldc + n) = ph;
                *reinterpret_cast<__nv_bfloat162*>(Cl + (size_t)m * ldc + n) = pl;
            }
        } else {
            #pragma unroll
            for (int c4 = 0; c4 < WN; c4 += 4) {
                float4 v;
                v.x = st[rr * 33 + c4];
                v.y = st[rr * 33 + c4 + 1];
                v.z = st[rr * 33 + c4 + 2];
                v.w = st[rr * 33 + c4 + 3];
                if (MODE == 2) {
                    int n = nbase + c4;
                    v.x += bias[n]; v.y += bias[n + 1];
                    v.z += bias[n + 2]; v.w += bias[n + 3];
                }
                *reinterpret_cast<float4*>(C + (size_t)m * ldc + nbase + c4) = v;
            }
        }
    }
}

// ---------------- persistent fused LSTM (steps 1..15, one launch) -----------
// grid (G4/64, B_SZ/64) = (64,2) = 128 CTAs of 128 threads, all resident.
// Device-wide barrier between steps via atomic counter (g_bar, zeroed in prep).
__global__ void __launch_bounds__(128)
lstm_persist(const __nv_bfloat16* __restrict__ hhb, const __nv_bfloat16* __restrict__ hlb,
             const __nv_bfloat16* __restrict__ Bh, const __nv_bfloat16* __restrict__ Bl,
             const float* __restrict__ xg, float* __restrict__ cstate,
             float* __restrict__ houtf,
             __nv_bfloat16* __restrict__ hhw, __nv_bfloat16* __restrict__ hlw)
{
    constexpr int BM = 64, BN = 64, NT = 128, MF = 2, NF = 4;
    constexpr int STAGE = (2 * BM + 2 * BN) * 64;
    constexpr int CHA = BM * 4, CHB = BN * 4, CHT = 2 * CHA + 2 * CHB;

    extern __shared__ char smem[];
    const uint32_t sbase = smem_u32(smem);
    const int tid  = threadIdx.x;
    const int lane = tid & 31;
    const int warp = tid >> 5;
    const int wm0 = (warp >> 1) * 32;
    const int wn0 = (warp & 1) * 32;
    const int m0 = blockIdx.y * BM;
    const int n0 = blockIdx.x * BN;
    const int li  = lane & 15;
    const int khb = (lane >> 4) << 4;
    const int swz = ((li >> 1) & 3) << 4;

    for (int l = 1; l < L_SZ; l++) {
        const __nv_bfloat16* Ah = hhb + (size_t)((l + 1) & 1) * (B_SZ * H_SZ);
        const __nv_bfloat16* Al = hlb + (size_t)((l + 1) & 1) * (B_SZ * H_SZ);
        __nv_bfloat16* Oh = hhw + (size_t)(l & 1) * (B_SZ * H_SZ);
        __nv_bfloat16* Ol = hlw + (size_t)(l & 1) * (B_SZ * H_SZ);
        const float* xgl = xg + (size_t)l * G4;

        float acc[MF][NF][4];
        #pragma unroll
        for (int i = 0; i < MF; i++)
            #pragma unroll
            for (int j = 0; j < NF; j++)
                #pragma unroll
                for (int q = 0; q < 4; q++) acc[i][j][q] = 0.f;

        auto load_stage = [&](int kt, int s) {
            const int k0 = kt * 32;
            const uint32_t tb = sbase + s * STAGE;
            #pragma unroll
            for (int q = 0; q < CHT / NT; q++) {
                const int i = tid + q * NT;
                const __nv_bfloat16* src;
                int toff, rr;
                if (i < CHA) {
                    rr = i >> 2; src = Ah + (size_t)(m0 + rr) * H_SZ; toff = 0;
                } else if (i < 2 * CHA) {
                    int j = i - CHA; rr = j >> 2;
                    src = Al + (size_t)(m0 + rr) * H_SZ; toff = BM * 64;
                } else if (i < 2 * CHA + CHB) {
                    int j = i - 2 * CHA; rr = j >> 2;
                    src = Bh + (size_t)(n0 + rr) * H_SZ; toff = 2 * BM * 64;
                } else {
                    int j = i - 2 * CHA - CHB; rr = j >> 2;
                    src = Bl + (size_t)(n0 + rr) * H_SZ; toff = 2 * BM * 64 + BN * 64;
                }
                const int c = i & 3;
                uint32_t dst = tb + toff + rr * 64 + ((c * 16) ^ (((rr >> 1) & 3) << 4));
                cp_async16(dst, src + k0 + c * 8);
            }
        };

        const int KT = H_SZ >> 5;   // 32
        load_stage(0, 0); cp_commit();
        load_stage(1, 1); cp_commit();

        for (int kt = 0; kt < KT; kt++) {
            const int s = kt % 3;
            if (kt + 2 < KT) load_stage(kt + 2, (kt + 2) % 3);
            cp_commit();
            cp_wait2();
            __syncthreads();

            const uint32_t tA  = sbase + s * STAGE;
            const uint32_t tAl = tA + BM * 64;
            const uint32_t tBh = tA + 2 * BM * 64;
            const uint32_t tBl = tBh + BN * 64;

            #pragma unroll
            for (int kk = 0; kk < 2; kk++) {
                const int cb = kk * 32;
                const uint32_t coff = (uint32_t)((cb + khb) ^ swz);
                uint32_t ah[MF][4], al_[MF][4];
                #pragma unroll
                for (int mf = 0; mf < MF; mf++) {
                    uint32_t ro = (wm0 + mf * 16 + li) * 64 + coff;
                    ldsm4(ah[mf],  tA  + ro);
                    ldsm4(al_[mf], tAl + ro);
                }
                uint32_t bh[NF][2], bl[NF][2];
                #pragma unroll
                for (int nf2 = 0; nf2 < NF / 2; nf2++) {
                    uint32_t ro = (wn0 + nf2 * 16 + li) * 64 + coff;
                    uint32_t t[4];
                    ldsm4(t, tBh + ro);
                    bh[2 * nf2][0] = t[0]; bh[2 * nf2][1] = t[2];
                    bh[2 * nf2 + 1][0] = t[1]; bh[2 * nf2 + 1][1] = t[3];
                    ldsm4(t, tBl + ro);
                    bl[2 * nf2][0] = t[0]; bl[2 * nf2][1] = t[2];
                    bl[2 * nf2 + 1][0] = t[1]; bl[2 * nf2 + 1][1] = t[3];
                }
                #pragma unroll
                for (int mf = 0; mf < MF; mf++)
                    #pragma unroll
                    for (int nf = 0; nf < NF; nf++) {
                        mma16816(acc[mf][nf], ah[mf],  bh[nf]);
                        mma16816(acc[mf][nf], ah[mf],  bl[nf]);
                        mma16816(acc[mf][nf], al_[mf], bh[nf]);
                    }
            }
            __syncthreads();
        }

        // fused gate nonlinearity + state update (gate-permuted columns)
        #pragma unroll
        for (int mf = 0; mf < MF; mf++) {
            #pragma unroll
            for (int qsel = 0; qsel < NF / 2; qsel++) {
                const int nb = n0 + wn0 + qsel * 16;
                const int a  = lane & 3;
                const int j  = 4 * (nb >> 4) + a;
                #pragma unroll
                for (int i = 0; i < 2; i++) {
                    const int m = m0 + wm0 + mf * 16 + (lane >> 2) + 8 * i;
                    const float* xrow = xgl + (size_t)m * (L_SZ * G4);
                    float2 xif = *reinterpret_cast<const float2*>(xrow + nb + 2 * a);
                    float2 xgo = *reinterpret_cast<const float2*>(xrow + nb + 8 + 2 * a);
                    float xi = acc[mf][2 * qsel][2 * i]         + xif.x;
                    float xf = acc[mf][2 * qsel][2 * i + 1]     + xif.y;
                    float xgv = acc[mf][2 * qsel + 1][2 * i]    + xgo.x;
                    float xo = acc[mf][2 * qsel + 1][2 * i + 1] + xgo.y;
                    float ig = sigf(xi), fg = sigf(xf);
                    float gg = tanhf(xgv), og = sigf(xo);
                    const int gi = (m << 10) + j;
                    float cv = fg * cstate[gi] + ig * gg;
                    cstate[gi] = cv;
                    float hv = og * tanhf(cv);
                    houtf[gi] = hv;
                    __nv_bfloat16 hi, lo; split_bf16(hv, hi, lo);
                    Oh[gi] = hi; Ol[gi] = lo;
                }
            }
        }

        // ---- device-wide barrier (all 128 CTAs resident) ----
        __threadfence();
        __syncthreads();
        if (tid == 0) {
            atomicAdd(&g_bar, 1u);
            volatile unsigned* vb = &g_bar;
            const unsigned target = 128u * (unsigned)l;
            while (*vb < target) { }
        }
        __syncthreads();
    }
}

// ---------------- converts (vectorized) -------------------------------------
__global__ void conv_split(const float* __restrict__ src, int C, int srcld, int Cp,
                           __nv_bfloat16* __restrict__ dh, __nv_bfloat16* __restrict__ dl)
{
    int c4 = (blockIdx.x * blockDim.x + threadIdx.x) * 4;
    int r = blockIdx.y;
    if (c4 >= Cp) return;
    float4 x = make_float4(0.f, 0.f, 0.f, 0.f);
    if (c4 < C) x = *reinterpret_cast<const float4*>(src + (size_t)r * srcld + c4);
    __nv_bfloat16 h0, l0, h1, l1, h2, l2, h3, l3;
    split_bf16(x.x, h0, l0); split_bf16(x.y, h1, l1);
    split_bf16(x.z, h2, l2); split_bf16(x.w, h3, l3);
    size_t o = (size_t)r * Cp + c4;
    __nv_bfloat162 ph0; ph0.x = h0; ph0.y = h1;
    __nv_bfloat162 ph1; ph1.x = h2; ph1.y = h3;
    __nv_bfloat162 pl0; pl0.x = l0; pl0.y = l1;
    __nv_bfloat162 pl1; pl1.x = l2; pl1.y = l3;
    *reinterpret_cast<__nv_bfloat162*>(dh + o)     = ph0;
    *reinterpret_cast<__nv_bfloat162*>(dh + o + 2) = ph1;
    *reinterpret_cast<__nv_bfloat162*>(dl + o)     = pl0;
    *reinterpret_cast<__nv_bfloat162*>(dl + o + 2) = pl1;
}

// gate permutation: new row r -> orig = gate*1024 + cell,
//   gate = ((r>>3)&1)*2 + (r&1),  cell = 4*(r>>4) + ((r>>1)&3)
__global__ void conv_perm_split(const float* __restrict__ src, int cols,
                                __nv_bfloat16* __restrict__ dh, __nv_bfloat16* __restrict__ dl)
{
    int c4 = (blockIdx.x * blockDim.x + threadIdx.x) * 4;
    int r = blockIdx.y;
    if (c4 >= cols) return;
    int gate = ((r >> 3) & 1) * 2 + (r & 1);
    int cell = 4 * (r >> 4) + ((r >> 1) & 3);
    int orig = gate * 1024 + cell;
    float4 x = *reinterpret_cast<const float4*>(src + (size_t)orig * cols + c4);
    __nv_bfloat16 h0, l0, h1, l1, h2, l2, h3, l3;
    split_bf16(x.x, h0, l0); split_bf16(x.y, h1, l1);
    split_bf16(x.z, h2, l2); split_bf16(x.w, h3, l3);
    size_t o = (size_t)r * cols + c4;
    __nv_bfloat162 ph0; ph0.x = h0; ph0.y = h1;
    __nv_bfloat162 ph1; ph1.x = h2; ph1.y = h3;
    __nv_bfloat162 pl0; pl0.x = l0; pl0.y = l1;
    __nv_bfloat162 pl1; pl1.x = l2; pl1.y = l3;
    *reinterpret_cast<__nv_bfloat162*>(dh + o)     = ph0;
    *reinterpret_cast<__nv_bfloat162*>(dh + o + 2) = ph1;
    *reinterpret_cast<__nv_bfloat162*>(dl + o)     = pl0;
    *reinterpret_cast<__nv_bfloat162*>(dl + o + 2) = pl1;
}

// prep: time-embed fold, permuted bias, W_vt split, barrier reset
__global__ void prep_kernel(const float* __restrict__ Wvt,
                            const float* __restrict__ wtw,
                            const float* __restrict__ wtb,
                            const float* __restrict__ bih,
                            const float* __restrict__ bhh)
{
    int i = blockIdx.x * blockDim.x + threadIdx.x;
    if (i == 0) g_bar = 0;
    if (i < HIN) {
        const float* row = Wvt + (size_t)i * (HIN + 128) + HIN;
        float u = 0.f, ub = 0.f;
        #pragma unroll 4
        for (int j = 0; j < 128; j++) { float w = row[j]; u += w * wtw[j]; ub += w * wtb[j]; }
        g_u[i] = u; g_ub[i] = ub;
    } else if (i < HIN + G4) {
        int r = i - HIN;
        int gate = ((r >> 3) & 1) * 2 + (r & 1);
        int cell = 4 * (r >> 4) + ((r >> 1) & 3);
        g_biasp[r] = bih[gate * 1024 + cell] + bhh[gate * 1024 + cell];
    } else if (i < HIN + G4 + HIN * HIN / 4) {
        int w = i - (HIN + G4);
        int r = w >> 7;            // 128 groups of 4 per 512-col row
        int c4 = (w & 127) * 4;
        float4 x = *reinterpret_cast<const float4*>(Wvt + (size_t)r * (HIN + 128) + c4);
        __nv_bfloat16 h0, l0, h1, l1, h2, l2, h3, l3;
        split_bf16(x.x, h0, l0); split_bf16(x.y, h1, l1);
        split_bf16(x.z, h2, l2); split_bf16(x.w, h3, l3);
        size_t o = (size_t)r * HIN + c4;
        __nv_bfloat162 ph0; ph0.x = h0; ph0.y = h1;
        __nv_bfloat162 ph1; ph1.x = h2; ph1.y = h3;
        __nv_bfloat162 pl0; pl0.x = l0; pl0.y = l1;
        __nv_bfloat162 pl1; pl1.x = l2; pl1.y = l3;
        *reinterpret_cast<__nv_bfloat162*>(g_wvth + o)     = ph0;
        *reinterpret_cast<__nv_bfloat162*>(g_wvth + o + 2) = ph1;
        *reinterpret_cast<__nv_bfloat162*>(g_wvtl + o)     = pl0;
        *reinterpret_cast<__nv_bfloat162*>(g_wvtl + o + 2) = pl1;
    }
}

__global__ void reduce_conv(void)
{
    int idx = blockIdx.x * 256 + threadIdx.x;
    float s = 0.f;
    #pragma unroll
    for (int z = 0; z < KSPLIT; z++) s += g_split[(size_t)z * ML * HIN + idx];
    __nv_bfloat16 hi, lo; split_bf16(s, hi, lo);
    g_vdh[idx] = hi; g_vdl[idx] = lo;
}

// LSTM step 0 (h=c=0): gates = permuted xg row l=0
__global__ void lstm_step0(void)
{
    int idx = blockIdx.x * 256 + threadIdx.x;     // m*1024 + j
    int m = idx >> 10, j = idx & (H_SZ - 1);
    int q = j >> 2, a = j & 3;
    const float* xrow = g_xg + (size_t)m * (L_SZ * G4);
    float xi = xrow[(q << 4) + 2 * a];
    float xg = xrow[(q << 4) + 8 + 2 * a];
    float xo = xrow[(q << 4) + 8 + 2 * a + 1];
    float c = sigf(xi) * tanhf(xg);
    g_c[idx] = c;
    float hv = sigf(xo) * tanhf(c);
    __nv_bfloat16 hi, lo; split_bf16(hv, hi, lo);
    g_hh[idx] = hi; g_hl[idx] = lo;               // buffer 0
}

__global__ void pred_kernel(const float* __restrict__ lw,
                            const float* __restrict__ lb,
                            float* __restrict__ out)
{
    int b = blockIdx.x, tid = threadIdx.x;
    const float* hr = g_h + (size_t)b * H_SZ;
    float s = 0.f;
    for (int k = tid; k < H_SZ; k += 128) s += hr[k] * lw[k];
    __shared__ float red[128];
    red[tid] = s; __syncthreads();
    for (int off = 64; off > 0; off >>= 1) {
        if (tid < off) red[tid] += red[tid + off];
        __syncthreads();
    }
    if (tid == 0) out[b] = red[0] + lb[0];
}

// ---------------- launch -----------------------------------------------------
#define SMEM_BIG  ((2 * 128 + 2 * 128) * 64 * 3)   // 98304
#define SMEM_LSTM ((2 * 64 + 2 * 64) * 64 * 3)     // 49152

extern "C" void kernel_launch(void* const* d_in, const int* in_sizes, int n_in,
                              void* d_out, int out_size)
{
    const float* v   = (const float*)d_in[0];
    const float* t   = (const float*)d_in[1];
    const float* Wd  = (const float*)d_in[2];
    const float* wtw = (const float*)d_in[3];
    const float* wtb = (const float*)d_in[4];
    const float* Wvt = (const float*)d_in[5];
    const float* Wih = (const float*)d_in[6];
    const float* Whh = (const float*)d_in[7];
    const float* bih = (const float*)d_in[8];
    const float* bhh = (const float*)d_in[9];
    const float* lw  = (const float*)d_in[10];
    const float* lb  = (const float*)d_in[11];
    float* out = (float*)d_out;

    __nv_bfloat16 *p_vh, *p_vl, *p_wdh, *p_wdl, *p_vdh, *p_vdl, *p_wvth, *p_wvtl;
    __nv_bfloat16 *p_ih, *p_il, *p_wihh, *p_wihl, *p_whhh, *p_whhl, *p_hh, *p_hl;
    float *p_split, *p_xg, *p_h, *p_c, *p_u, *p_ub, *p_biasp;
    cudaGetSymbolAddress((void**)&p_vh, g_vh);     cudaGetSymbolAddress((void**)&p_vl, g_vl);
    cudaGetSymbolAddress((void**)&p_wdh, g_wdh);   cudaGetSymbolAddress((void**)&p_wdl, g_wdl);
    cudaGetSymbolAddress((void**)&p_vdh, g_vdh);   cudaGetSymbolAddress((void**)&p_vdl, g_vdl);
    cudaGetSymbolAddress((void**)&p_wvth, g_wvth); cudaGetSymbolAddress((void**)&p_wvtl, g_wvtl);
    cudaGetSymbolAddress((void**)&p_ih, g_ih);     cudaGetSymbolAddress((void**)&p_il, g_il);
    cudaGetSymbolAddress((void**)&p_wihh, g_wihh); cudaGetSymbolAddress((void**)&p_wihl, g_wihl);
    cudaGetSymbolAddress((void**)&p_whhh, g_whhh); cudaGetSymbolAddress((void**)&p_whhl, g_whhl);
    cudaGetSymbolAddress((void**)&p_hh, g_hh);     cudaGetSymbolAddress((void**)&p_hl, g_hl);
    cudaGetSymbolAddress((void**)&p_split, g_split);
    cudaGetSymbolAddress((void**)&p_xg, g_xg);
    cudaGetSymbolAddress((void**)&p_h, g_h);       cudaGetSymbolAddress((void**)&p_c, g_c);
    cudaGetSymbolAddress((void**)&p_u, g_u);       cudaGetSymbolAddress((void**)&p_ub, g_ub);
    cudaGetSymbolAddress((void**)&p_biasp, g_biasp);

    cudaFuncSetAttribute(mma_gemm<128, 128, 64, 32, 0>, cudaFuncAttributeMaxDynamicSharedMemorySize, SMEM_BIG);
    cudaFuncSetAttribute(mma_gemm<128, 128, 64, 32, 1>, cudaFuncAttributeMaxDynamicSharedMemorySize, SMEM_BIG);
    cudaFuncSetAttribute(mma_gemm<128, 128, 64, 32, 2>, cudaFuncAttributeMaxDynamicSharedMemorySize, SMEM_BIG);
    cudaFuncSetAttribute(lstm_persist, cudaFuncAttributeMaxDynamicSharedMemorySize, SMEM_LSTM);

    // 0) prep (u/ub fold, permuted bias, W_vt split, barrier reset)
    prep_kernel<<<(HIN + G4 + HIN * HIN / 4) / 256, 256>>>(Wvt, wtw, wtb, bih, bhh);
    // 1-2) big converts (vectorized)
    conv_split<<<dim3((KPAD / 4 + 255) / 256, ML), 256>>>(v, N_SZ, N_SZ, KPAD, p_vh, p_vl);
    conv_split<<<dim3((KPAD / 4 + 255) / 256, HIN), 256>>>(Wd, N_SZ, N_SZ, KPAD, p_wdh, p_wdl);
    // 3-4) weight perms
    conv_perm_split<<<dim3(1, G4), 256>>>(Wih, HIN, p_wihh, p_wihl);
    conv_perm_split<<<dim3(1, G4), 256>>>(Whh, H_SZ, p_whhh, p_whhl);

    // 5) GEMM1 (split-K=4 -> 256 CTAs -> 2 CTAs/SM): partials = v @ W_down^T
    mma_gemm<128, 128, 64, 32, 0><<<dim3(HIN / 128, ML / 128, KSPLIT), 256, SMEM_BIG>>>(
        p_vh, p_vl, KPAD, p_wdh, p_wdl, KPAD, KCHUNK,
        p_split, HIN, (size_t)ML * HIN,
        nullptr, nullptr, nullptr, nullptr, nullptr);
    // 6) reduce partials -> vd bf16 split
    reduce_conv<<<(ML * HIN) / 256, 256>>>();

    // 7) GEMM2: inputs = vd @ Wvt_s^T + t[m]*u[n] + ub[n]  -> bf16 split
    mma_gemm<128, 128, 64, 32, 1><<<dim3(HIN / 128, ML / 128), 256, SMEM_BIG>>>(
        p_vdh, p_vdl, HIN, p_wvth, p_wvtl, HIN, HIN,
        nullptr, HIN, 0, p_ub, t, p_u, p_ih, p_il);

    // 8) GEMM3: xg = inputs @ Wih_perm^T + bias_perm (gate-permuted cols)
    mma_gemm<128, 128, 64, 32, 2><<<dim3(G4 / 128, ML / 128), 256, SMEM_BIG>>>(
        p_ih, p_il, HIN, p_wihh, p_wihl, HIN, HIN,
        p_xg, G4, 0, p_biasp, nullptr, nullptr, nullptr, nullptr);

    // 9) LSTM step 0 + 10) persistent steps 1..15
    lstm_step0<<<(B_SZ * H_SZ) / 256, 256>>>();
    lstm_persist<<<dim3(G4 / 64, B_SZ / 64), 128, SMEM_LSTM>>>(
        p_hh, p_hl, p_whhh, p_whhl, p_xg, p_c, p_h, p_hh, p_hl);

    // 11) pred
    pred_kernel<<<B_SZ, 128>>>(lw, lb, out);
}

// round 6
// speedup vs baseline: 4.7595x; 1.4366x over previous
#include <cuda_runtime.h>
#include <cuda_fp16.h>
#include <cstdint>
#include <math.h>

// ---------------- dims ------------------------------------------------------
#define B_SZ 128
#define L_SZ 16
#define N_SZ 20000
#define KPAD 20096          // divisible by 32, 4*32
#define HIN  512
#define H_SZ 1024
#define G4   4096
#define ML   2048
#define KSPLIT 4
#define KCHUNK (KPAD / KSPLIT)   // 5024 = 157 * 32

// ---------------- device global scratch ------------------------------------
__device__ __half g_vh[(size_t)ML * KPAD];        // v hi (exact split)
__device__ __half g_vl[(size_t)ML * KPAD];        // v lo
__device__ __half g_wd[(size_t)HIN * KPAD];       // W_down rounded
__device__ float g_split[KSPLIT * ML * HIN];
__device__ __half g_vdh[ML * HIN];                // vd split
__device__ __half g_vdl[ML * HIN];
__device__ __half g_wvt[HIN * HIN];               // W_vt[:, :512] rounded
__device__ __half g_ih[ML * HIN];                 // inputs split
__device__ __half g_il[ML * HIN];
__device__ __half g_wih[G4 * HIN];                // W_ih permuted rounded
__device__ __half g_whh[(size_t)G4 * H_SZ];       // W_hh permuted rounded
__device__ float g_xg[(size_t)ML * G4];           // permuted gate cols
__device__ __half g_hh[2 * B_SZ * H_SZ];          // h split, double buffered
__device__ __half g_hl[2 * B_SZ * H_SZ];
__device__ float g_h[B_SZ * H_SZ];
__device__ float g_c[B_SZ * H_SZ];
__device__ float g_u[HIN];
__device__ float g_ub[HIN];
__device__ float g_biasp[G4];
__device__ unsigned g_bar;

// ---------------- helpers ---------------------------------------------------
__device__ __forceinline__ uint32_t smem_u32(const void* p) {
    uint32_t a;
    asm("{ .reg .u64 t; cvta.to.shared.u64 t, %1; cvt.u32.u64 %0, t; }" : "=r"(a) : "l"(p));
    return a;
}
__device__ __forceinline__ void cp_async16(uint32_t dst, const void* src) {
    asm volatile("cp.async.cg.shared.global [%0], [%1], 16;" :: "r"(dst), "l"(src));
}
__device__ __forceinline__ void cp_commit() {
    asm volatile("cp.async.commit_group;" ::: "memory");
}
__device__ __forceinline__ void cp_wait2() {
    asm volatile("cp.async.wait_group 2;" ::: "memory");
}
__device__ __forceinline__ void ldsm4(uint32_t* r, uint32_t addr) {
    asm volatile("ldmatrix.sync.aligned.m8n8.x4.shared.b16 {%0,%1,%2,%3}, [%4];"
        : "=r"(r[0]), "=r"(r[1]), "=r"(r[2]), "=r"(r[3]) : "r"(addr));
}
__device__ __forceinline__ void mma16816(float* c, const uint32_t* a, const uint32_t* b) {
    asm volatile("mma.sync.aligned.m16n8k16.row.col.f32.f16.f16.f32 "
        "{%0,%1,%2,%3}, {%4,%5,%6,%7}, {%8,%9}, {%0,%1,%2,%3};"
        : "+f"(c[0]), "+f"(c[1]), "+f"(c[2]), "+f"(c[3])
        : "r"(a[0]), "r"(a[1]), "r"(a[2]), "r"(a[3]), "r"(b[0]), "r"(b[1]));
}
__device__ __forceinline__ float sigf(float x) { return 1.f / (1.f + expf(-x)); }
__device__ __forceinline__ void split_h(float x, __half& hi, __half& lo) {
    hi = __float2half_rn(x);
    lo = __float2half_rn(x - __half2float(hi));
}

// smem tile: 64B rows; 16B chunk c of row r at r*64 + ((c*16) ^ (((r>>1)&3)<<4))

// ---------------- tensor-core GEMM (2-term fp16) -----------------------------
// C[M,N] = (Ah+Al)[M,K] @ B[N,K]^T   (A split exact, B pre-rounded fp16)
// MODE 0: fp32 partial to C + z*zstride (split-K)
// MODE 1: += srow[m]*ucol[n] + bias[n]; fp16-split out to Ch/Cl
// MODE 2: += bias[n]; fp32 out
template<int BM, int BN, int WM, int WN, int MODE>
__global__ void __launch_bounds__((BM / WM) * (BN / WN) * 32)
mma_gemm(const __half* __restrict__ Ah, const __half* __restrict__ Al, int lda,
         const __half* __restrict__ Bm, int ldb, int K,
         float* __restrict__ C, int ldc, size_t zstride,
         const float* __restrict__ bias,
         const float* __restrict__ srow, const float* __restrict__ ucol,
         __half* __restrict__ Ch, __half* __restrict__ Cl)
{
    constexpr int NT = (BM / WM) * (BN / WN) * 32;
    constexpr int MF = WM / 16;
    constexpr int NF = WN / 8;
    constexpr int STAGE = (2 * BM + BN) * 64;
    constexpr int CHA = BM * 4;
    constexpr int CHB = BN * 4;
    constexpr int CHT = 2 * CHA + CHB;

    extern __shared__ char smem[];
    const uint32_t sbase = smem_u32(smem);
    const int tid  = threadIdx.x;
    const int lane = tid & 31;
    const int warp = tid >> 5;
    const int wm0 = (warp / (BN / WN)) * WM;
    const int wn0 = (warp % (BN / WN)) * WN;
    const int m0 = blockIdx.y * BM;
    const int n0 = blockIdx.x * BN;

    if (MODE == 0) {
        Ah += (size_t)blockIdx.z * K;  Al += (size_t)blockIdx.z * K;
        Bm += (size_t)blockIdx.z * K;
        C  += (size_t)blockIdx.z * zstride;
    }

    float acc[MF][NF][4];
    #pragma unroll
    for (int i = 0; i < MF; i++)
        #pragma unroll
        for (int j = 0; j < NF; j++)
            #pragma unroll
            for (int q = 0; q < 4; q++) acc[i][j][q] = 0.f;

    auto load_stage = [&](int kt, int s) {
        const int k0 = kt * 32;
        const uint32_t tb = sbase + s * STAGE;
        #pragma unroll
        for (int q = 0; q < CHT / NT; q++) {
            const int i = tid + q * NT;
            const __half* src;
            int toff, rr;
            if (i < CHA) {
                rr = i >> 2; src = Ah + (size_t)(m0 + rr) * lda; toff = 0;
            } else if (i < 2 * CHA) {
                int j = i - CHA; rr = j >> 2;
                src = Al + (size_t)(m0 + rr) * lda; toff = BM * 64;
            } else {
                int j = i - 2 * CHA; rr = j >> 2;
                src = Bm + (size_t)(n0 + rr) * ldb; toff = 2 * BM * 64;
            }
            const int c = i & 3;
            uint32_t dst = tb + toff + rr * 64 + ((c * 16) ^ (((rr >> 1) & 3) << 4));
            cp_async16(dst, src + k0 + c * 8);
        }
    };

    const int KT = K >> 5;
    load_stage(0, 0); cp_commit();
    load_stage(1, 1); cp_commit();

    const int li  = lane & 15;
    const int khb = (lane >> 4) << 4;
    const int swz = ((li >> 1) & 3) << 4;

    for (int kt = 0; kt < KT; kt++) {
        const int s = kt % 3;
        if (kt + 2 < KT) load_stage(kt + 2, (kt + 2) % 3);
        cp_commit();
        cp_wait2();
        __syncthreads();

        const uint32_t tA  = sbase + s * STAGE;
        const uint32_t tAl = tA + BM * 64;
        const uint32_t tB  = tA + 2 * BM * 64;

        #pragma unroll
        for (int kk = 0; kk < 2; kk++) {
            const int cb = kk * 32;
            const uint32_t coff = (uint32_t)((cb + khb) ^ swz);
            uint32_t ah[MF][4], al_[MF][4];
            #pragma unroll
            for (int mf = 0; mf < MF; mf++) {
                uint32_t ro = (wm0 + mf * 16 + li) * 64 + coff;
                ldsm4(ah[mf],  tA  + ro);
                ldsm4(al_[mf], tAl + ro);
            }
            uint32_t bh[NF][2];
            #pragma unroll
            for (int nf2 = 0; nf2 < NF / 2; nf2++) {
                uint32_t ro = (wn0 + nf2 * 16 + li) * 64 + coff;
                uint32_t t[4];
                ldsm4(t, tB + ro);
                bh[2 * nf2][0] = t[0]; bh[2 * nf2][1] = t[2];
                bh[2 * nf2 + 1][0] = t[1]; bh[2 * nf2 + 1][1] = t[3];
            }
            #pragma unroll
            for (int mf = 0; mf < MF; mf++)
                #pragma unroll
                for (int nf = 0; nf < NF; nf++) {
                    mma16816(acc[mf][nf], ah[mf],  bh[nf]);
                    mma16816(acc[mf][nf], al_[mf], bh[nf]);
                }
        }
        __syncthreads();
    }

    // ---- epilogue: stage warp tile in smem, coalesced out ----
    float* st = reinterpret_cast<float*>(smem) + warp * (WM * 33);
    #pragma unroll
    for (int mf = 0; mf < MF; mf++)
        #pragma unroll
        for (int nf = 0; nf < NF; nf++)
            #pragma unroll
            for (int i = 0; i < 2; i++) {
                int r = mf * 16 + (lane >> 2) + 8 * i;
                int c = nf * 8 + 2 * (lane & 3);
                st[r * 33 + c]     = acc[mf][nf][2 * i];
                st[r * 33 + c + 1] = acc[mf][nf][2 * i + 1];
            }
    __syncwarp();
    #pragma unroll
    for (int rr = lane; rr < WM; rr += 32) {
        const int m = m0 + wm0 + rr;
        const int nbase = n0 + wn0;
        if (MODE == 1) {
            const float tm = srow[m];
            #pragma unroll
            for (int c = 0; c < WN; c += 2) {
                int n = nbase + c;
                float v0 = st[rr * 33 + c]     + tm * ucol[n]     + bias[n];
                float v1 = st[rr * 33 + c + 1] + tm * ucol[n + 1] + bias[n + 1];
                __half h0, l0, h1, l1;
                split_h(v0, h0, l0); split_h(v1, h1, l1);
                __half2 ph; ph.x = h0; ph.y = h1;
                __half2 pl; pl.x = l0; pl.y = l1;
                *reinterpret_cast<__half2*>(Ch + (size_t)m * ldc + n) = ph;
                *reinterpret_cast<__half2*>(Cl + (size_t)m * ldc + n) = pl;
            }
        } else {
            #pragma unroll
            for (int c4 = 0; c4 < WN; c4 += 4) {
                float4 v;
                v.x = st[rr * 33 + c4];
                v.y = st[rr * 33 + c4 + 1];
                v.z = st[rr * 33 + c4 + 2];
                v.w = st[rr * 33 + c4 + 3];
                if (MODE == 2) {
                    int n = nbase + c4;
                    v.x += bias[n]; v.y += bias[n + 1];
                    v.z += bias[n + 2]; v.w += bias[n + 3];
                }
                *reinterpret_cast<float4*>(C + (size_t)m * ldc + nbase + c4) = v;
            }
        }
    }
}

// ---------------- persistent fused LSTM (steps 1..15) ------------------------
// grid (G4/64, B_SZ/32) = (64,4) = 256 CTAs x 128 threads, all resident.
// Tile 32(batch) x 64(gates); warp tile 16x32 (MF=1, NF=4).
__global__ void __launch_bounds__(128)
lstm_persist(const __half* __restrict__ hhb, const __half* __restrict__ hlb,
             const __half* __restrict__ Bm,
             const float* __restrict__ xg, float* __restrict__ cstate,
             float* __restrict__ houtf,
             __half* __restrict__ hhw, __half* __restrict__ hlw)
{
    constexpr int BM = 32, BN = 64, NT = 128, NF = 4;
    constexpr int STAGE = (2 * BM + BN) * 64;    // 8192
    constexpr int CHA = BM * 4, CHB = BN * 4, CHT = 2 * CHA + CHB;

    extern __shared__ char smem[];
    const uint32_t sbase = smem_u32(smem);
    const int tid  = threadIdx.x;
    const int lane = tid & 31;
    const int warp = tid >> 5;
    const int wm0 = (warp >> 1) * 16;
    const int wn0 = (warp & 1) * 32;
    const int m0 = blockIdx.y * BM;
    const int n0 = blockIdx.x * BN;
    const int li  = lane & 15;
    const int khb = (lane >> 4) << 4;
    const int swz = ((li >> 1) & 3) << 4;

    for (int l = 1; l < L_SZ; l++) {
        const __half* Ah = hhb + (size_t)((l + 1) & 1) * (B_SZ * H_SZ);
        const __half* Al = hlb + (size_t)((l + 1) & 1) * (B_SZ * H_SZ);
        __half* Oh = hhw + (size_t)(l & 1) * (B_SZ * H_SZ);
        __half* Ol = hlw + (size_t)(l & 1) * (B_SZ * H_SZ);
        const float* xgl = xg + (size_t)l * G4;

        float acc[NF][4];
        #pragma unroll
        for (int j = 0; j < NF; j++)
            #pragma unroll
            for (int q = 0; q < 4; q++) acc[j][q] = 0.f;

        auto load_stage = [&](int kt, int s) {
            const int k0 = kt * 32;
            const uint32_t tb = sbase + s * STAGE;
            #pragma unroll
            for (int q = 0; q < CHT / NT; q++) {
                const int i = tid + q * NT;
                const __half* src;
                int toff, rr;
                if (i < CHA) {
                    rr = i >> 2; src = Ah + (size_t)(m0 + rr) * H_SZ; toff = 0;
                } else if (i < 2 * CHA) {
                    int j = i - CHA; rr = j >> 2;
                    src = Al + (size_t)(m0 + rr) * H_SZ; toff = BM * 64;
                } else {
                    int j = i - 2 * CHA; rr = j >> 2;
                    src = Bm + (size_t)(n0 + rr) * H_SZ; toff = 2 * BM * 64;
                }
                const int c = i & 3;
                uint32_t dst = tb + toff + rr * 64 + ((c * 16) ^ (((rr >> 1) & 3) << 4));
                cp_async16(dst, src + k0 + c * 8);
            }
        };

        const int KT = H_SZ >> 5;   // 32
        load_stage(0, 0); cp_commit();
        load_stage(1, 1); cp_commit();

        for (int kt = 0; kt < KT; kt++) {
            const int s = kt % 3;
            if (kt + 2 < KT) load_stage(kt + 2, (kt + 2) % 3);
            cp_commit();
            cp_wait2();
            __syncthreads();

            const uint32_t tA  = sbase + s * STAGE;
            const uint32_t tAl = tA + BM * 64;
            const uint32_t tB  = tA + 2 * BM * 64;

            #pragma unroll
            for (int kk = 0; kk < 2; kk++) {
                const int cb = kk * 32;
                const uint32_t coff = (uint32_t)((cb + khb) ^ swz);
                uint32_t ah[4], al_[4];
                {
                    uint32_t ro = (wm0 + li) * 64 + coff;
                    ldsm4(ah,  tA  + ro);
                    ldsm4(al_, tAl + ro);
                }
                uint32_t bh[NF][2];
                #pragma unroll
                for (int nf2 = 0; nf2 < NF / 2; nf2++) {
                    uint32_t ro = (wn0 + nf2 * 16 + li) * 64 + coff;
                    uint32_t t[4];
                    ldsm4(t, tB + ro);
                    bh[2 * nf2][0] = t[0]; bh[2 * nf2][1] = t[2];
                    bh[2 * nf2 + 1][0] = t[1]; bh[2 * nf2 + 1][1] = t[3];
                }
                #pragma unroll
                for (int nf = 0; nf < NF; nf++) {
                    mma16816(acc[nf], ah,  bh[nf]);
                    mma16816(acc[nf], al_, bh[nf]);
                }
            }
            __syncthreads();
        }

        // fused gate nonlinearity + state update (gate-permuted columns)
        #pragma unroll
        for (int qsel = 0; qsel < NF / 2; qsel++) {
            const int nb = n0 + wn0 + qsel * 16;
            const int a  = lane & 3;
            const int j  = 4 * (nb >> 4) + a;
            #pragma unroll
            for (int i = 0; i < 2; i++) {
                const int m = m0 + wm0 + (lane >> 2) + 8 * i;
                const float* xrow = xgl + (size_t)m * (L_SZ * G4);
                float2 xif = *reinterpret_cast<const float2*>(xrow + nb + 2 * a);
                float2 xgo = *reinterpret_cast<const float2*>(xrow + nb + 8 + 2 * a);
                float xi = acc[2 * qsel][2 * i]         + xif.x;
                float xf = acc[2 * qsel][2 * i + 1]     + xif.y;
                float xgv = acc[2 * qsel + 1][2 * i]    + xgo.x;
                float xo = acc[2 * qsel + 1][2 * i + 1] + xgo.y;
                float ig = sigf(xi), fg = sigf(xf);
                float gg = tanhf(xgv), og = sigf(xo);
                const int gi = (m << 10) + j;
                float cv = fg * cstate[gi] + ig * gg;
                cstate[gi] = cv;
                float hv = og * tanhf(cv);
                houtf[gi] = hv;
                __half hi, lo; split_h(hv, hi, lo);
                Oh[gi] = hi; Ol[gi] = lo;
            }
        }

        // ---- device-wide barrier (256 CTAs, all resident) ----
        __threadfence();
        __syncthreads();
        if (tid == 0) {
            atomicAdd(&g_bar, 1u);
            volatile unsigned* vb = &g_bar;
            const unsigned target = 256u * (unsigned)l;
            while (*vb < target) { }
        }
        __syncthreads();
    }
}

// ---------------- converts ---------------------------------------------------
// fp32 -> fp16 exact split (hi + lo), zero-padded to Cp
__global__ void conv_split2(const float* __restrict__ src, int C, int srcld, int Cp,
                            __half* __restrict__ dh, __half* __restrict__ dl)
{
    int c4 = (blockIdx.x * blockDim.x + threadIdx.x) * 4;
    int r = blockIdx.y;
    if (c4 >= Cp) return;
    float4 x = make_float4(0.f, 0.f, 0.f, 0.f);
    if (c4 < C) x = *reinterpret_cast<const float4*>(src + (size_t)r * srcld + c4);
    __half h0, l0, h1, l1, h2, l2, h3, l3;
    split_h(x.x, h0, l0); split_h(x.y, h1, l1);
    split_h(x.z, h2, l2); split_h(x.w, h3, l3);
    size_t o = (size_t)r * Cp + c4;
    __half2 a; a.x = h0; a.y = h1;
    __half2 b; b.x = h2; b.y = h3;
    __half2 c; c.x = l0; c.y = l1;
    __half2 d; d.x = l2; d.y = l3;
    *reinterpret_cast<__half2*>(dh + o)     = a;
    *reinterpret_cast<__half2*>(dh + o + 2) = b;
    *reinterpret_cast<__half2*>(dl + o)     = c;
    *reinterpret_cast<__half2*>(dl + o + 2) = d;
}

// fp32 -> fp16 rounded, zero-padded
__global__ void conv_round(const float* __restrict__ src, int C, int srcld, int Cp,
                           __half* __restrict__ dst)
{
    int c4 = (blockIdx.x * blockDim.x + threadIdx.x) * 4;
    int r = blockIdx.y;
    if (c4 >= Cp) return;
    float4 x = make_float4(0.f, 0.f, 0.f, 0.f);
    if (c4 < C) x = *reinterpret_cast<const float4*>(src + (size_t)r * srcld + c4);
    size_t o = (size_t)r * Cp + c4;
    __half2 a; a.x = __float2half_rn(x.x); a.y = __float2half_rn(x.y);
    __half2 b; b.x = __float2half_rn(x.z); b.y = __float2half_rn(x.w);
    *reinterpret_cast<__half2*>(dst + o)     = a;
    *reinterpret_cast<__half2*>(dst + o + 2) = b;
}

// gate permutation + round: new row r -> orig = gate*1024 + cell,
//   gate = ((r>>3)&1)*2 + (r&1),  cell = 4*(r>>4) + ((r>>1)&3)
__global__ void conv_perm_round(const float* __restrict__ src, int cols,
                                __half* __restrict__ dst)
{
    int c4 = (blockIdx.x * blockDim.x + threadIdx.x) * 4;
    int r = blockIdx.y;
    if (c4 >= cols) return;
    int gate = ((r >> 3) & 1) * 2 + (r & 1);
    int cell = 4 * (r >> 4) + ((r >> 1) & 3);
    int orig = gate * 1024 + cell;
    float4 x = *reinterpret_cast<const float4*>(src + (size_t)orig * cols + c4);
    size_t o = (size_t)r * cols + c4;
    __half2 a; a.x = __float2half_rn(x.x); a.y = __float2half_rn(x.y);
    __half2 b; b.x = __float2half_rn(x.z); b.y = __float2half_rn(x.w);
    *reinterpret_cast<__half2*>(dst + o)     = a;
    *reinterpret_cast<__half2*>(dst + o + 2) = b;
}

// prep: time-embed fold, permuted bias, W_vt round, barrier reset
__global__ void prep_kernel(const float* __restrict__ Wvt,
                            const float* __restrict__ wtw,
                            const float* __restrict__ wtb,
                            const float* __restrict__ bih,
                            const float* __restrict__ bhh)
{
    int i = blockIdx.x * blockDim.x + threadIdx.x;
    if (i == 0) g_bar = 0;
    if (i < HIN) {
        const float* row = Wvt + (size_t)i * (HIN + 128) + HIN;
        float u = 0.f, ub = 0.f;
        #pragma unroll 4
        for (int j = 0; j < 128; j++) { float w = row[j]; u += w * wtw[j]; ub += w * wtb[j]; }
        g_u[i] = u; g_ub[i] = ub;
    } else if (i < HIN + G4) {
        int r = i - HIN;
        int gate = ((r >> 3) & 1) * 2 + (r & 1);
        int cell = 4 * (r >> 4) + ((r >> 1) & 3);
        g_biasp[r] = bih[gate * 1024 + cell] + bhh[gate * 1024 + cell];
    } else if (i < HIN + G4 + HIN * HIN / 4) {
        int w = i - (HIN + G4);
        int r = w >> 7;
        int c4 = (w & 127) * 4;
        float4 x = *reinterpret_cast<const float4*>(Wvt + (size_t)r * (HIN + 128) + c4);
        size_t o = (size_t)r * HIN + c4;
        __half2 a; a.x = __float2half_rn(x.x); a.y = __float2half_rn(x.y);
        __half2 b; b.x = __float2half_rn(x.z); b.y = __float2half_rn(x.w);
        *reinterpret_cast<__half2*>(g_wvt + o)     = a;
        *reinterpret_cast<__half2*>(g_wvt + o + 2) = b;
    }
}

__global__ void reduce_conv(void)
{
    int idx = blockIdx.x * 256 + threadIdx.x;
    float s = 0.f;
    #pragma unroll
    for (int z = 0; z < KSPLIT; z++) s += g_split[(size_t)z * ML * HIN + idx];
    __half hi, lo; split_h(s, hi, lo);
    g_vdh[idx] = hi; g_vdl[idx] = lo;
}

// LSTM step 0 (h=c=0): gates = permuted xg row l=0
__global__ void lstm_step0(void)
{
    int idx = blockIdx.x * 256 + threadIdx.x;
    int m = idx >> 10, j = idx & (H_SZ - 1);
    int q = j >> 2, a = j & 3;
    const float* xrow = g_xg + (size_t)m * (L_SZ * G4);
    float xi = xrow[(q << 4) + 2 * a];
    float xg = xrow[(q << 4) + 8 + 2 * a];
    float xo = xrow[(q << 4) + 8 + 2 * a + 1];
    float c = sigf(xi) * tanhf(xg);
    g_c[idx] = c;
    float hv = sigf(xo) * tanhf(c);
    __half hi, lo; split_h(hv, hi, lo);
    g_hh[idx] = hi; g_hl[idx] = lo;
}

__global__ void pred_kernel(const float* __restrict__ lw,
                            const float* __restrict__ lb,
                            float* __restrict__ out)
{
    int b = blockIdx.x, tid = threadIdx.x;
    const float* hr = g_h + (size_t)b * H_SZ;
    float s = 0.f;
    for (int k = tid; k < H_SZ; k += 128) s += hr[k] * lw[k];
    __shared__ float red[128];
    red[tid] = s; __syncthreads();
    for (int off = 64; off > 0; off >>= 1) {
        if (tid < off) red[tid] += red[tid + off];
        __syncthreads();
    }
    if (tid == 0) out[b] = red[0] + lb[0];
}

// ---------------- launch -----------------------------------------------------
#define SMEM_BIG  ((2 * 128 + 128) * 64 * 3)   // 73728
#define SMEM_LSTM ((2 * 32 + 64) * 64 * 3)     // 24576

extern "C" void kernel_launch(void* const* d_in, const int* in_sizes, int n_in,
                              void* d_out, int out_size)
{
    const float* v   = (const float*)d_in[0];
    const float* t   = (const float*)d_in[1];
    const float* Wd  = (const float*)d_in[2];
    const float* wtw = (const float*)d_in[3];
    const float* wtb = (const float*)d_in[4];
    const float* Wvt = (const float*)d_in[5];
    const float* Wih = (const float*)d_in[6];
    const float* Whh = (const float*)d_in[7];
    const float* bih = (const float*)d_in[8];
    const float* bhh = (const float*)d_in[9];
    const float* lw  = (const float*)d_in[10];
    const float* lb  = (const float*)d_in[11];
    float* out = (float*)d_out;

    __half *p_vh, *p_vl, *p_wd, *p_vdh, *p_vdl, *p_wvt, *p_ih, *p_il;
    __half *p_wih, *p_whh, *p_hh, *p_hl;
    float *p_split, *p_xg, *p_h, *p_c, *p_u, *p_ub, *p_biasp;
    cudaGetSymbolAddress((void**)&p_vh, g_vh);   cudaGetSymbolAddress((void**)&p_vl, g_vl);
    cudaGetSymbolAddress((void**)&p_wd, g_wd);
    cudaGetSymbolAddress((void**)&p_vdh, g_vdh); cudaGetSymbolAddress((void**)&p_vdl, g_vdl);
    cudaGetSymbolAddress((void**)&p_wvt, g_wvt);
    cudaGetSymbolAddress((void**)&p_ih, g_ih);   cudaGetSymbolAddress((void**)&p_il, g_il);
    cudaGetSymbolAddress((void**)&p_wih, g_wih); cudaGetSymbolAddress((void**)&p_whh, g_whh);
    cudaGetSymbolAddress((void**)&p_hh, g_hh);   cudaGetSymbolAddress((void**)&p_hl, g_hl);
    cudaGetSymbolAddress((void**)&p_split, g_split);
    cudaGetSymbolAddress((void**)&p_xg, g_xg);
    cudaGetSymbolAddress((void**)&p_h, g_h);     cudaGetSymbolAddress((void**)&p_c, g_c);
    cudaGetSymbolAddress((void**)&p_u, g_u);     cudaGetSymbolAddress((void**)&p_ub, g_ub);
    cudaGetSymbolAddress((void**)&p_biasp, g_biasp);

    cudaFuncSetAttribute(mma_gemm<128, 128, 64, 32, 0>, cudaFuncAttributeMaxDynamicSharedMemorySize, SMEM_BIG);
    cudaFuncSetAttribute(mma_gemm<128, 128, 64, 32, 1>, cudaFuncAttributeMaxDynamicSharedMemorySize, SMEM_BIG);
    cudaFuncSetAttribute(mma_gemm<128, 128, 64, 32, 2>, cudaFuncAttributeMaxDynamicSharedMemorySize, SMEM_BIG);
    cudaFuncSetAttribute(lstm_persist, cudaFuncAttributeMaxDynamicSharedMemorySize, SMEM_LSTM);

    // 1) prep  2) v split  3) W_down round  4) W_ih perm-round
    prep_kernel<<<(HIN + G4 + HIN * HIN / 4) / 256, 256>>>(Wvt, wtw, wtb, bih, bhh);
    conv_split2<<<dim3((KPAD / 4 + 255) / 256, ML), 256>>>(v, N_SZ, N_SZ, KPAD, p_vh, p_vl);
    conv_round<<<dim3((KPAD / 4 + 255) / 256, HIN), 256>>>(Wd, N_SZ, N_SZ, KPAD, p_wd);
    conv_perm_round<<<dim3(1, G4), 256>>>(Wih, HIN, p_wih);

    // 5) GEMM1 (split-K=4 -> 256 CTAs): partials = v @ W_down^T
    mma_gemm<128, 128, 64, 32, 0><<<dim3(HIN / 128, ML / 128, KSPLIT), 256, SMEM_BIG>>>(
        p_vh, p_vl, KPAD, p_wd, KPAD, KCHUNK,
        p_split, HIN, (size_t)ML * HIN,
        nullptr, nullptr, nullptr, nullptr, nullptr);

    // 6) reduce partials -> vd fp16 split
    reduce_conv<<<(ML * HIN) / 256, 256>>>();

    // 7) GEMM2: inputs = vd @ Wvt_s^T + t[m]*u[n] + ub[n] -> fp16 split
    mma_gemm<128, 128, 64, 32, 1><<<dim3(HIN / 128, ML / 128), 256, SMEM_BIG>>>(
        p_vdh, p_vdl, HIN, p_wvt, HIN, HIN,
        nullptr, HIN, 0, p_ub, t, p_u, p_ih, p_il);

    // 8) GEMM3: xg = inputs @ Wih_perm^T + bias_perm (gate-permuted cols)
    mma_gemm<128, 128, 64, 32, 2><<<dim3(G4 / 128, ML / 128), 256, SMEM_BIG>>>(
        p_ih, p_il, HIN, p_wih, HIN, HIN,
        p_xg, G4, 0, p_biasp, nullptr, nullptr, nullptr, nullptr);

    // 9) W_hh perm-round (only needed from here)  10) step0  11) persistent scan
    conv_perm_round<<<dim3(2, G4), 256>>>(Whh, H_SZ, p_whh);
    lstm_step0<<<(B_SZ * H_SZ) / 256, 256>>>();
    lstm_persist<<<dim3(G4 / 64, B_SZ / 32), 128, SMEM_LSTM>>>(
        p_hh, p_hl, p_whh, p_xg, p_c, p_h, p_hh, p_hl);

    // 12) pred
    pred_kernel<<<B_SZ, 128>>>(lw, lb, out);
}

// round 7
// speedup vs baseline: 5.0843x; 1.0682x over previous
#include <cuda_runtime.h>
#include <cuda_fp16.h>
#include <cstdint>
#include <math.h>

// ---------------- dims ------------------------------------------------------
#define B_SZ 128
#define L_SZ 16
#define N_SZ 20000
#define HIN  512
#define H_SZ 1024
#define G4   4096
#define ML   2048
#define KSPLIT 4
// split-K chunks: 5024,5024,5024,4928 (all %32==0, sum 20000)

// ---------------- device global scratch ------------------------------------
__device__ __half g_wd[(size_t)HIN * N_SZ];       // W_down rounded fp16
__device__ float g_split[KSPLIT * ML * HIN];
__device__ __half g_vdh[ML * HIN];                // vd split
__device__ __half g_vdl[ML * HIN];
__device__ __half g_wvt[HIN * HIN];               // W_vt[:, :512] rounded
__device__ __half g_ih[ML * HIN];                 // inputs split
__device__ __half g_il[ML * HIN];
__device__ __half g_wih[G4 * HIN];                // W_ih permuted rounded
__device__ __half g_whh[(size_t)G4 * H_SZ];       // W_hh permuted rounded
__device__ float g_xg[(size_t)ML * G4];           // permuted gate cols
__device__ __half g_hh[2 * B_SZ * H_SZ];          // h split, double buffered
__device__ __half g_hl[2 * B_SZ * H_SZ];
__device__ float g_h[B_SZ * H_SZ];
__device__ float g_c[B_SZ * H_SZ];
__device__ float g_u[HIN];
__device__ float g_ub[HIN];
__device__ float g_biasp[G4];
__device__ unsigned g_bar;

// ---------------- helpers ---------------------------------------------------
__device__ __forceinline__ uint32_t smem_u32(const void* p) {
    uint32_t a;
    asm("{ .reg .u64 t; cvta.to.shared.u64 t, %1; cvt.u32.u64 %0, t; }" : "=r"(a) : "l"(p));
    return a;
}
__device__ __forceinline__ void cp_async16(uint32_t dst, const void* src) {
    asm volatile("cp.async.cg.shared.global [%0], [%1], 16;" :: "r"(dst), "l"(src));
}
__device__ __forceinline__ void cp_commit() {
    asm volatile("cp.async.commit_group;" ::: "memory");
}
__device__ __forceinline__ void cp_wait2() {
    asm volatile("cp.async.wait_group 2;" ::: "memory");
}
__device__ __forceinline__ void ldsm4(uint32_t* r, uint32_t addr) {
    asm volatile("ldmatrix.sync.aligned.m8n8.x4.shared.b16 {%0,%1,%2,%3}, [%4];"
        : "=r"(r[0]), "=r"(r[1]), "=r"(r[2]), "=r"(r[3]) : "r"(addr));
}
__device__ __forceinline__ void mma16816(float* c, const uint32_t* a, const uint32_t* b) {
    asm volatile("mma.sync.aligned.m16n8k16.row.col.f32.f16.f16.f32 "
        "{%0,%1,%2,%3}, {%4,%5,%6,%7}, {%8,%9}, {%0,%1,%2,%3};"
        : "+f"(c[0]), "+f"(c[1]), "+f"(c[2]), "+f"(c[3])
        : "r"(a[0]), "r"(a[1]), "r"(a[2]), "r"(a[3]), "r"(b[0]), "r"(b[1]));
}
__device__ __forceinline__ float sigf(float x) { return 1.f / (1.f + expf(-x)); }
__device__ __forceinline__ void split_h(float x, __half& hi, __half& lo) {
    hi = __float2half_rn(x);
    lo = __float2half_rn(x - __half2float(hi));
}

// fp16 smem tile: 64B rows; 16B chunk c of row r at r*64 + ((c*16) ^ (((r>>1)&3)<<4))
// fp32 smem tile: 128B rows; 16B chunk c of row r at r*128 + ((c ^ (r&7))*16)

// ---------------- GEMM1: fused fp32-A split + 2-term fp16 HMMA --------------
// C_partial[z] = v_fp32 @ W_down_fp16^T over k chunk z.
__global__ void __launch_bounds__(256, 2)
gemm1_fused(const float* __restrict__ Afp, int lda,
            const __half* __restrict__ Bm, int ldb,
            float* __restrict__ C, int ldc, size_t zstride)
{
    constexpr int BM = 128, BN = 128, WM = 64, WN = 32, MF = 4, NF = 4;
    constexpr int A32S  = 128 * 128;               // fp32 stage bytes
    constexpr int B16S  = 128 * 64;                // fp16 B stage bytes
    constexpr int OFF_B  = 3 * A32S;               // 49152
    constexpr int OFF_AH = OFF_B + 3 * B16S;       // 73728
    constexpr int OFF_AL = OFF_AH + 8192;          // 81920 (total 90112)

    extern __shared__ char smem[];
    const uint32_t sbase = smem_u32(smem);
    const int tid  = threadIdx.x;
    const int lane = tid & 31;
    const int warp = tid >> 5;
    const int wm0 = (warp / (BN / WN)) * WM;
    const int wn0 = (warp % (BN / WN)) * WN;
    const int m0 = blockIdx.y * BM;
    const int n0 = blockIdx.x * BN;
    const int kbase = blockIdx.z * 5024;
    const int Kz = (blockIdx.z == 3) ? 4928 : 5024;
    C += (size_t)blockIdx.z * zstride;

    float acc[MF][NF][4];
    #pragma unroll
    for (int i = 0; i < MF; i++)
        #pragma unroll
        for (int j = 0; j < NF; j++)
            #pragma unroll
            for (int q = 0; q < 4; q++) acc[i][j][q] = 0.f;

    auto load_stage = [&](int kt, int s) {
        const int k0 = kbase + kt * 32;
        #pragma unroll
        for (int q = 0; q < 6; q++) {
            const int i = tid + q * 256;
            if (i < 1024) {                       // A fp32: 128 rows x 8 chunks
                int row = i >> 3, c = i & 7;
                uint32_t dst = sbase + s * A32S + row * 128 + ((c ^ (row & 7)) << 4);
                cp_async16(dst, Afp + (size_t)(m0 + row) * lda + k0 + c * 4);
            } else {                              // B fp16: 128 rows x 4 chunks
                int j = i - 1024; int row = j >> 2, c = j & 3;
                uint32_t dst = sbase + OFF_B + s * B16S + row * 64 +
                               ((c * 16) ^ (((row >> 1) & 3) << 4));
                cp_async16(dst, Bm + (size_t)(n0 + row) * ldb + k0 + c * 8);
            }
        }
    };

    const int KT = Kz >> 5;
    load_stage(0, 0); cp_commit();
    load_stage(1, 1); cp_commit();

    const int li  = lane & 15;
    const int khb = (lane >> 4) << 4;
    const int swz = ((li >> 1) & 3) << 4;
    const int cr = tid & 127;          // convert: row
    const int cj = tid >> 7;           // convert: k-half (0 or 1)

    for (int kt = 0; kt < KT; kt++) {
        const int s = kt % 3;
        if (kt + 2 < KT) load_stage(kt + 2, (kt + 2) % 3);
        cp_commit();
        cp_wait2();
        __syncthreads();

        // ---- convert A32[s] -> Ah/Al (this thread: row cr, k 16*cj..16*cj+15)
        {
            const char* a32 = smem + s * A32S + cr * 128;
            #pragma unroll
            for (int q2 = 0; q2 < 2; q2++) {
                const int c32a = 4 * cj + 2 * q2;
                float4 f0 = *reinterpret_cast<const float4*>(a32 + (((c32a)     ^ (cr & 7)) << 4));
                float4 f1 = *reinterpret_cast<const float4*>(a32 + (((c32a + 1) ^ (cr & 7)) << 4));
                __half h[8], l[8];
                split_h(f0.x, h[0], l[0]); split_h(f0.y, h[1], l[1]);
                split_h(f0.z, h[2], l[2]); split_h(f0.w, h[3], l[3]);
                split_h(f1.x, h[4], l[4]); split_h(f1.y, h[5], l[5]);
                split_h(f1.z, h[6], l[6]); split_h(f1.w, h[7], l[7]);
                uint4 ph, pl;
                __half2 t0, t1, t2, t3;
                t0.x = h[0]; t0.y = h[1]; t1.x = h[2]; t1.y = h[3];
                t2.x = h[4]; t2.y = h[5]; t3.x = h[6]; t3.y = h[7];
                ph.x = *reinterpret_cast<uint32_t*>(&t0); ph.y = *reinterpret_cast<uint32_t*>(&t1);
                ph.z = *reinterpret_cast<uint32_t*>(&t2); ph.w = *reinterpret_cast<uint32_t*>(&t3);
                t0.x = l[0]; t0.y = l[1]; t1.x = l[2]; t1.y = l[3];
                t2.x = l[4]; t2.y = l[5]; t3.x = l[6]; t3.y = l[7];
                pl.x = *reinterpret_cast<uint32_t*>(&t0); pl.y = *reinterpret_cast<uint32_t*>(&t1);
                pl.z = *reinterpret_cast<uint32_t*>(&t2); pl.w = *reinterpret_cast<uint32_t*>(&t3);
                const int cH = 2 * cj + q2;
                const uint32_t so = cr * 64 + ((cH * 16) ^ (((cr >> 1) & 3) << 4));
                *reinterpret_cast<uint4*>(smem + OFF_AH + so) = ph;
                *reinterpret_cast<uint4*>(smem + OFF_AL + so) = pl;
            }
        }
        __syncthreads();

        // ---- HMMA from Ah/Al (single buffer) + B16[s]
        const uint32_t tAh = sbase + OFF_AH;
        const uint32_t tAl = sbase + OFF_AL;
        const uint32_t tB  = sbase + OFF_B + s * B16S;
        #pragma unroll
        for (int kk = 0; kk < 2; kk++) {
            const int cb = kk * 32;
            const uint32_t coff = (uint32_t)((cb + khb) ^ swz);
            uint32_t ah[MF][4], al_[MF][4];
            #pragma unroll
            for (int mf = 0; mf < MF; mf++) {
                uint32_t ro = (wm0 + mf * 16 + li) * 64 + coff;
                ldsm4(ah[mf],  tAh + ro);
                ldsm4(al_[mf], tAl + ro);
            }
            uint32_t bh[NF][2];
            #pragma unroll
            for (int nf2 = 0; nf2 < NF / 2; nf2++) {
                uint32_t ro = (wn0 + nf2 * 16 + li) * 64 + coff;
                uint32_t t[4];
                ldsm4(t, tB + ro);
                bh[2 * nf2][0] = t[0]; bh[2 * nf2][1] = t[2];
                bh[2 * nf2 + 1][0] = t[1]; bh[2 * nf2 + 1][1] = t[3];
            }
            #pragma unroll
            for (int mf = 0; mf < MF; mf++)
                #pragma unroll
                for (int nf = 0; nf < NF; nf++) {
                    mma16816(acc[mf][nf], ah[mf],  bh[nf]);
                    mma16816(acc[mf][nf], al_[mf], bh[nf]);
                }
        }
        __syncthreads();
    }

    // ---- epilogue: fp32 partials, coalesced ----
    float* st = reinterpret_cast<float*>(smem) + warp * (WM * 33);
    #pragma unroll
    for (int mf = 0; mf < MF; mf++)
        #pragma unroll
        for (int nf = 0; nf < NF; nf++)
            #pragma unroll
            for (int i = 0; i < 2; i++) {
                int r = mf * 16 + (lane >> 2) + 8 * i;
                int c = nf * 8 + 2 * (lane & 3);
                st[r * 33 + c]     = acc[mf][nf][2 * i];
                st[r * 33 + c + 1] = acc[mf][nf][2 * i + 1];
            }
    __syncwarp();
    #pragma unroll
    for (int rr = lane; rr < WM; rr += 32) {
        const int m = m0 + wm0 + rr;
        #pragma unroll
        for (int c4 = 0; c4 < WN; c4 += 4) {
            float4 v;
            v.x = st[rr * 33 + c4];     v.y = st[rr * 33 + c4 + 1];
            v.z = st[rr * 33 + c4 + 2]; v.w = st[rr * 33 + c4 + 3];
            *reinterpret_cast<float4*>(C + (size_t)m * ldc + n0 + wn0 + c4) = v;
        }
    }
}

// ---------------- generic 2-term fp16 GEMM (modes 1,2) ----------------------
// MODE 1: += srow[m]*ucol[n] + bias[n]; fp16-split out to Ch/Cl
// MODE 2: += bias[n]; fp32 out
template<int BM, int BN, int WM, int WN, int MODE>
__global__ void __launch_bounds__((BM / WM) * (BN / WN) * 32)
mma_gemm(const __half* __restrict__ Ah, const __half* __restrict__ Al, int lda,
         const __half* __restrict__ Bm, int ldb, int K,
         float* __restrict__ C, int ldc,
         const float* __restrict__ bias,
         const float* __restrict__ srow, const float* __restrict__ ucol,
         __half* __restrict__ Ch, __half* __restrict__ Cl)
{
    constexpr int NT = (BM / WM) * (BN / WN) * 32;
    constexpr int MF = WM / 16;
    constexpr int NF = WN / 8;
    constexpr int STAGE = (2 * BM + BN) * 64;
    constexpr int CHA = BM * 4;
    constexpr int CHB = BN * 4;
    constexpr int CHT = 2 * CHA + CHB;

    extern __shared__ char smem[];
    const uint32_t sbase = smem_u32(smem);
    const int tid  = threadIdx.x;
    const int lane = tid & 31;
    const int warp = tid >> 5;
    const int wm0 = (warp / (BN / WN)) * WM;
    const int wn0 = (warp % (BN / WN)) * WN;
    const int m0 = blockIdx.y * BM;
    const int n0 = blockIdx.x * BN;

    float acc[MF][NF][4];
    #pragma unroll
    for (int i = 0; i < MF; i++)
        #pragma unroll
        for (int j = 0; j < NF; j++)
            #pragma unroll
            for (int q = 0; q < 4; q++) acc[i][j][q] = 0.f;

    auto load_stage = [&](int kt, int s) {
        const int k0 = kt * 32;
        const uint32_t tb = sbase + s * STAGE;
        #pragma unroll
        for (int q = 0; q < CHT / NT; q++) {
            const int i = tid + q * NT;
            const __half* src;
            int toff, rr;
            if (i < CHA) {
                rr = i >> 2; src = Ah + (size_t)(m0 + rr) * lda; toff = 0;
            } else if (i < 2 * CHA) {
                int j = i - CHA; rr = j >> 2;
                src = Al + (size_t)(m0 + rr) * lda; toff = BM * 64;
            } else {
                int j = i - 2 * CHA; rr = j >> 2;
                src = Bm + (size_t)(n0 + rr) * ldb; toff = 2 * BM * 64;
            }
            const int c = i & 3;
            uint32_t dst = tb + toff + rr * 64 + ((c * 16) ^ (((rr >> 1) & 3) << 4));
            cp_async16(dst, src + k0 + c * 8);
        }
    };

    const int KT = K >> 5;
    load_stage(0, 0); cp_commit();
    load_stage(1, 1); cp_commit();

    const int li  = lane & 15;
    const int khb = (lane >> 4) << 4;
    const int swz = ((li >> 1) & 3) << 4;

    for (int kt = 0; kt < KT; kt++) {
        const int s = kt % 3;
        if (kt + 2 < KT) load_stage(kt + 2, (kt + 2) % 3);
        cp_commit();
        cp_wait2();
        __syncthreads();

        const uint32_t tA  = sbase + s * STAGE;
        const uint32_t tAl = tA + BM * 64;
        const uint32_t tB  = tA + 2 * BM * 64;

        #pragma unroll
        for (int kk = 0; kk < 2; kk++) {
            const int cb = kk * 32;
            const uint32_t coff = (uint32_t)((cb + khb) ^ swz);
            uint32_t ah[MF][4], al_[MF][4];
            #pragma unroll
            for (int mf = 0; mf < MF; mf++) {
                uint32_t ro = (wm0 + mf * 16 + li) * 64 + coff;
                ldsm4(ah[mf],  tA  + ro);
                ldsm4(al_[mf], tAl + ro);
            }
            uint32_t bh[NF][2];
            #pragma unroll
            for (int nf2 = 0; nf2 < NF / 2; nf2++) {
                uint32_t ro = (wn0 + nf2 * 16 + li) * 64 + coff;
                uint32_t t[4];
                ldsm4(t, tB + ro);
                bh[2 * nf2][0] = t[0]; bh[2 * nf2][1] = t[2];
                bh[2 * nf2 + 1][0] = t[1]; bh[2 * nf2 + 1][1] = t[3];
            }
            #pragma unroll
            for (int mf = 0; mf < MF; mf++)
                #pragma unroll
                for (int nf = 0; nf < NF; nf++) {
                    mma16816(acc[mf][nf], ah[mf],  bh[nf]);
                    mma16816(acc[mf][nf], al_[mf], bh[nf]);
                }
        }
        __syncthreads();
    }

    float* st = reinterpret_cast<float*>(smem) + warp * (WM * 33);
    #pragma unroll
    for (int mf = 0; mf < MF; mf++)
        #pragma unroll
        for (int nf = 0; nf < NF; nf++)
            #pragma unroll
            for (int i = 0; i < 2; i++) {
                int r = mf * 16 + (lane >> 2) + 8 * i;
                int c = nf * 8 + 2 * (lane & 3);
                st[r * 33 + c]     = acc[mf][nf][2 * i];
                st[r * 33 + c + 1] = acc[mf][nf][2 * i + 1];
            }
    __syncwarp();
    #pragma unroll
    for (int rr = lane; rr < WM; rr += 32) {
        const int m = m0 + wm0 + rr;
        const int nbase = n0 + wn0;
        if (MODE == 1) {
            const float tm = srow[m];
            #pragma unroll
            for (int c = 0; c < WN; c += 2) {
                int n = nbase + c;
                float v0 = st[rr * 33 + c]     + tm * ucol[n]     + bias[n];
                float v1 = st[rr * 33 + c + 1] + tm * ucol[n + 1] + bias[n + 1];
                __half h0, l0, h1, l1;
                split_h(v0, h0, l0); split_h(v1, h1, l1);
                __half2 ph; ph.x = h0; ph.y = h1;
                __half2 pl; pl.x = l0; pl.y = l1;
                *reinterpret_cast<__half2*>(Ch + (size_t)m * ldc + n) = ph;
                *reinterpret_cast<__half2*>(Cl + (size_t)m * ldc + n) = pl;
            }
        } else {
            #pragma unroll
            for (int c4 = 0; c4 < WN; c4 += 4) {
                float4 v;
                v.x = st[rr * 33 + c4];
                v.y = st[rr * 33 + c4 + 1];
                v.z = st[rr * 33 + c4 + 2];
                v.w = st[rr * 33 + c4 + 3];
                int n = nbase + c4;
                v.x += bias[n]; v.y += bias[n + 1];
                v.z += bias[n + 2]; v.w += bias[n + 3];
                *reinterpret_cast<float4*>(C + (size_t)m * ldc + nbase + c4) = v;
            }
        }
    }
}

// ---------------- persistent fused LSTM (steps 0..15, one launch) ------------
// grid (G4/64, B_SZ/32) = 256 CTAs x 128 threads, all resident.
__global__ void __launch_bounds__(128)
lstm_persist(const __half* __restrict__ hhb, const __half* __restrict__ hlb,
             const __half* __restrict__ Bm,
             const float* __restrict__ xg, float* __restrict__ cstate,
             float* __restrict__ houtf,
             __half* __restrict__ hhw, __half* __restrict__ hlw)
{
    constexpr int BM = 32, BN = 64, NT = 128, NF = 4;
    constexpr int STAGE = (2 * BM + BN) * 64;    // 8192
    constexpr int CHA = BM * 4, CHB = BN * 4, CHT = 2 * CHA + CHB;

    extern __shared__ char smem[];
    const uint32_t sbase = smem_u32(smem);
    const int tid  = threadIdx.x;
    const int lane = tid & 31;
    const int warp = tid >> 5;
    const int wm0 = (warp >> 1) * 16;
    const int wn0 = (warp & 1) * 32;
    const int m0 = blockIdx.y * BM;
    const int n0 = blockIdx.x * BN;
    const int li  = lane & 15;
    const int khb = (lane >> 4) << 4;
    const int swz = ((li >> 1) & 3) << 4;

    // ---- step 0: h=c=0, gates = xg row (epilogue only) ----
    {
        __half* Oh = hhw;   // buffer 0
        __half* Ol = hlw;
        const float* xgl = xg;   // l = 0
        #pragma unroll
        for (int qsel = 0; qsel < NF / 2; qsel++) {
            const int nb = n0 + wn0 + qsel * 16;
            const int a  = lane & 3;
            const int j  = 4 * (nb >> 4) + a;
            #pragma unroll
            for (int i = 0; i < 2; i++) {
                const int m = m0 + wm0 + (lane >> 2) + 8 * i;
                const float* xrow = xgl + (size_t)m * (L_SZ * G4);
                float2 xif = *reinterpret_cast<const float2*>(xrow + nb + 2 * a);
                float2 xgo = *reinterpret_cast<const float2*>(xrow + nb + 8 + 2 * a);
                float ig = sigf(xif.x);
                float gg = tanhf(xgo.x), og = sigf(xgo.y);
                const int gi = (m << 10) + j;
                float cv = ig * gg;
                cstate[gi] = cv;
                float hv = og * tanhf(cv);
                __half hi, lo; split_h(hv, hi, lo);
                Oh[gi] = hi; Ol[gi] = lo;
            }
        }
        __threadfence();
        __syncthreads();
        if (tid == 0) {
            atomicAdd(&g_bar, 1u);
            volatile unsigned* vb = &g_bar;
            while (*vb < 256u) { }
        }
        __syncthreads();
    }

    for (int l = 1; l < L_SZ; l++) {
        const __half* Ah = hhb + (size_t)((l + 1) & 1) * (B_SZ * H_SZ);
        const __half* Al = hlb + (size_t)((l + 1) & 1) * (B_SZ * H_SZ);
        __half* Oh = hhw + (size_t)(l & 1) * (B_SZ * H_SZ);
        __half* Ol = hlw + (size_t)(l & 1) * (B_SZ * H_SZ);
        const float* xgl = xg + (size_t)l * G4;

        float acc[NF][4];
        #pragma unroll
        for (int j = 0; j < NF; j++)
            #pragma unroll
            for (int q = 0; q < 4; q++) acc[j][q] = 0.f;

        auto load_stage = [&](int kt, int s) {
            const int k0 = kt * 32;
            const uint32_t tb = sbase + s * STAGE;
            #pragma unroll
            for (int q = 0; q < CHT / NT; q++) {
                const int i = tid + q * NT;
                const __half* src;
                int toff, rr;
                if (i < CHA) {
                    rr = i >> 2; src = Ah + (size_t)(m0 + rr) * H_SZ; toff = 0;
                } else if (i < 2 * CHA) {
                    int j = i - CHA; rr = j >> 2;
                    src = Al + (size_t)(m0 + rr) * H_SZ; toff = BM * 64;
                } else {
                    int j = i - 2 * CHA; rr = j >> 2;
                    src = Bm + (size_t)(n0 + rr) * H_SZ; toff = 2 * BM * 64;
                }
                const int c = i & 3;
                uint32_t dst = tb + toff + rr * 64 + ((c * 16) ^ (((rr >> 1) & 3) << 4));
                cp_async16(dst, src + k0 + c * 8);
            }
        };

        const int KT = H_SZ >> 5;   // 32
        load_stage(0, 0); cp_commit();
        load_stage(1, 1); cp_commit();

        for (int kt = 0; kt < KT; kt++) {
            const int s = kt % 3;
            if (kt + 2 < KT) load_stage(kt + 2, (kt + 2) % 3);
            cp_commit();
            cp_wait2();
            __syncthreads();

            const uint32_t tA  = sbase + s * STAGE;
            const uint32_t tAl = tA + BM * 64;
            const uint32_t tB  = tA + 2 * BM * 64;

            #pragma unroll
            for (int kk = 0; kk < 2; kk++) {
                const int cb = kk * 32;
                const uint32_t coff = (uint32_t)((cb + khb) ^ swz);
                uint32_t ah[4], al_[4];
                {
                    uint32_t ro = (wm0 + li) * 64 + coff;
                    ldsm4(ah,  tA  + ro);
                    ldsm4(al_, tAl + ro);
                }
                uint32_t bh[NF][2];
                #pragma unroll
                for (int nf2 = 0; nf2 < NF / 2; nf2++) {
                    uint32_t ro = (wn0 + nf2 * 16 + li) * 64 + coff;
                    uint32_t t[4];
                    ldsm4(t, tB + ro);
                    bh[2 * nf2][0] = t[0]; bh[2 * nf2][1] = t[2];
                    bh[2 * nf2 + 1][0] = t[1]; bh[2 * nf2 + 1][1] = t[3];
                }
                #pragma unroll
                for (int nf = 0; nf < NF; nf++) {
                    mma16816(acc[nf], ah,  bh[nf]);
                    mma16816(acc[nf], al_, bh[nf]);
                }
            }
            __syncthreads();
        }

        // fused gate nonlinearity + state update
        #pragma unroll
        for (int qsel = 0; qsel < NF / 2; qsel++) {
            const int nb = n0 + wn0 + qsel * 16;
            const int a  = lane & 3;
            const int j  = 4 * (nb >> 4) + a;
            #pragma unroll
            for (int i = 0; i < 2; i++) {
                const int m = m0 + wm0 + (lane >> 2) + 8 * i;
                const float* xrow = xgl + (size_t)m * (L_SZ * G4);
                float2 xif = *reinterpret_cast<const float2*>(xrow + nb + 2 * a);
                float2 xgo = *reinterpret_cast<const float2*>(xrow + nb + 8 + 2 * a);
                float xi = acc[2 * qsel][2 * i]         + xif.x;
                float xf = acc[2 * qsel][2 * i + 1]     + xif.y;
                float xgv = acc[2 * qsel + 1][2 * i]    + xgo.x;
                float xo = acc[2 * qsel + 1][2 * i + 1] + xgo.y;
                float ig = sigf(xi), fg = sigf(xf);
                float gg = tanhf(xgv), og = sigf(xo);
                const int gi = (m << 10) + j;
                float cv = fg * cstate[gi] + ig * gg;
                cstate[gi] = cv;
                float hv = og * tanhf(cv);
                if (l == L_SZ - 1) houtf[gi] = hv;
                __half hi, lo; split_h(hv, hi, lo);
                Oh[gi] = hi; Ol[gi] = lo;
            }
        }

        __threadfence();
        __syncthreads();
        if (tid == 0) {
            atomicAdd(&g_bar, 1u);
            volatile unsigned* vb = &g_bar;
            const unsigned target = 256u * (unsigned)(l + 1);
            while (*vb < target) { }
        }
        __syncthreads();
    }
}

// ---------------- converts ---------------------------------------------------
// fp32 -> fp16 rounded
__global__ void conv_round(const float* __restrict__ src, int C, int srcld,
                           __half* __restrict__ dst)
{
    int c4 = (blockIdx.x * blockDim.x + threadIdx.x) * 4;
    int r = blockIdx.y;
    if (c4 >= C) return;
    float4 x = *reinterpret_cast<const float4*>(src + (size_t)r * srcld + c4);
    size_t o = (size_t)r * C + c4;
    __half2 a; a.x = __float2half_rn(x.x); a.y = __float2half_rn(x.y);
    __half2 b; b.x = __float2half_rn(x.z); b.y = __float2half_rn(x.w);
    *reinterpret_cast<__half2*>(dst + o)     = a;
    *reinterpret_cast<__half2*>(dst + o + 2) = b;
}

// gate permutation + round: new row r -> orig = gate*1024 + cell
__global__ void conv_perm_round(const float* __restrict__ src, int cols,
                                __half* __restrict__ dst)
{
    int c4 = (blockIdx.x * blockDim.x + threadIdx.x) * 4;
    int r = blockIdx.y;
    if (c4 >= cols) return;
    int gate = ((r >> 3) & 1) * 2 + (r & 1);
    int cell = 4 * (r >> 4) + ((r >> 1) & 3);
    int orig = gate * 1024 + cell;
    float4 x = *reinterpret_cast<const float4*>(src + (size_t)orig * cols + c4);
    size_t o = (size_t)r * cols + c4;
    __half2 a; a.x = __float2half_rn(x.x); a.y = __float2half_rn(x.y);
    __half2 b; b.x = __float2half_rn(x.z); b.y = __float2half_rn(x.w);
    *reinterpret_cast<__half2*>(dst + o)     = a;
    *reinterpret_cast<__half2*>(dst + o + 2) = b;
}

// prep: time-embed fold, permuted bias, W_vt round, barrier reset
__global__ void prep_kernel(const float* __restrict__ Wvt,
                            const float* __restrict__ wtw,
                            const float* __restrict__ wtb,
                            const float* __restrict__ bih,
                            const float* __restrict__ bhh)
{
    int i = blockIdx.x * blockDim.x + threadIdx.x;
    if (i == 0) g_bar = 0;
    if (i < HIN) {
        const float* row = Wvt + (size_t)i * (HIN + 128) + HIN;
        float u = 0.f, ub = 0.f;
        #pragma unroll 4
        for (int j = 0; j < 128; j++) { float w = row[j]; u += w * wtw[j]; ub += w * wtb[j]; }
        g_u[i] = u; g_ub[i] = ub;
    } else if (i < HIN + G4) {
        int r = i - HIN;
        int gate = ((r >> 3) & 1) * 2 + (r & 1);
        int cell = 4 * (r >> 4) + ((r >> 1) & 3);
        g_biasp[r] = bih[gate * 1024 + cell] + bhh[gate * 1024 + cell];
    } else if (i < HIN + G4 + HIN * HIN / 4) {
        int w = i - (HIN + G4);
        int r = w >> 7;
        int c4 = (w & 127) * 4;
        float4 x = *reinterpret_cast<const float4*>(Wvt + (size_t)r * (HIN + 128) + c4);
        size_t o = (size_t)r * HIN + c4;
        __half2 a; a.x = __float2half_rn(x.x); a.y = __float2half_rn(x.y);
        __half2 b; b.x = __float2half_rn(x.z); b.y = __float2half_rn(x.w);
        *reinterpret_cast<__half2*>(g_wvt + o)     = a;
        *reinterpret_cast<__half2*>(g_wvt + o + 2) = b;
    }
}

__global__ void reduce_conv(void)
{
    int idx = blockIdx.x * 256 + threadIdx.x;
    float s = 0.f;
    #pragma unroll
    for (int z = 0; z < KSPLIT; z++) s += g_split[(size_t)z * ML * HIN + idx];
    __half hi, lo; split_h(s, hi, lo);
    g_vdh[idx] = hi; g_vdl[idx] = lo;
}

__global__ void pred_kernel(const float* __restrict__ lw,
                            const float* __restrict__ lb,
                            float* __restrict__ out)
{
    int b = blockIdx.x, tid = threadIdx.x;
    const float* hr = g_h + (size_t)b * H_SZ;
    float s = 0.f;
    for (int k = tid; k < H_SZ; k += 128) s += hr[k] * lw[k];
    __shared__ float red[128];
    red[tid] = s; __syncthreads();
    for (int off = 64; off > 0; off >>= 1) {
        if (tid < off) red[tid] += red[tid + off];
        __syncthreads();
    }
    if (tid == 0) out[b] = red[0] + lb[0];
}

// ---------------- launch -----------------------------------------------------
#define SMEM_G1   90112                          // 3*16K A32 + 3*8K B + 2*8K A16
#define SMEM_BIG  ((2 * 128 + 128) * 64 * 3)     // 73728
#define SMEM_LSTM ((2 * 32 + 64) * 64 * 3)       // 24576

extern "C" void kernel_launch(void* const* d_in, const int* in_sizes, int n_in,
                              void* d_out, int out_size)
{
    const float* v   = (const float*)d_in[0];
    const float* t   = (const float*)d_in[1];
    const float* Wd  = (const float*)d_in[2];
    const float* wtw = (const float*)d_in[3];
    const float* wtb = (const float*)d_in[4];
    const float* Wvt = (const float*)d_in[5];
    const float* Wih = (const float*)d_in[6];
    const float* Whh = (const float*)d_in[7];
    const float* bih = (const float*)d_in[8];
    const float* bhh = (const float*)d_in[9];
    const float* lw  = (const float*)d_in[10];
    const float* lb  = (const float*)d_in[11];
    float* out = (float*)d_out;

    __half *p_wd, *p_vdh, *p_vdl, *p_wvt, *p_ih, *p_il, *p_wih, *p_whh, *p_hh, *p_hl;
    float *p_split, *p_xg, *p_h, *p_c, *p_u, *p_ub, *p_biasp;
    cudaGetSymbolAddress((void**)&p_wd, g_wd);
    cudaGetSymbolAddress((void**)&p_vdh, g_vdh); cudaGetSymbolAddress((void**)&p_vdl, g_vdl);
    cudaGetSymbolAddress((void**)&p_wvt, g_wvt);
    cudaGetSymbolAddress((void**)&p_ih, g_ih);   cudaGetSymbolAddress((void**)&p_il, g_il);
    cudaGetSymbolAddress((void**)&p_wih, g_wih); cudaGetSymbolAddress((void**)&p_whh, g_whh);
    cudaGetSymbolAddress((void**)&p_hh, g_hh);   cudaGetSymbolAddress((void**)&p_hl, g_hl);
    cudaGetSymbolAddress((void**)&p_split, g_split);
    cudaGetSymbolAddress((void**)&p_xg, g_xg);
    cudaGetSymbolAddress((void**)&p_h, g_h);     cudaGetSymbolAddress((void**)&p_c, g_c);
    cudaGetSymbolAddress((void**)&p_u, g_u);     cudaGetSymbolAddress((void**)&p_ub, g_ub);
    cudaGetSymbolAddress((void**)&p_biasp, g_biasp);

    cudaFuncSetAttribute(gemm1_fused, cudaFuncAttributeMaxDynamicSharedMemorySize, SMEM_G1);
    cudaFuncSetAttribute(mma_gemm<128, 128, 64, 32, 1>, cudaFuncAttributeMaxDynamicSharedMemorySize, SMEM_BIG);
    cudaFuncSetAttribute(mma_gemm<128, 128, 64, 32, 2>, cudaFuncAttributeMaxDynamicSharedMemorySize, SMEM_BIG);
    cudaFuncSetAttribute(lstm_persist, cudaFuncAttributeMaxDynamicSharedMemorySize, SMEM_LSTM);

    // 1) prep  2) W_down round  3) W_ih perm-round
    prep_kernel<<<(HIN + G4 + HIN * HIN / 4) / 256, 256>>>(Wvt, wtw, wtb, bih, bhh);
    conv_round<<<dim3((N_SZ / 4 + 255) / 256, HIN), 256>>>(Wd, N_SZ, N_SZ, p_wd);
    conv_perm_round<<<dim3(1, G4), 256>>>(Wih, HIN, p_wih);

    // 4) GEMM1 (fused fp32-A split, split-K=4): partials = v @ W_down^T
    gemm1_fused<<<dim3(HIN / 128, ML / 128, KSPLIT), 256, SMEM_G1>>>(
        v, N_SZ, p_wd, N_SZ, p_split, HIN, (size_t)ML * HIN);

    // 5) reduce partials -> vd fp16 split
    reduce_conv<<<(ML * HIN) / 256, 256>>>();

    // 6) GEMM2: inputs = vd @ Wvt_s^T + t[m]*u[n] + ub[n] -> fp16 split
    mma_gemm<128, 128, 64, 32, 1><<<dim3(HIN / 128, ML / 128), 256, SMEM_BIG>>>(
        p_vdh, p_vdl, HIN, p_wvt, HIN, HIN,
        nullptr, HIN, p_ub, t, p_u, p_ih, p_il);

    // 7) GEMM3: xg = inputs @ Wih_perm^T + bias_perm
    mma_gemm<128, 128, 64, 32, 2><<<dim3(G4 / 128, ML / 128), 256, SMEM_BIG>>>(
        p_ih, p_il, HIN, p_wih, HIN, HIN,
        p_xg, G4, p_biasp, nullptr, nullptr, nullptr, nullptr);

    // 8) W_hh perm-round  9) persistent LSTM steps 0..15
    conv_perm_round<<<dim3(2, G4), 256>>>(Whh, H_SZ, p_whh);
    lstm_persist<<<dim3(G4 / 64, B_SZ / 32), 128, SMEM_LSTM>>>(
        p_hh, p_hl, p_whh, p_xg, p_c, p_h, p_hh, p_hl);

    // 10) pred
    pred_kernel<<<B_SZ, 128>>>(lw, lb, out);
}

// round 9
// speedup vs baseline: 6.4624x; 1.2710x over previous
#include <cuda_runtime.h>
#include <cuda_fp16.h>
#include <cstdint>
#include <math.h>

// ---------------- dims ------------------------------------------------------
#define B_SZ 128
#define L_SZ 16
#define N_SZ 20000
#define HIN  512
#define H_SZ 1024
#define G4   4096
#define ML   2048
#define KSPLIT 4
// split-K chunks: 5024,5024,5024,4928 (all %32==0, sum 20000)

// ---------------- device global scratch ------------------------------------
__device__ __half g_wd[(size_t)HIN * N_SZ];       // W_down rounded fp16
__device__ float g_split[KSPLIT * ML * HIN];
__device__ __half g_vdh[ML * HIN];                // vd split
__device__ __half g_vdl[ML * HIN];
__device__ __half g_wvt[HIN * HIN];               // W_vt[:, :512] rounded
__device__ __half g_ih[ML * HIN];                 // inputs split
__device__ __half g_il[ML * HIN];
__device__ __half g_wih[G4 * HIN];                // W_ih permuted rounded
__device__ __half g_whh[(size_t)G4 * H_SZ];       // W_hh permuted rounded
__device__ float g_xg[(size_t)ML * G4];           // permuted gate cols
__device__ __half g_hh[2 * B_SZ * H_SZ];          // h split, double buffered
__device__ __half g_hl[2 * B_SZ * H_SZ];
__device__ float g_h[B_SZ * H_SZ];
__device__ float g_c[B_SZ * H_SZ];
__device__ float g_u[HIN];
__device__ float g_ub[HIN];
__device__ float g_biasp[G4];
__device__ unsigned g_bar;

// ---------------- helpers ---------------------------------------------------
__device__ __forceinline__ uint32_t smem_u32(const void* p) {
    uint32_t a;
    asm("{ .reg .u64 t; cvta.to.shared.u64 t, %1; cvt.u32.u64 %0, t; }" : "=r"(a) : "l"(p));
    return a;
}
__device__ __forceinline__ void cp_async16(uint32_t dst, const void* src) {
    asm volatile("cp.async.cg.shared.global [%0], [%1], 16;" :: "r"(dst), "l"(src));
}
__device__ __forceinline__ void cp_commit() {
    asm volatile("cp.async.commit_group;" ::: "memory");
}
__device__ __forceinline__ void cp_wait2() {
    asm volatile("cp.async.wait_group 2;" ::: "memory");
}
__device__ __forceinline__ void ldsm4(uint32_t* r, uint32_t addr) {
    asm volatile("ldmatrix.sync.aligned.m8n8.x4.shared.b16 {%0,%1,%2,%3}, [%4];"
        : "=r"(r[0]), "=r"(r[1]), "=r"(r[2]), "=r"(r[3]) : "r"(addr));
}
__device__ __forceinline__ void mma16816(float* c, const uint32_t* a, const uint32_t* b) {
    asm volatile("mma.sync.aligned.m16n8k16.row.col.f32.f16.f16.f32 "
        "{%0,%1,%2,%3}, {%4,%5,%6,%7}, {%8,%9}, {%0,%1,%2,%3};"
        : "+f"(c[0]), "+f"(c[1]), "+f"(c[2]), "+f"(c[3])
        : "r"(a[0]), "r"(a[1]), "r"(a[2]), "r"(a[3]), "r"(b[0]), "r"(b[1]));
}
__device__ __forceinline__ float sigf(float x) { return 1.f / (1.f + expf(-x)); }
__device__ __forceinline__ void split_h(float x, __half& hi, __half& lo) {
    hi = __float2half_rn(x);
    lo = __float2half_rn(x - __half2float(hi));
}

// fp16 smem tile: 64B rows; 16B chunk c of row r at r*64 + ((c*16) ^ (((r>>1)&3)<<4))
// fp32 smem tile: 128B rows; 16B chunk c of row r at r*128 + ((c ^ (r&7))*16)

// ---------------- GEMM1: fused fp32->fp16 round + 1-term fp16 HMMA ----------
// C_partial[z] = fp16(v) @ W_down_fp16^T over k chunk z.
// Structure identical to the R7 (proven) version; Al term removed.
__global__ void __launch_bounds__(256, 2)
gemm1_fused(const float* __restrict__ Afp, int lda,
            const __half* __restrict__ Bm, int ldb,
            float* __restrict__ C, int ldc, size_t zstride)
{
    constexpr int BM = 128, BN = 128, WM = 64, WN = 32, MF = 4, NF = 4;
    constexpr int A32S  = 128 * 128;               // fp32 stage bytes
    constexpr int B16S  = 128 * 64;                // fp16 B stage bytes
    constexpr int OFF_B  = 3 * A32S;               // 49152
    constexpr int OFF_AH = OFF_B + 3 * B16S;       // 73728 (total 81920)

    extern __shared__ char smem[];
    const uint32_t sbase = smem_u32(smem);
    const int tid  = threadIdx.x;
    const int lane = tid & 31;
    const int warp = tid >> 5;
    const int wm0 = (warp / (BN / WN)) * WM;
    const int wn0 = (warp % (BN / WN)) * WN;
    const int m0 = blockIdx.y * BM;
    const int n0 = blockIdx.x * BN;
    const int kbase = blockIdx.z * 5024;
    const int Kz = (blockIdx.z == 3) ? 4928 : 5024;
    C += (size_t)blockIdx.z * zstride;

    float acc[MF][NF][4];
    #pragma unroll
    for (int i = 0; i < MF; i++)
        #pragma unroll
        for (int j = 0; j < NF; j++)
            #pragma unroll
            for (int q = 0; q < 4; q++) acc[i][j][q] = 0.f;

    auto load_stage = [&](int kt, int s) {
        const int k0 = kbase + kt * 32;
        #pragma unroll
        for (int q = 0; q < 6; q++) {
            const int i = tid + q * 256;
            if (i < 1024) {                       // A fp32: 128 rows x 8 chunks
                int row = i >> 3, c = i & 7;
                uint32_t dst = sbase + s * A32S + row * 128 + ((c ^ (row & 7)) << 4);
                cp_async16(dst, Afp + (size_t)(m0 + row) * lda + k0 + c * 4);
            } else {                              // B fp16: 128 rows x 4 chunks
                int j = i - 1024; int row = j >> 2, c = j & 3;
                uint32_t dst = sbase + OFF_B + s * B16S + row * 64 +
                               ((c * 16) ^ (((row >> 1) & 3) << 4));
                cp_async16(dst, Bm + (size_t)(n0 + row) * ldb + k0 + c * 8);
            }
        }
    };

    const int KT = Kz >> 5;
    load_stage(0, 0); cp_commit();
    load_stage(1, 1); cp_commit();

    const int li  = lane & 15;
    const int khb = (lane >> 4) << 4;
    const int swz = ((li >> 1) & 3) << 4;
    const int cr = tid & 127;          // convert: row
    const int cj = tid >> 7;           // convert: k-half (0 or 1)

    for (int kt = 0; kt < KT; kt++) {
        const int s = kt % 3;
        if (kt + 2 < KT) load_stage(kt + 2, (kt + 2) % 3);
        cp_commit();
        cp_wait2();
        __syncthreads();

        // ---- convert A32[s] -> Ah (hi only) ----
        {
            const char* a32 = smem + s * A32S + cr * 128;
            #pragma unroll
            for (int q2 = 0; q2 < 2; q2++) {
                const int c32a = 4 * cj + 2 * q2;
                float4 f0 = *reinterpret_cast<const float4*>(a32 + (((c32a)     ^ (cr & 7)) << 4));
                float4 f1 = *reinterpret_cast<const float4*>(a32 + (((c32a + 1) ^ (cr & 7)) << 4));
                __half2 t0, t1, t2, t3;
                t0.x = __float2half_rn(f0.x); t0.y = __float2half_rn(f0.y);
                t1.x = __float2half_rn(f0.z); t1.y = __float2half_rn(f0.w);
                t2.x = __float2half_rn(f1.x); t2.y = __float2half_rn(f1.y);
                t3.x = __float2half_rn(f1.z); t3.y = __float2half_rn(f1.w);
                uint4 ph;
                ph.x = *reinterpret_cast<uint32_t*>(&t0);
                ph.y = *reinterpret_cast<uint32_t*>(&t1);
                ph.z = *reinterpret_cast<uint32_t*>(&t2);
                ph.w = *reinterpret_cast<uint32_t*>(&t3);
                const int cH = 2 * cj + q2;
                const uint32_t so = cr * 64 + ((cH * 16) ^ (((cr >> 1) & 3) << 4));
                *reinterpret_cast<uint4*>(smem + OFF_AH + so) = ph;
            }
        }
        __syncthreads();

        // ---- HMMA (1-term): Ah + B16[s] ----
        const uint32_t tAh = sbase + OFF_AH;
        const uint32_t tB  = sbase + OFF_B + s * B16S;
        #pragma unroll
        for (int kk = 0; kk < 2; kk++) {
            const int cb = kk * 32;
            const uint32_t coff = (uint32_t)((cb + khb) ^ swz);
            uint32_t ah[MF][4];
            #pragma unroll
            for (int mf = 0; mf < MF; mf++) {
                uint32_t ro = (wm0 + mf * 16 + li) * 64 + coff;
                ldsm4(ah[mf], tAh + ro);
            }
            uint32_t bh[NF][2];
            #pragma unroll
            for (int nf2 = 0; nf2 < NF / 2; nf2++) {
                uint32_t ro = (wn0 + nf2 * 16 + li) * 64 + coff;
                uint32_t t[4];
                ldsm4(t, tB + ro);
                bh[2 * nf2][0] = t[0]; bh[2 * nf2][1] = t[2];
                bh[2 * nf2 + 1][0] = t[1]; bh[2 * nf2 + 1][1] = t[3];
            }
            #pragma unroll
            for (int mf = 0; mf < MF; mf++)
                #pragma unroll
                for (int nf = 0; nf < NF; nf++)
                    mma16816(acc[mf][nf], ah[mf], bh[nf]);
        }
        __syncthreads();
    }

    // ---- epilogue: fp32 partials, coalesced ----
    float* st = reinterpret_cast<float*>(smem) + warp * (WM * 33);
    #pragma unroll
    for (int mf = 0; mf < MF; mf++)
        #pragma unroll
        for (int nf = 0; nf < NF; nf++)
            #pragma unroll
            for (int i = 0; i < 2; i++) {
                int r = mf * 16 + (lane >> 2) + 8 * i;
                int c = nf * 8 + 2 * (lane & 3);
                st[r * 33 + c]     = acc[mf][nf][2 * i];
                st[r * 33 + c + 1] = acc[mf][nf][2 * i + 1];
            }
    __syncwarp();
    #pragma unroll
    for (int rr = lane; rr < WM; rr += 32) {
        const int m = m0 + wm0 + rr;
        #pragma unroll
        for (int c4 = 0; c4 < WN; c4 += 4) {
            float4 v;
            v.x = st[rr * 33 + c4];     v.y = st[rr * 33 + c4 + 1];
            v.z = st[rr * 33 + c4 + 2]; v.w = st[rr * 33 + c4 + 3];
            *reinterpret_cast<float4*>(C + (size_t)m * ldc + n0 + wn0 + c4) = v;
        }
    }
}

// ---------------- generic 2-term fp16 GEMM (modes 1,2) — R7 proven ----------
template<int BM, int BN, int WM, int WN, int MODE>
__global__ void __launch_bounds__((BM / WM) * (BN / WN) * 32)
mma_gemm(const __half* __restrict__ Ah, const __half* __restrict__ Al, int lda,
         const __half* __restrict__ Bm, int ldb, int K,
         float* __restrict__ C, int ldc,
         const float* __restrict__ bias,
         const float* __restrict__ srow, const float* __restrict__ ucol,
         __half* __restrict__ Ch, __half* __restrict__ Cl)
{
    constexpr int NT = (BM / WM) * (BN / WN) * 32;
    constexpr int MF = WM / 16;
    constexpr int NF = WN / 8;
    constexpr int STAGE = (2 * BM + BN) * 64;
    constexpr int CHA = BM * 4;
    constexpr int CHB = BN * 4;
    constexpr int CHT = 2 * CHA + CHB;

    extern __shared__ char smem[];
    const uint32_t sbase = smem_u32(smem);
    const int tid  = threadIdx.x;
    const int lane = tid & 31;
    const int warp = tid >> 5;
    const int wm0 = (warp / (BN / WN)) * WM;
    const int wn0 = (warp % (BN / WN)) * WN;
    const int m0 = blockIdx.y * BM;
    const int n0 = blockIdx.x * BN;

    float acc[MF][NF][4];
    #pragma unroll
    for (int i = 0; i < MF; i++)
        #pragma unroll
        for (int j = 0; j < NF; j++)
            #pragma unroll
            for (int q = 0; q < 4; q++) acc[i][j][q] = 0.f;

    auto load_stage = [&](int kt, int s) {
        const int k0 = kt * 32;
        const uint32_t tb = sbase + s * STAGE;
        #pragma unroll
        for (int q = 0; q < CHT / NT; q++) {
            const int i = tid + q * NT;
            const __half* src;
            int toff, rr;
            if (i < CHA) {
                rr = i >> 2; src = Ah + (size_t)(m0 + rr) * lda; toff = 0;
            } else if (i < 2 * CHA) {
                int j = i - CHA; rr = j >> 2;
                src = Al + (size_t)(m0 + rr) * lda; toff = BM * 64;
            } else {
                int j = i - 2 * CHA; rr = j >> 2;
                src = Bm + (size_t)(n0 + rr) * ldb; toff = 2 * BM * 64;
            }
            const int c = i & 3;
            uint32_t dst = tb + toff + rr * 64 + ((c * 16) ^ (((rr >> 1) & 3) << 4));
            cp_async16(dst, src + k0 + c * 8);
        }
    };

    const int KT = K >> 5;
    load_stage(0, 0); cp_commit();
    load_stage(1, 1); cp_commit();

    const int li  = lane & 15;
    const int khb = (lane >> 4) << 4;
    const int swz = ((li >> 1) & 3) << 4;

    for (int kt = 0; kt < KT; kt++) {
        const int s = kt % 3;
        if (kt + 2 < KT) load_stage(kt + 2, (kt + 2) % 3);
        cp_commit();
        cp_wait2();
        __syncthreads();

        const uint32_t tA  = sbase + s * STAGE;
        const uint32_t tAl = tA + BM * 64;
        const uint32_t tB  = tA + 2 * BM * 64;

        #pragma unroll
        for (int kk = 0; kk < 2; kk++) {
            const int cb = kk * 32;
            const uint32_t coff = (uint32_t)((cb + khb) ^ swz);
            uint32_t ah[MF][4], al_[MF][4];
            #pragma unroll
            for (int mf = 0; mf < MF; mf++) {
                uint32_t ro = (wm0 + mf * 16 + li) * 64 + coff;
                ldsm4(ah[mf],  tA  + ro);
                ldsm4(al_[mf], tAl + ro);
            }
            uint32_t bh[NF][2];
            #pragma unroll
            for (int nf2 = 0; nf2 < NF / 2; nf2++) {
                uint32_t ro = (wn0 + nf2 * 16 + li) * 64 + coff;
                uint32_t t[4];
                ldsm4(t, tB + ro);
                bh[2 * nf2][0] = t[0]; bh[2 * nf2][1] = t[2];
                bh[2 * nf2 + 1][0] = t[1]; bh[2 * nf2 + 1][1] = t[3];
            }
            #pragma unroll
            for (int mf = 0; mf < MF; mf++)
                #pragma unroll
                for (int nf = 0; nf < NF; nf++) {
                    mma16816(acc[mf][nf], ah[mf],  bh[nf]);
                    mma16816(acc[mf][nf], al_[mf], bh[nf]);
                }
        }
        __syncthreads();
    }

    float* st = reinterpret_cast<float*>(smem) + warp * (WM * 33);
    #pragma unroll
    for (int mf = 0; mf < MF; mf++)
        #pragma unroll
        for (int nf = 0; nf < NF; nf++)
            #pragma unroll
            for (int i = 0; i < 2; i++) {
                int r = mf * 16 + (lane >> 2) + 8 * i;
                int c = nf * 8 + 2 * (lane & 3);
                st[r * 33 + c]     = acc[mf][nf][2 * i];
                st[r * 33 + c + 1] = acc[mf][nf][2 * i + 1];
            }
    __syncwarp();
    #pragma unroll
    for (int rr = lane; rr < WM; rr += 32) {
        const int m = m0 + wm0 + rr;
        const int nbase = n0 + wn0;
        if (MODE == 1) {
            const float tm = srow[m];
            #pragma unroll
            for (int c = 0; c < WN; c += 2) {
                int n = nbase + c;
                float v0 = st[rr * 33 + c]     + tm * ucol[n]     + bias[n];
                float v1 = st[rr * 33 + c + 1] + tm * ucol[n + 1] + bias[n + 1];
                __half h0, l0, h1, l1;
                split_h(v0, h0, l0); split_h(v1, h1, l1);
                __half2 ph; ph.x = h0; ph.y = h1;
                __half2 pl; pl.x = l0; pl.y = l1;
                *reinterpret_cast<__half2*>(Ch + (size_t)m * ldc + n) = ph;
                *reinterpret_cast<__half2*>(Cl + (size_t)m * ldc + n) = pl;
            }
        } else {
            #pragma unroll
            for (int c4 = 0; c4 < WN; c4 += 4) {
                float4 v;
                v.x = st[rr * 33 + c4];
                v.y = st[rr * 33 + c4 + 1];
                v.z = st[rr * 33 + c4 + 2];
                v.w = st[rr * 33 + c4 + 3];
                int n = nbase + c4;
                v.x += bias[n]; v.y += bias[n + 1];
                v.z += bias[n + 2]; v.w += bias[n + 3];
                *reinterpret_cast<float4*>(C + (size_t)m * ldc + nbase + c4) = v;
            }
        }
    }
}

// ---------------- persistent fused LSTM (steps 0..15) — R7 proven ------------
__global__ void __launch_bounds__(128)
lstm_persist(const __half* __restrict__ hhb, const __half* __restrict__ hlb,
             const __half* __restrict__ Bm,
             const float* __restrict__ xg, float* __restrict__ cstate,
             float* __restrict__ houtf,
             __half* __restrict__ hhw, __half* __restrict__ hlw)
{
    constexpr int BM = 32, BN = 64, NT = 128, NF = 4;
    constexpr int STAGE = (2 * BM + BN) * 64;    // 8192
    constexpr int CHA = BM * 4, CHB = BN * 4, CHT = 2 * CHA + CHB;

    extern __shared__ char smem[];
    const uint32_t sbase = smem_u32(smem);
    const int tid  = threadIdx.x;
    const int lane = tid & 31;
    const int warp = tid >> 5;
    const int wm0 = (warp >> 1) * 16;
    const int wn0 = (warp & 1) * 32;
    const int m0 = blockIdx.y * BM;
    const int n0 = blockIdx.x * BN;
    const int li  = lane & 15;
    const int khb = (lane >> 4) << 4;
    const int swz = ((li >> 1) & 3) << 4;

    // ---- step 0: h=c=0, gates = xg row ----
    {
        __half* Oh = hhw;
        __half* Ol = hlw;
        const float* xgl = xg;
        #pragma unroll
        for (int qsel = 0; qsel < NF / 2; qsel++) {
            const int nb = n0 + wn0 + qsel * 16;
            const int a  = lane & 3;
            const int j  = 4 * (nb >> 4) + a;
            #pragma unroll
            for (int i = 0; i < 2; i++) {
                const int m = m0 + wm0 + (lane >> 2) + 8 * i;
                const float* xrow = xgl + (size_t)m * (L_SZ * G4);
                float2 xif = *reinterpret_cast<const float2*>(xrow + nb + 2 * a);
                float2 xgo = *reinterpret_cast<const float2*>(xrow + nb + 8 + 2 * a);
                float ig = sigf(xif.x);
                float gg = tanhf(xgo.x), og = sigf(xgo.y);
                const int gi = (m << 10) + j;
                float cv = ig * gg;
                cstate[gi] = cv;
                float hv = og * tanhf(cv);
                __half hi, lo; split_h(hv, hi, lo);
                Oh[gi] = hi; Ol[gi] = lo;
            }
        }
        __threadfence();
        __syncthreads();
        if (tid == 0) {
            atomicAdd(&g_bar, 1u);
            volatile unsigned* vb = &g_bar;
            while (*vb < 256u) { }
        }
        __syncthreads();
    }

    for (int l = 1; l < L_SZ; l++) {
        const __half* Ah = hhb + (size_t)((l + 1) & 1) * (B_SZ * H_SZ);
        const __half* Al = hlb + (size_t)((l + 1) & 1) * (B_SZ * H_SZ);
        __half* Oh = hhw + (size_t)(l & 1) * (B_SZ * H_SZ);
        __half* Ol = hlw + (size_t)(l & 1) * (B_SZ * H_SZ);
        const float* xgl = xg + (size_t)l * G4;

        float acc[NF][4];
        #pragma unroll
        for (int j = 0; j < NF; j++)
            #pragma unroll
            for (int q = 0; q < 4; q++) acc[j][q] = 0.f;

        auto load_stage = [&](int kt, int s) {
            const int k0 = kt * 32;
            const uint32_t tb = sbase + s * STAGE;
            #pragma unroll
            for (int q = 0; q < CHT / NT; q++) {
                const int i = tid + q * NT;
                const __half* src;
                int toff, rr;
                if (i < CHA) {
                    rr = i >> 2; src = Ah + (size_t)(m0 + rr) * H_SZ; toff = 0;
                } else if (i < 2 * CHA) {
                    int j = i - CHA; rr = j >> 2;
                    src = Al + (size_t)(m0 + rr) * H_SZ; toff = BM * 64;
                } else {
                    int j = i - 2 * CHA; rr = j >> 2;
                    src = Bm + (size_t)(n0 + rr) * H_SZ; toff = 2 * BM * 64;
                }
                const int c = i & 3;
                uint32_t dst = tb + toff + rr * 64 + ((c * 16) ^ (((rr >> 1) & 3) << 4));
                cp_async16(dst, src + k0 + c * 8);
            }
        };

        const int KT = H_SZ >> 5;   // 32
        load_stage(0, 0); cp_commit();
        load_stage(1, 1); cp_commit();

        for (int kt = 0; kt < KT; kt++) {
            const int s = kt % 3;
            if (kt + 2 < KT) load_stage(kt + 2, (kt + 2) % 3);
            cp_commit();
            cp_wait2();
            __syncthreads();

            const uint32_t tA  = sbase + s * STAGE;
            const uint32_t tAl = tA + BM * 64;
            const uint32_t tB  = tA + 2 * BM * 64;

            #pragma unroll
            for (int kk = 0; kk < 2; kk++) {
                const int cb = kk * 32;
                const uint32_t coff = (uint32_t)((cb + khb) ^ swz);
                uint32_t ah[4], al_[4];
                {
                    uint32_t ro = (wm0 + li) * 64 + coff;
                    ldsm4(ah,  tA  + ro);
                    ldsm4(al_, tAl + ro);
                }
                uint32_t bh[NF][2];
                #pragma unroll
                for (int nf2 = 0; nf2 < NF / 2; nf2++) {
                    uint32_t ro = (wn0 + nf2 * 16 + li) * 64 + coff;
                    uint32_t t[4];
                    ldsm4(t, tB + ro);
                    bh[2 * nf2][0] = t[0]; bh[2 * nf2][1] = t[2];
                    bh[2 * nf2 + 1][0] = t[1]; bh[2 * nf2 + 1][1] = t[3];
                }
                #pragma unroll
                for (int nf = 0; nf < NF; nf++) {
                    mma16816(acc[nf], ah,  bh[nf]);
                    mma16816(acc[nf], al_, bh[nf]);
                }
            }
            __syncthreads();
        }

        // fused gate nonlinearity + state update
        #pragma unroll
        for (int qsel = 0; qsel < NF / 2; qsel++) {
            const int nb = n0 + wn0 + qsel * 16;
            const int a  = lane & 3;
            const int j  = 4 * (nb >> 4) + a;
            #pragma unroll
            for (int i = 0; i < 2; i++) {
                const int m = m0 + wm0 + (lane >> 2) + 8 * i;
                const float* xrow = xgl + (size_t)m * (L_SZ * G4);
                float2 xif = *reinterpret_cast<const float2*>(xrow + nb + 2 * a);
                float2 xgo = *reinterpret_cast<const float2*>(xrow + nb + 8 + 2 * a);
                float xi = acc[2 * qsel][2 * i]         + xif.x;
                float xf = acc[2 * qsel][2 * i + 1]     + xif.y;
                float xgv = acc[2 * qsel + 1][2 * i]    + xgo.x;
                float xo = acc[2 * qsel + 1][2 * i + 1] + xgo.y;
                float ig = sigf(xi), fg = sigf(xf);
                float gg = tanhf(xgv), og = sigf(xo);
                const int gi = (m << 10) + j;
                float cv = fg * cstate[gi] + ig * gg;
                cstate[gi] = cv;
                float hv = og * tanhf(cv);
                houtf[gi] = hv;
                __half hi, lo; split_h(hv, hi, lo);
                Oh[gi] = hi; Ol[gi] = lo;
            }
        }

        __threadfence();
        __syncthreads();
        if (tid == 0) {
            atomicAdd(&g_bar, 1u);
            volatile unsigned* vb = &g_bar;
            const unsigned target = 256u * (unsigned)(l + 1);
            while (*vb < target) { }
        }
        __syncthreads();
    }
}

// ---------------- converts ---------------------------------------------------
__global__ void conv_round(const float* __restrict__ src, int C, int srcld,
                           __half* __restrict__ dst)
{
    int c4 = (blockIdx.x * blockDim.x + threadIdx.x) * 4;
    int r = blockIdx.y;
    if (c4 >= C) return;
    float4 x = *reinterpret_cast<const float4*>(src + (size_t)r * srcld + c4);
    size_t o = (size_t)r * C + c4;
    __half2 a; a.x = __float2half_rn(x.x); a.y = __float2half_rn(x.y);
    __half2 b; b.x = __float2half_rn(x.z); b.y = __float2half_rn(x.w);
    *reinterpret_cast<__half2*>(dst + o)     = a;
    *reinterpret_cast<__half2*>(dst + o + 2) = b;
}

__global__ void conv_perm_round(const float* __restrict__ src, int cols,
                                __half* __restrict__ dst)
{
    int c4 = (blockIdx.x * blockDim.x + threadIdx.x) * 4;
    int r = blockIdx.y;
    if (c4 >= cols) return;
    int gate = ((r >> 3) & 1) * 2 + (r & 1);
    int cell = 4 * (r >> 4) + ((r >> 1) & 3);
    int orig = gate * 1024 + cell;
    float4 x = *reinterpret_cast<const float4*>(src + (size_t)orig * cols + c4);
    size_t o = (size_t)r * cols + c4;
    __half2 a; a.x = __float2half_rn(x.x); a.y = __float2half_rn(x.y);
    __half2 b; b.x = __float2half_rn(x.z); b.y = __float2half_rn(x.w);
    *reinterpret_cast<__half2*>(dst + o)     = a;
    *reinterpret_cast<__half2*>(dst + o + 2) = b;
}

__global__ void prep_kernel(const float* __restrict__ Wvt,
                            const float* __restrict__ wtw,
                            const float* __restrict__ wtb,
                            const float* __restrict__ bih,
                            const float* __restrict__ bhh)
{
    int i = blockIdx.x * blockDim.x + threadIdx.x;
    if (i == 0) g_bar = 0;
    if (i < HIN) {
        const float* row = Wvt + (size_t)i * (HIN + 128) + HIN;
        float u = 0.f, ub = 0.f;
        #pragma unroll 4
        for (int j = 0; j < 128; j++) { float w = row[j]; u += w * wtw[j]; ub += w * wtb[j]; }
        g_u[i] = u; g_ub[i] = ub;
    } else if (i < HIN + G4) {
        int r = i - HIN;
        int gate = ((r >> 3) & 1) * 2 + (r & 1);
        int cell = 4 * (r >> 4) + ((r >> 1) & 3);
        g_biasp[r] = bih[gate * 1024 + cell] + bhh[gate * 1024 + cell];
    } else if (i < HIN + G4 + HIN * HIN / 4) {
        int w = i - (HIN + G4);
        int r = w >> 7;
        int c4 = (w & 127) * 4;
        float4 x = *reinterpret_cast<const float4*>(Wvt + (size_t)r * (HIN + 128) + c4);
        size_t o = (size_t)r * HIN + c4;
        __half2 a; a.x = __float2half_rn(x.x); a.y = __float2half_rn(x.y);
        __half2 b; b.x = __float2half_rn(x.z); b.y = __float2half_rn(x.w);
        *reinterpret_cast<__half2*>(g_wvt + o)     = a;
        *reinterpret_cast<__half2*>(g_wvt + o + 2) = b;
    }
}

__global__ void reduce_conv(void)
{
    int idx = blockIdx.x * 256 + threadIdx.x;
    float s = 0.f;
    #pragma unroll
    for (int z = 0; z < KSPLIT; z++) s += g_split[(size_t)z * ML * HIN + idx];
    __half hi, lo; split_h(s, hi, lo);
    g_vdh[idx] = hi; g_vdl[idx] = lo;
}

__global__ void pred_kernel(const float* __restrict__ lw,
                            const float* __restrict__ lb,
                            float* __restrict__ out)
{
    int b = blockIdx.x, tid = threadIdx.x;
    const float* hr = g_h + (size_t)b * H_SZ;
    float s = 0.f;
    for (int k = tid; k < H_SZ; k += 128) s += hr[k] * lw[k];
    __shared__ float red[128];
    red[tid] = s; __syncthreads();
    for (int off = 64; off > 0; off >>= 1) {
        if (tid < off) red[tid] += red[tid + off];
        __syncthreads();
    }
    if (tid == 0) out[b] = red[0] + lb[0];
}

// ---------------- launch -----------------------------------------------------
#define SMEM_G1   81920                          // 3*16K A32 + 3*8K B + 8K Ah
#define SMEM_BIG  ((2 * 128 + 128) * 64 * 3)     // 73728
#define SMEM_LSTM ((2 * 32 + 64) * 64 * 3)       // 24576

extern "C" void kernel_launch(void* const* d_in, const int* in_sizes, int n_in,
                              void* d_out, int out_size)
{
    const float* v   = (const float*)d_in[0];
    const float* t   = (const float*)d_in[1];
    const float* Wd  = (const float*)d_in[2];
    const float* wtw = (const float*)d_in[3];
    const float* wtb = (const float*)d_in[4];
    const float* Wvt = (const float*)d_in[5];
    const float* Wih = (const float*)d_in[6];
    const float* Whh = (const float*)d_in[7];
    const float* bih = (const float*)d_in[8];
    const float* bhh = (const float*)d_in[9];
    const float* lw  = (const float*)d_in[10];
    const float* lb  = (const float*)d_in[11];
    float* out = (float*)d_out;

    __half *p_wd, *p_vdh, *p_vdl, *p_wvt, *p_ih, *p_il, *p_wih, *p_whh, *p_hh, *p_hl;
    float *p_split, *p_xg, *p_h, *p_c, *p_u, *p_ub, *p_biasp;
    cudaGetSymbolAddress((void**)&p_wd, g_wd);
    cudaGetSymbolAddress((void**)&p_vdh, g_vdh); cudaGetSymbolAddress((void**)&p_vdl, g_vdl);
    cudaGetSymbolAddress((void**)&p_wvt, g_wvt);
    cudaGetSymbolAddress((void**)&p_ih, g_ih);   cudaGetSymbolAddress((void**)&p_il, g_il);
    cudaGetSymbolAddress((void**)&p_wih, g_wih); cudaGetSymbolAddress((void**)&p_whh, g_whh);
    cudaGetSymbolAddress((void**)&p_hh, g_hh);   cudaGetSymbolAddress((void**)&p_hl, g_hl);
    cudaGetSymbolAddress((void**)&p_split, g_split);
    cudaGetSymbolAddress((void**)&p_xg, g_xg);
    cudaGetSymbolAddress((void**)&p_h, g_h);     cudaGetSymbolAddress((void**)&p_c, g_c);
    cudaGetSymbolAddress((void**)&p_u, g_u);     cudaGetSymbolAddress((void**)&p_ub, g_ub);
    cudaGetSymbolAddress((void**)&p_biasp, g_biasp);

    cudaFuncSetAttribute(gemm1_fused, cudaFuncAttributeMaxDynamicSharedMemorySize, SMEM_G1);
    cudaFuncSetAttribute(mma_gemm<128, 128, 64, 32, 1>, cudaFuncAttributeMaxDynamicSharedMemorySize, SMEM_BIG);
    cudaFuncSetAttribute(mma_gemm<128, 128, 64, 32, 2>, cudaFuncAttributeMaxDynamicSharedMemorySize, SMEM_BIG);
    cudaFuncSetAttribute(lstm_persist, cudaFuncAttributeMaxDynamicSharedMemorySize, SMEM_LSTM);

    // 1) prep  2) W_down round  3) W_ih perm-round
    prep_kernel<<<(HIN + G4 + HIN * HIN / 4) / 256, 256>>>(Wvt, wtw, wtb, bih, bhh);
    conv_round<<<dim3((N_SZ / 4 + 255) / 256, HIN), 256>>>(Wd, N_SZ, N_SZ, p_wd);
    conv_perm_round<<<dim3(1, G4), 256>>>(Wih, HIN, p_wih);

    // 4) GEMM1 (fused fp32->fp16 round, 1-term, split-K=4)
    gemm1_fused<<<dim3(HIN / 128, ML / 128, KSPLIT), 256, SMEM_G1>>>(
        v, N_SZ, p_wd, N_SZ, p_split, HIN, (size_t)ML * HIN);

    // 5) reduce partials -> vd fp16 split
    reduce_conv<<<(ML * HIN) / 256, 256>>>();

    // 6) GEMM2: inputs = vd @ Wvt_s^T + t[m]*u[n] + ub[n] -> fp16 split
    mma_gemm<128, 128, 64, 32, 1><<<dim3(HIN / 128, ML / 128), 256, SMEM_BIG>>>(
        p_vdh, p_vdl, HIN, p_wvt, HIN, HIN,
        nullptr, HIN, p_ub, t, p_u, p_ih, p_il);

    // 7) GEMM3: xg = inputs @ Wih_perm^T + bias_perm
    mma_gemm<128, 128, 64, 32, 2><<<dim3(G4 / 128, ML / 128), 256, SMEM_BIG>>>(
        p_ih, p_il, HIN, p_wih, HIN, HIN,
        p_xg, G4, p_biasp, nullptr, nullptr, nullptr, nullptr);

    // 8) W_hh perm-round  9) persistent LSTM steps 0..15
    conv_perm_round<<<dim3(2, G4), 256>>>(Whh, H_SZ, p_whh);
    lstm_persist<<<dim3(G4 / 64, B_SZ / 32), 128, SMEM_LSTM>>>(
        p_hh, p_hl, p_whh, p_xg, p_c, p_h, p_hh, p_hl);

    // 10) pred
    pred_kernel<<<B_SZ, 128>>>(lw, lb, out);
}

// round 11
// speedup vs baseline: 6.7939x; 1.0513x over previous
#include <cuda_runtime.h>
#include <cuda_fp16.h>
#include <cstdint>
#include <math.h>

// ---------------- dims ------------------------------------------------------
#define B_SZ 128
#define L_SZ 16
#define N_SZ 20000
#define HIN  512
#define H_SZ 1024
#define G4   4096
#define ML   2048
#define KSPLIT 4
// split-K chunks: 5024,5024,5024,4928 (all %32==0, sum 20000)

// ---------------- device global scratch ------------------------------------
__device__ __half g_wd[(size_t)HIN * N_SZ];       // W_down rounded fp16
__device__ float g_split[KSPLIT * ML * HIN];
__device__ __half g_vdh[ML * HIN];                // vd split
__device__ __half g_vdl[ML * HIN];
__device__ __half g_wvt[HIN * HIN];               // W_vt[:, :512] rounded
__device__ __half g_ih[ML * HIN];                 // inputs (hi, exact round)
__device__ __half g_wih[G4 * HIN];                // W_ih permuted rounded
__device__ __half g_whh[(size_t)G4 * H_SZ];       // W_hh permuted rounded
__device__ float g_xg[(size_t)ML * G4];           // permuted gate cols
__device__ __half g_hh[2 * B_SZ * H_SZ];          // h split, double buffered
__device__ __half g_hl[2 * B_SZ * H_SZ];
__device__ float g_h[B_SZ * H_SZ];
__device__ float g_c[B_SZ * H_SZ];
__device__ float g_u[HIN];
__device__ float g_ub[HIN];
__device__ float g_biasp[G4];
__device__ unsigned g_bar;

// ---------------- helpers ---------------------------------------------------
__device__ __forceinline__ uint32_t smem_u32(const void* p) {
    uint32_t a;
    asm("{ .reg .u64 t; cvta.to.shared.u64 t, %1; cvt.u32.u64 %0, t; }" : "=r"(a) : "l"(p));
    return a;
}
__device__ __forceinline__ void cp_async16(uint32_t dst, const void* src) {
    asm volatile("cp.async.cg.shared.global [%0], [%1], 16;" :: "r"(dst), "l"(src));
}
__device__ __forceinline__ void cp_commit() {
    asm volatile("cp.async.commit_group;" ::: "memory");
}
__device__ __forceinline__ void cp_wait1() {
    asm volatile("cp.async.wait_group 1;" ::: "memory");
}
__device__ __forceinline__ void cp_wait2() {
    asm volatile("cp.async.wait_group 2;" ::: "memory");
}
__device__ __forceinline__ void ldsm4(uint32_t* r, uint32_t addr) {
    asm volatile("ldmatrix.sync.aligned.m8n8.x4.shared.b16 {%0,%1,%2,%3}, [%4];"
        : "=r"(r[0]), "=r"(r[1]), "=r"(r[2]), "=r"(r[3]) : "r"(addr));
}
__device__ __forceinline__ void mma16816(float* c, const uint32_t* a, const uint32_t* b) {
    asm volatile("mma.sync.aligned.m16n8k16.row.col.f32.f16.f16.f32 "
        "{%0,%1,%2,%3}, {%4,%5,%6,%7}, {%8,%9}, {%0,%1,%2,%3};"
        : "+f"(c[0]), "+f"(c[1]), "+f"(c[2]), "+f"(c[3])
        : "r"(a[0]), "r"(a[1]), "r"(a[2]), "r"(a[3]), "r"(b[0]), "r"(b[1]));
}
__device__ __forceinline__ float sigf(float x) { return 1.f / (1.f + expf(-x)); }
__device__ __forceinline__ void split_h(float x, __half& hi, __half& lo) {
    hi = __float2half_rn(x);
    lo = __float2half_rn(x - __half2float(hi));
}

// fp16 smem tile: 64B rows; 16B chunk c of row r at r*64 + ((c*16) ^ (((r>>1)&3)<<4))
// fp32 smem tile: 128B rows; 16B chunk c of row r at r*128 + ((c ^ (r&7))*16)

// ---------------- GEMM1: fused fp32->fp16 round + 1-term HMMA, overlapped ---
// Iteration kt: loads(kt+2); wait1; sync1; [convert(kt+1) || HMMA(kt)]; sync2.
// A32 ring=3, B ring=3, Ah double-buffered.
__global__ void __launch_bounds__(256, 2)
gemm1_fused(const float* __restrict__ Afp, int lda,
            const __half* __restrict__ Bm, int ldb,
            float* __restrict__ C, int ldc, size_t zstride)
{
    constexpr int BM = 128, BN = 128, WM = 64, WN = 32, MF = 4, NF = 4;
    constexpr int A32S  = 128 * 128;               // fp32 stage bytes
    constexpr int B16S  = 128 * 64;                // fp16 B stage bytes
    constexpr int OFF_B  = 3 * A32S;               // 49152
    constexpr int OFF_AH = OFF_B + 3 * B16S;       // 73728; Ah[2] -> total 90112

    extern __shared__ char smem[];
    const uint32_t sbase = smem_u32(smem);
    const int tid  = threadIdx.x;
    const int lane = tid & 31;
    const int warp = tid >> 5;
    const int wm0 = (warp / (BN / WN)) * WM;
    const int wn0 = (warp % (BN / WN)) * WN;
    const int m0 = blockIdx.y * BM;
    const int n0 = blockIdx.x * BN;
    const int kbase = blockIdx.z * 5024;
    const int Kz = (blockIdx.z == 3) ? 4928 : 5024;
    C += (size_t)blockIdx.z * zstride;

    float acc[MF][NF][4];
    #pragma unroll
    for (int i = 0; i < MF; i++)
        #pragma unroll
        for (int j = 0; j < NF; j++)
            #pragma unroll
            for (int q = 0; q < 4; q++) acc[i][j][q] = 0.f;

    auto load_stage = [&](int kt) {
        const int k0 = kbase + kt * 32;
        const int s = kt % 3;
        #pragma unroll
        for (int q = 0; q < 6; q++) {
            const int i = tid + q * 256;
            if (i < 1024) {                       // A fp32: 128 rows x 8 chunks
                int row = i >> 3, c = i & 7;
                uint32_t dst = sbase + s * A32S + row * 128 + ((c ^ (row & 7)) << 4);
                cp_async16(dst, Afp + (size_t)(m0 + row) * lda + k0 + c * 4);
            } else {                              // B fp16: 128 rows x 4 chunks
                int j = i - 1024; int row = j >> 2, c = j & 3;
                uint32_t dst = sbase + OFF_B + s * B16S + row * 64 +
                               ((c * 16) ^ (((row >> 1) & 3) << 4));
                cp_async16(dst, Bm + (size_t)(n0 + row) * ldb + k0 + c * 8);
            }
        }
    };

    const int cr = tid & 127;          // convert: row
    const int cj = tid >> 7;           // convert: k-half (0 or 1)
    auto convert_stage = [&](int kt) {
        const char* a32 = smem + (kt % 3) * A32S + cr * 128;
        char* ahb = smem + OFF_AH + (kt & 1) * 8192;
        #pragma unroll
        for (int q2 = 0; q2 < 2; q2++) {
            const int c32a = 4 * cj + 2 * q2;
            float4 f0 = *reinterpret_cast<const float4*>(a32 + (((c32a)     ^ (cr & 7)) << 4));
            float4 f1 = *reinterpret_cast<const float4*>(a32 + (((c32a + 1) ^ (cr & 7)) << 4));
            __half2 t0, t1, t2, t3;
            t0.x = __float2half_rn(f0.x); t0.y = __float2half_rn(f0.y);
            t1.x = __float2half_rn(f0.z); t1.y = __float2half_rn(f0.w);
            t2.x = __float2half_rn(f1.x); t2.y = __float2half_rn(f1.y);
            t3.x = __float2half_rn(f1.z); t3.y = __float2half_rn(f1.w);
            uint4 ph;
            ph.x = *reinterpret_cast<uint32_t*>(&t0);
            ph.y = *reinterpret_cast<uint32_t*>(&t1);
            ph.z = *reinterpret_cast<uint32_t*>(&t2);
            ph.w = *reinterpret_cast<uint32_t*>(&t3);
            const int cH = 2 * cj + q2;
            const uint32_t so = cr * 64 + ((cH * 16) ^ (((cr >> 1) & 3) << 4));
            *reinterpret_cast<uint4*>(ahb + so) = ph;
        }
    };

    const int KT = Kz >> 5;
    load_stage(0); cp_commit();
    load_stage(1); cp_commit();
    cp_wait1();                 // group 0 (stage 0) complete
    __syncthreads();            // cross-thread visibility of A32[0]
    convert_stage(0);           // Ah[0]

    const int li  = lane & 15;
    const int khb = (lane >> 4) << 4;
    const int swz = ((li >> 1) & 3) << 4;

    for (int kt = 0; kt < KT; kt++) {
        if (kt + 2 < KT) load_stage(kt + 2);
        cp_commit();            // unconditional: group counting stays uniform
        cp_wait1();             // all but newest group done -> stages kt, kt+1 resident
        __syncthreads();        // sync1: visibility + all warps past HMMA(kt-1)

        if (kt + 1 < KT) convert_stage(kt + 1);   // writes Ah[(kt+1)&1]

        // HMMA(kt): Ah[kt&1] + B[kt%3]  (independent of convert above)
        {
            const uint32_t tAh = sbase + OFF_AH + (kt & 1) * 8192;
            const uint32_t tB  = sbase + OFF_B + (kt % 3) * B16S;
            #pragma unroll
            for (int kk = 0; kk < 2; kk++) {
                const int cb = kk * 32;
                const uint32_t coff = (uint32_t)((cb + khb) ^ swz);
                uint32_t ah[MF][4];
                #pragma unroll
                for (int mf = 0; mf < MF; mf++) {
                    uint32_t ro = (wm0 + mf * 16 + li) * 64 + coff;
                    ldsm4(ah[mf], tAh + ro);
                }
                uint32_t bh[NF][2];
                #pragma unroll
                for (int nf2 = 0; nf2 < NF / 2; nf2++) {
                    uint32_t ro = (wn0 + nf2 * 16 + li) * 64 + coff;
                    uint32_t t[4];
                    ldsm4(t, tB + ro);
                    bh[2 * nf2][0] = t[0]; bh[2 * nf2][1] = t[2];
                    bh[2 * nf2 + 1][0] = t[1]; bh[2 * nf2 + 1][1] = t[3];
                }
                #pragma unroll
                for (int mf = 0; mf < MF; mf++)
                    #pragma unroll
                    for (int nf = 0; nf < NF; nf++)
                        mma16816(acc[mf][nf], ah[mf], bh[nf]);
            }
        }
        __syncthreads();        // sync2: Ah[(kt+1)&1] committed; B[kt%3] reads done
    }

    // ---- epilogue: fp32 partials, coalesced ----
    float* st = reinterpret_cast<float*>(smem) + warp * (WM * 33);
    #pragma unroll
    for (int mf = 0; mf < MF; mf++)
        #pragma unroll
        for (int nf = 0; nf < NF; nf++)
            #pragma unroll
            for (int i = 0; i < 2; i++) {
                int r = mf * 16 + (lane >> 2) + 8 * i;
                int c = nf * 8 + 2 * (lane & 3);
                st[r * 33 + c]     = acc[mf][nf][2 * i];
                st[r * 33 + c + 1] = acc[mf][nf][2 * i + 1];
            }
    __syncwarp();
    #pragma unroll
    for (int rr = lane; rr < WM; rr += 32) {
        const int m = m0 + wm0 + rr;
        #pragma unroll
        for (int c4 = 0; c4 < WN; c4 += 4) {
            float4 v;
            v.x = st[rr * 33 + c4];     v.y = st[rr * 33 + c4 + 1];
            v.z = st[rr * 33 + c4 + 2]; v.w = st[rr * 33 + c4 + 3];
            *reinterpret_cast<float4*>(C + (size_t)m * ldc + n0 + wn0 + c4) = v;
        }
    }
}

// ---------------- generic fp16 GEMM (modes 1,2; 1 or 2 A terms) — R7 proven -
// MODE 1: += srow[m]*ucol[n] + bias[n]; fp16 (hi only) out to Ch
// MODE 2: += bias[n]; fp32 out
template<int BM, int BN, int WM, int WN, int MODE, int TERMS>
__global__ void __launch_bounds__((BM / WM) * (BN / WN) * 32)
mma_gemm(const __half* __restrict__ Ah, const __half* __restrict__ Al, int lda,
         const __half* __restrict__ Bm, int ldb, int K,
         float* __restrict__ C, int ldc,
         const float* __restrict__ bias,
         const float* __restrict__ srow, const float* __restrict__ ucol,
         __half* __restrict__ Ch)
{
    constexpr int NT = (BM / WM) * (BN / WN) * 32;
    constexpr int MF = WM / 16;
    constexpr int NF = WN / 8;
    constexpr int STAGE = (TERMS * BM + BN) * 64;
    constexpr int CHA = BM * 4;
    constexpr int CHB = BN * 4;
    constexpr int CHT = TERMS * CHA + CHB;

    extern __shared__ char smem[];
    const uint32_t sbase = smem_u32(smem);
    const int tid  = threadIdx.x;
    const int lane = tid & 31;
    const int warp = tid >> 5;
    const int wm0 = (warp / (BN / WN)) * WM;
    const int wn0 = (warp % (BN / WN)) * WN;
    const int m0 = blockIdx.y * BM;
    const int n0 = blockIdx.x * BN;

    float acc[MF][NF][4];
    #pragma unroll
    for (int i = 0; i < MF; i++)
        #pragma unroll
        for (int j = 0; j < NF; j++)
            #pragma unroll
            for (int q = 0; q < 4; q++) acc[i][j][q] = 0.f;

    auto load_stage = [&](int kt, int s) {
        const int k0 = kt * 32;
        const uint32_t tb = sbase + s * STAGE;
        #pragma unroll
        for (int q = 0; q < CHT / NT; q++) {
            const int i = tid + q * NT;
            const __half* src;
            int toff, rr;
            if (i < CHA) {
                rr = i >> 2; src = Ah + (size_t)(m0 + rr) * lda; toff = 0;
            } else if (TERMS == 2 && i < 2 * CHA) {
                int j = i - CHA; rr = j >> 2;
                src = Al + (size_t)(m0 + rr) * lda; toff = BM * 64;
            } else {
                int j = i - TERMS * CHA; rr = j >> 2;
                src = Bm + (size_t)(n0 + rr) * ldb; toff = TERMS * BM * 64;
            }
            const int c = i & 3;
            uint32_t dst = tb + toff + rr * 64 + ((c * 16) ^ (((rr >> 1) & 3) << 4));
            cp_async16(dst, src + k0 + c * 8);
        }
    };

    const int KT = K >> 5;
    load_stage(0, 0); cp_commit();
    load_stage(1, 1); cp_commit();

    const int li  = lane & 15;
    const int khb = (lane >> 4) << 4;
    const int swz = ((li >> 1) & 3) << 4;

    for (int kt = 0; kt < KT; kt++) {
        const int s = kt % 3;
        if (kt + 2 < KT) load_stage(kt + 2, (kt + 2) % 3);
        cp_commit();
        cp_wait2();
        __syncthreads();

        const uint32_t tA  = sbase + s * STAGE;
        const uint32_t tAl = tA + BM * 64;
        const uint32_t tB  = tA + TERMS * BM * 64;

        #pragma unroll
        for (int kk = 0; kk < 2; kk++) {
            const int cb = kk * 32;
            const uint32_t coff = (uint32_t)((cb + khb) ^ swz);
            uint32_t ah[MF][4], al_[MF][4];
            #pragma unroll
            for (int mf = 0; mf < MF; mf++) {
                uint32_t ro = (wm0 + mf * 16 + li) * 64 + coff;
                ldsm4(ah[mf], tA + ro);
                if (TERMS == 2) ldsm4(al_[mf], tAl + ro);
            }
            uint32_t bh[NF][2];
            #pragma unroll
            for (int nf2 = 0; nf2 < NF / 2; nf2++) {
                uint32_t ro = (wn0 + nf2 * 16 + li) * 64 + coff;
                uint32_t t[4];
                ldsm4(t, tB + ro);
                bh[2 * nf2][0] = t[0]; bh[2 * nf2][1] = t[2];
                bh[2 * nf2 + 1][0] = t[1]; bh[2 * nf2 + 1][1] = t[3];
            }
            #pragma unroll
            for (int mf = 0; mf < MF; mf++)
                #pragma unroll
                for (int nf = 0; nf < NF; nf++) {
                    mma16816(acc[mf][nf], ah[mf], bh[nf]);
                    if (TERMS == 2) mma16816(acc[mf][nf], al_[mf], bh[nf]);
                }
        }
        __syncthreads();
    }

    float* st = reinterpret_cast<float*>(smem) + warp * (WM * 33);
    #pragma unroll
    for (int mf = 0; mf < MF; mf++)
        #pragma unroll
        for (int nf = 0; nf < NF; nf++)
            #pragma unroll
            for (int i = 0; i < 2; i++) {
                int r = mf * 16 + (lane >> 2) + 8 * i;
                int c = nf * 8 + 2 * (lane & 3);
                st[r * 33 + c]     = acc[mf][nf][2 * i];
                st[r * 33 + c + 1] = acc[mf][nf][2 * i + 1];
            }
    __syncwarp();
    #pragma unroll
    for (int rr = lane; rr < WM; rr += 32) {
        const int m = m0 + wm0 + rr;
        const int nbase = n0 + wn0;
        if (MODE == 1) {
            const float tm = srow[m];
            #pragma unroll
            for (int c = 0; c < WN; c += 2) {
                int n = nbase + c;
                float v0 = st[rr * 33 + c]     + tm * ucol[n]     + bias[n];
                float v1 = st[rr * 33 + c + 1] + tm * ucol[n + 1] + bias[n + 1];
                __half2 ph;
                ph.x = __float2half_rn(v0); ph.y = __float2half_rn(v1);
                *reinterpret_cast<__half2*>(Ch + (size_t)m * ldc + n) = ph;
            }
        } else {
            #pragma unroll
            for (int c4 = 0; c4 < WN; c4 += 4) {
                float4 v;
                v.x = st[rr * 33 + c4];
                v.y = st[rr * 33 + c4 + 1];
                v.z = st[rr * 33 + c4 + 2];
                v.w = st[rr * 33 + c4 + 3];
                int n = nbase + c4;
                v.x += bias[n]; v.y += bias[n + 1];
                v.z += bias[n + 2]; v.w += bias[n + 3];
                *reinterpret_cast<float4*>(C + (size_t)m * ldc + nbase + c4) = v;
            }
        }
    }
}

// ---------------- persistent fused LSTM (steps 0..15) — R7 proven ------------
__global__ void __launch_bounds__(128)
lstm_persist(const __half* __restrict__ hhb, const __half* __restrict__ hlb,
             const __half* __restrict__ Bm,
             const float* __restrict__ xg, float* __restrict__ cstate,
             float* __restrict__ houtf,
             __half* __restrict__ hhw, __half* __restrict__ hlw)
{
    constexpr int BM = 32, BN = 64, NT = 128, NF = 4;
    constexpr int STAGE = (2 * BM + BN) * 64;    // 8192
    constexpr int CHA = BM * 4, CHB = BN * 4, CHT = 2 * CHA + CHB;

    extern __shared__ char smem[];
    const uint32_t sbase = smem_u32(smem);
    const int tid  = threadIdx.x;
    const int lane = tid & 31;
    const int warp = tid >> 5;
    const int wm0 = (warp >> 1) * 16;
    const int wn0 = (warp & 1) * 32;
    const int m0 = blockIdx.y * BM;
    const int n0 = blockIdx.x * BN;
    const int li  = lane & 15;
    const int khb = (lane >> 4) << 4;
    const int swz = ((li >> 1) & 3) << 4;

    // ---- step 0: h=c=0, gates = xg row ----
    {
        __half* Oh = hhw;
        __half* Ol = hlw;
        const float* xgl = xg;
        #pragma unroll
        for (int qsel = 0; qsel < NF / 2; qsel++) {
            const int nb = n0 + wn0 + qsel * 16;
            const int a  = lane & 3;
            const int j  = 4 * (nb >> 4) + a;
            #pragma unroll
            for (int i = 0; i < 2; i++) {
                const int m = m0 + wm0 + (lane >> 2) + 8 * i;
                const float* xrow = xgl + (size_t)m * (L_SZ * G4);
                float2 xif = *reinterpret_cast<const float2*>(xrow + nb + 2 * a);
                float2 xgo = *reinterpret_cast<const float2*>(xrow + nb + 8 + 2 * a);
                float ig = sigf(xif.x);
                float gg = tanhf(xgo.x), og = sigf(xgo.y);
                const int gi = (m << 10) + j;
                float cv = ig * gg;
                cstate[gi] = cv;
                float hv = og * tanhf(cv);
                __half hi, lo; split_h(hv, hi, lo);
                Oh[gi] = hi; Ol[gi] = lo;
            }
        }
        __threadfence();
        __syncthreads();
        if (tid == 0) {
            atomicAdd(&g_bar, 1u);
            volatile unsigned* vb = &g_bar;
            while (*vb < 256u) { }
        }
        __syncthreads();
    }

    for (int l = 1; l < L_SZ; l++) {
        const __half* Ah = hhb + (size_t)((l + 1) & 1) * (B_SZ * H_SZ);
        const __half* Al = hlb + (size_t)((l + 1) & 1) * (B_SZ * H_SZ);
        __half* Oh = hhw + (size_t)(l & 1) * (B_SZ * H_SZ);
        __half* Ol = hlw + (size_t)(l & 1) * (B_SZ * H_SZ);
        const float* xgl = xg + (size_t)l * G4;

        float acc[NF][4];
        #pragma unroll
        for (int j = 0; j < NF; j++)
            #pragma unroll
            for (int q = 0; q < 4; q++) acc[j][q] = 0.f;

        auto load_stage = [&](int kt, int s) {
            const int k0 = kt * 32;
            const uint32_t tb = sbase + s * STAGE;
            #pragma unroll
            for (int q = 0; q < CHT / NT; q++) {
                const int i = tid + q * NT;
                const __half* src;
                int toff, rr;
                if (i < CHA) {
                    rr = i >> 2; src = Ah + (size_t)(m0 + rr) * H_SZ; toff = 0;
                } else if (i < 2 * CHA) {
                    int j = i - CHA; rr = j >> 2;
                    src = Al + (size_t)(m0 + rr) * H_SZ; toff = BM * 64;
                } else {
                    int j = i - 2 * CHA; rr = j >> 2;
                    src = Bm + (size_t)(n0 + rr) * H_SZ; toff = 2 * BM * 64;
                }
                const int c = i & 3;
                uint32_t dst = tb + toff + rr * 64 + ((c * 16) ^ (((rr >> 1) & 3) << 4));
                cp_async16(dst, src + k0 + c * 8);
            }
        };

        const int KT = H_SZ >> 5;   // 32
        load_stage(0, 0); cp_commit();
        load_stage(1, 1); cp_commit();

        for (int kt = 0; kt < KT; kt++) {
            const int s = kt % 3;
            if (kt + 2 < KT) load_stage(kt + 2, (kt + 2) % 3);
            cp_commit();
            cp_wait2();
            __syncthreads();

            const uint32_t tA  = sbase + s * STAGE;
            const uint32_t tAl = tA + BM * 64;
            const uint32_t tB  = tA + 2 * BM * 64;

            #pragma unroll
            for (int kk = 0; kk < 2; kk++) {
                const int cb = kk * 32;
                const uint32_t coff = (uint32_t)((cb + khb) ^ swz);
                uint32_t ah[4], al_[4];
                {
                    uint32_t ro = (wm0 + li) * 64 + coff;
                    ldsm4(ah,  tA  + ro);
                    ldsm4(al_, tAl + ro);
                }
                uint32_t bh[NF][2];
                #pragma unroll
                for (int nf2 = 0; nf2 < NF / 2; nf2++) {
                    uint32_t ro = (wn0 + nf2 * 16 + li) * 64 + coff;
                    uint32_t t[4];
                    ldsm4(t, tB + ro);
                    bh[2 * nf2][0] = t[0]; bh[2 * nf2][1] = t[2];
                    bh[2 * nf2 + 1][0] = t[1]; bh[2 * nf2 + 1][1] = t[3];
                }
                #pragma unroll
                for (int nf = 0; nf < NF; nf++) {
                    mma16816(acc[nf], ah,  bh[nf]);
                    mma16816(acc[nf], al_, bh[nf]);
                }
            }
            __syncthreads();
        }

        // fused gate nonlinearity + state update
        #pragma unroll
        for (int qsel = 0; qsel < NF / 2; qsel++) {
            const int nb = n0 + wn0 + qsel * 16;
            const int a  = lane & 3;
            const int j  = 4 * (nb >> 4) + a;
            #pragma unroll
            for (int i = 0; i < 2; i++) {
                const int m = m0 + wm0 + (lane >> 2) + 8 * i;
                const float* xrow = xgl + (size_t)m * (L_SZ * G4);
                float2 xif = *reinterpret_cast<const float2*>(xrow + nb + 2 * a);
                float2 xgo = *reinterpret_cast<const float2*>(xrow + nb + 8 + 2 * a);
                float xi = acc[2 * qsel][2 * i]         + xif.x;
                float xf = acc[2 * qsel][2 * i + 1]     + xif.y;
                float xgv = acc[2 * qsel + 1][2 * i]    + xgo.x;
                float xo = acc[2 * qsel + 1][2 * i + 1] + xgo.y;
                float ig = sigf(xi), fg = sigf(xf);
                float gg = tanhf(xgv), og = sigf(xo);
                const int gi = (m << 10) + j;
                float cv = fg * cstate[gi] + ig * gg;
                cstate[gi] = cv;
                float hv = og * tanhf(cv);
                houtf[gi] = hv;
                __half hi, lo; split_h(hv, hi, lo);
                Oh[gi] = hi; Ol[gi] = lo;
            }
        }

        __threadfence();
        __syncthreads();
        if (tid == 0) {
            atomicAdd(&g_bar, 1u);
            volatile unsigned* vb = &g_bar;
            const unsigned target = 256u * (unsigned)(l + 1);
            while (*vb < target) { }
        }
        __syncthreads();
    }
}

// ---------------- converts ---------------------------------------------------
__global__ void conv_round(const float* __restrict__ src, int C, int srcld,
                           __half* __restrict__ dst)
{
    int c4 = (blockIdx.x * blockDim.x + threadIdx.x) * 4;
    int r = blockIdx.y;
    if (c4 >= C) return;
    float4 x = *reinterpret_cast<const float4*>(src + (size_t)r * srcld + c4);
    size_t o = (size_t)r * C + c4;
    __half2 a; a.x = __float2half_rn(x.x); a.y = __float2half_rn(x.y);
    __half2 b; b.x = __float2half_rn(x.z); b.y = __float2half_rn(x.w);
    *reinterpret_cast<__half2*>(dst + o)     = a;
    *reinterpret_cast<__half2*>(dst + o + 2) = b;
}

__global__ void conv_perm_round(const float* __restrict__ src, int cols,
                                __half* __restrict__ dst)
{
    int c4 = (blockIdx.x * blockDim.x + threadIdx.x) * 4;
    int r = blockIdx.y;
    if (c4 >= cols) return;
    int gate = ((r >> 3) & 1) * 2 + (r & 1);
    int cell = 4 * (r >> 4) + ((r >> 1) & 3);
    int orig = gate * 1024 + cell;
    float4 x = *reinterpret_cast<const float4*>(src + (size_t)orig * cols + c4);
    size_t o = (size_t)r * cols + c4;
    __half2 a; a.x = __float2half_rn(x.x); a.y = __float2half_rn(x.y);
    __half2 b; b.x = __float2half_rn(x.z); b.y = __float2half_rn(x.w);
    *reinterpret_cast<__half2*>(dst + o)     = a;
    *reinterpret_cast<__half2*>(dst + o + 2) = b;
}

__global__ void prep_kernel(const float* __restrict__ Wvt,
                            const float* __restrict__ wtw,
                            const float* __restrict__ wtb,
                            const float* __restrict__ bih,
                            const float* __restrict__ bhh)
{
    int i = blockIdx.x * blockDim.x + threadIdx.x;
    if (i == 0) g_bar = 0;
    if (i < HIN) {
        const float* row = Wvt + (size_t)i * (HIN + 128) + HIN;
        float u = 0.f, ub = 0.f;
        #pragma unroll 4
        for (int j = 0; j < 128; j++) { float w = row[j]; u += w * wtw[j]; ub += w * wtb[j]; }
        g_u[i] = u; g_ub[i] = ub;
    } else if (i < HIN + G4) {
        int r = i - HIN;
        int gate = ((r >> 3) & 1) * 2 + (r & 1);
        int cell = 4 * (r >> 4) + ((r >> 1) & 3);
        g_biasp[r] = bih[gate * 1024 + cell] + bhh[gate * 1024 + cell];
    } else if (i < HIN + G4 + HIN * HIN / 4) {
        int w = i - (HIN + G4);
        int r = w >> 7;
        int c4 = (w & 127) * 4;
        float4 x = *reinterpret_cast<const float4*>(Wvt + (size_t)r * (HIN + 128) + c4);
        size_t o = (size_t)r * HIN + c4;
        __half2 a; a.x = __float2half_rn(x.x); a.y = __float2half_rn(x.y);
        __half2 b; b.x = __float2half_rn(x.z); b.y = __float2half_rn(x.w);
        *reinterpret_cast<__half2*>(g_wvt + o)     = a;
        *reinterpret_cast<__half2*>(g_wvt + o + 2) = b;
    }
}

__global__ void reduce_conv(void)
{
    int idx = blockIdx.x * 256 + threadIdx.x;
    float s = 0.f;
    #pragma unroll
    for (int z = 0; z < KSPLIT; z++) s += g_split[(size_t)z * ML * HIN + idx];
    __half hi, lo; split_h(s, hi, lo);
    g_vdh[idx] = hi; g_vdl[idx] = lo;
}

__global__ void pred_kernel(const float* __restrict__ lw,
                            const float* __restrict__ lb,
                            float* __restrict__ out)
{
    int b = blockIdx.x, tid = threadIdx.x;
    const float* hr = g_h + (size_t)b * H_SZ;
    float s = 0.f;
    for (int k = tid; k < H_SZ; k += 128) s += hr[k] * lw[k];
    __shared__ float red[128];
    red[tid] = s; __syncthreads();
    for (int off = 64; off > 0; off >>= 1) {
        if (tid < off) red[tid] += red[tid + off];
        __syncthreads();
    }
    if (tid == 0) out[b] = red[0] + lb[0];
}

// ---------------- launch -----------------------------------------------------
#define SMEM_G1   90112                          // 3*16K A32 + 3*8K B + 2*8K Ah
#define SMEM_T2   ((2 * 128 + 128) * 64 * 3)     // 73728 (2-term; >= epilogue 67584)
#define SMEM_T1   67584                          // max(pipeline 49152, epilogue 8*64*33*4)
#define SMEM_LSTM ((2 * 32 + 64) * 64 * 3)       // 24576

extern "C" void kernel_launch(void* const* d_in, const int* in_sizes, int n_in,
                              void* d_out, int out_size)
{
    const float* v   = (const float*)d_in[0];
    const float* t   = (const float*)d_in[1];
    const float* Wd  = (const float*)d_in[2];
    const float* wtw = (const float*)d_in[3];
    const float* wtb = (const float*)d_in[4];
    const float* Wvt = (const float*)d_in[5];
    const float* Wih = (const float*)d_in[6];
    const float* Whh = (const float*)d_in[7];
    const float* bih = (const float*)d_in[8];
    const float* bhh = (const float*)d_in[9];
    const float* lw  = (const float*)d_in[10];
    const float* lb  = (const float*)d_in[11];
    float* out = (float*)d_out;

    __half *p_wd, *p_vdh, *p_vdl, *p_wvt, *p_ih, *p_wih, *p_whh, *p_hh, *p_hl;
    float *p_split, *p_xg, *p_h, *p_c, *p_u, *p_ub, *p_biasp;
    cudaGetSymbolAddress((void**)&p_wd, g_wd);
    cudaGetSymbolAddress((void**)&p_vdh, g_vdh); cudaGetSymbolAddress((void**)&p_vdl, g_vdl);
    cudaGetSymbolAddress((void**)&p_wvt, g_wvt);
    cudaGetSymbolAddress((void**)&p_ih, g_ih);
    cudaGetSymbolAddress((void**)&p_wih, g_wih); cudaGetSymbolAddress((void**)&p_whh, g_whh);
    cudaGetSymbolAddress((void**)&p_hh, g_hh);   cudaGetSymbolAddress((void**)&p_hl, g_hl);
    cudaGetSymbolAddress((void**)&p_split, g_split);
    cudaGetSymbolAddress((void**)&p_xg, g_xg);
    cudaGetSymbolAddress((void**)&p_h, g_h);     cudaGetSymbolAddress((void**)&p_c, g_c);
    cudaGetSymbolAddress((void**)&p_u, g_u);     cudaGetSymbolAddress((void**)&p_ub, g_ub);
    cudaGetSymbolAddress((void**)&p_biasp, g_biasp);

    cudaFuncSetAttribute(gemm1_fused, cudaFuncAttributeMaxDynamicSharedMemorySize, SMEM_G1);
    cudaFuncSetAttribute(mma_gemm<128, 128, 64, 32, 1, 2>, cudaFuncAttributeMaxDynamicSharedMemorySize, SMEM_T2);
    cudaFuncSetAttribute(mma_gemm<128, 128, 64, 32, 2, 1>, cudaFuncAttributeMaxDynamicSharedMemorySize, SMEM_T1);
    cudaFuncSetAttribute(lstm_persist, cudaFuncAttributeMaxDynamicSharedMemorySize, SMEM_LSTM);

    // 1) prep  2) W_down round  3) W_ih perm-round
    prep_kernel<<<(HIN + G4 + HIN * HIN / 4) / 256, 256>>>(Wvt, wtw, wtb, bih, bhh);
    conv_round<<<dim3((N_SZ / 4 + 255) / 256, HIN), 256>>>(Wd, N_SZ, N_SZ, p_wd);
    conv_perm_round<<<dim3(1, G4), 256>>>(Wih, HIN, p_wih);

    // 4) GEMM1 (fused round, 1-term, convert||HMMA overlapped, split-K=4)
    gemm1_fused<<<dim3(HIN / 128, ML / 128, KSPLIT), 256, SMEM_G1>>>(
        v, N_SZ, p_wd, N_SZ, p_split, HIN, (size_t)ML * HIN);

    // 5) reduce partials -> vd fp16 split (2-term input to GEMM2)
    reduce_conv<<<(ML * HIN) / 256, 256>>>();

    // 6) GEMM2 (2-term): inputs = vd @ Wvt_s^T + t[m]*u[n] + ub[n] -> fp16 hi
    mma_gemm<128, 128, 64, 32, 1, 2><<<dim3(HIN / 128, ML / 128), 256, SMEM_T2>>>(
        p_vdh, p_vdl, HIN, p_wvt, HIN, HIN,
        nullptr, HIN, p_ub, t, p_u, p_ih);

    // 7) GEMM3 (1-term): xg = inputs_fp16 @ Wih_perm^T + bias_perm
    mma_gemm<128, 128, 64, 32, 2, 1><<<dim3(G4 / 128, ML / 128), 256, SMEM_T1>>>(
        p_ih, nullptr, HIN, p_wih, HIN, HIN,
        p_xg, G4, p_biasp, nullptr, nullptr, nullptr);

    // 8) W_hh perm-round  9) persistent LSTM steps 0..15
    conv_perm_round<<<dim3(2, G4), 256>>>(Whh, H_SZ, p_whh);
    lstm_persist<<<dim3(G4 / 64, B_SZ / 32), 128, SMEM_LSTM>>>(
        p_hh, p_hl, p_whh, p_xg, p_c, p_h, p_hh, p_hl);

    // 10) pred
    pred_kernel<<<B_SZ, 128>>>(lw, lb, out);
}

// round 12
// speedup vs baseline: 6.9030x; 1.0161x over previous
#include <cuda_runtime.h>
#include <cuda_fp16.h>
#include <cstdint>
#include <math.h>

// ---------------- dims ------------------------------------------------------
#define B_SZ 128
#define L_SZ 16
#define N_SZ 20000
#define HIN  512
#define H_SZ 1024
#define G4   4096
#define ML   2048
#define KSPLIT 4
// split-K chunks: 5024,5024,5024,4928 (all %32==0, sum 20000)

// ---------------- device global scratch ------------------------------------
__device__ __half g_wd[(size_t)HIN * N_SZ];       // W_down rounded fp16
__device__ float g_split[KSPLIT * ML * HIN];
__device__ __half g_vdh[ML * HIN];                // vd split
__device__ __half g_vdl[ML * HIN];
__device__ __half g_wvt[HIN * HIN];               // W_vt[:, :512] rounded
__device__ __half g_ih[ML * HIN];                 // inputs (hi, exact round)
__device__ __half g_wih[G4 * HIN];                // W_ih permuted rounded
__device__ __half g_whh[(size_t)G4 * H_SZ];       // W_hh permuted rounded
__device__ float g_xg[(size_t)ML * G4];           // permuted gate cols
__device__ __half g_hh[2 * B_SZ * H_SZ];          // h split, double buffered
__device__ __half g_hl[2 * B_SZ * H_SZ];
__device__ float g_h[B_SZ * H_SZ];
__device__ float g_c[B_SZ * H_SZ];
__device__ float g_u[HIN];
__device__ float g_ub[HIN];
__device__ float g_biasp[G4];
__device__ unsigned g_bar;

// ---------------- helpers ---------------------------------------------------
__device__ __forceinline__ uint32_t smem_u32(const void* p) {
    uint32_t a;
    asm("{ .reg .u64 t; cvta.to.shared.u64 t, %1; cvt.u32.u64 %0, t; }" : "=r"(a) : "l"(p));
    return a;
}
__device__ __forceinline__ void cp_async16(uint32_t dst, const void* src) {
    asm volatile("cp.async.cg.shared.global [%0], [%1], 16;" :: "r"(dst), "l"(src));
}
__device__ __forceinline__ void cp_commit() {
    asm volatile("cp.async.commit_group;" ::: "memory");
}
__device__ __forceinline__ void cp_wait1() {
    asm volatile("cp.async.wait_group 1;" ::: "memory");
}
__device__ __forceinline__ void cp_wait2() {
    asm volatile("cp.async.wait_group 2;" ::: "memory");
}
__device__ __forceinline__ void ldsm4(uint32_t* r, uint32_t addr) {
    asm volatile("ldmatrix.sync.aligned.m8n8.x4.shared.b16 {%0,%1,%2,%3}, [%4];"
        : "=r"(r[0]), "=r"(r[1]), "=r"(r[2]), "=r"(r[3]) : "r"(addr));
}
__device__ __forceinline__ void mma16816(float* c, const uint32_t* a, const uint32_t* b) {
    asm volatile("mma.sync.aligned.m16n8k16.row.col.f32.f16.f16.f32 "
        "{%0,%1,%2,%3}, {%4,%5,%6,%7}, {%8,%9}, {%0,%1,%2,%3};"
        : "+f"(c[0]), "+f"(c[1]), "+f"(c[2]), "+f"(c[3])
        : "r"(a[0]), "r"(a[1]), "r"(a[2]), "r"(a[3]), "r"(b[0]), "r"(b[1]));
}
__device__ __forceinline__ float sigf(float x) { return 1.f / (1.f + expf(-x)); }
__device__ __forceinline__ void split_h(float x, __half& hi, __half& lo) {
    hi = __float2half_rn(x);
    lo = __float2half_rn(x - __half2float(hi));
}
__device__ __forceinline__ uint32_t pack2(float a, float b) {
    __half2 t; t.x = __float2half_rn(a); t.y = __float2half_rn(b);
    return *reinterpret_cast<uint32_t*>(&t);
}

// fp16 smem tile (64B rows):  16B chunk c of row r at r*64 + ((c*16) ^ (((r>>1)&3)<<4))
// fp16 smem tile (128B rows): 16B chunk c of row r at r*128 + ((c ^ (r&7))<<4)

// ---------------- GEMM1: LDG->reg fp32, convert->fp16 STS, 1-term HMMA ------
// A never touches smem as fp32. B via cp.async ring-3. Ah double-buffered.
// Iter kt: loadB(kt+2); wait1; sync1; [convert(pa->Ah[(kt+1)&1]); LDGA(kt+2)->pa]
//          HMMA(kt) from Ah[kt&1]+B[kt%3]; sync2.
__global__ void __launch_bounds__(256, 2)
gemm1_fused(const float* __restrict__ Afp, int lda,
            const __half* __restrict__ Bm, int ldb,
            float* __restrict__ C, int ldc, size_t zstride)
{
    constexpr int BM = 128, BN = 128, WM = 64, WN = 32, MF = 4, NF = 4;
    constexpr int B16S = 128 * 64;                 // 8192 per B stage
    constexpr int OFF_AH = 3 * B16S;               // 24576; Ah[2] -> 40960 pipeline

    extern __shared__ char smem[];
    const uint32_t sbase = smem_u32(smem);
    const int tid  = threadIdx.x;
    const int lane = tid & 31;
    const int warp = tid >> 5;
    const int wm0 = (warp / (BN / WN)) * WM;
    const int wn0 = (warp % (BN / WN)) * WN;
    const int m0 = blockIdx.y * BM;
    const int n0 = blockIdx.x * BN;
    const int kbase = blockIdx.z * 5024;
    const int Kz = (blockIdx.z == 3) ? 4928 : 5024;
    C += (size_t)blockIdx.z * zstride;

    float acc[MF][NF][4];
    #pragma unroll
    for (int i = 0; i < MF; i++)
        #pragma unroll
        for (int j = 0; j < NF; j++)
            #pragma unroll
            for (int q = 0; q < 4; q++) acc[i][j][q] = 0.f;

    auto loadB = [&](int kt) {
        const int k0 = kbase + kt * 32;
        const uint32_t tb = sbase + (kt % 3) * B16S;
        #pragma unroll
        for (int q = 0; q < 2; q++) {
            const int i = tid + q * 256;
            int row = i >> 2, c = i & 3;
            uint32_t dst = tb + row * 64 + ((c * 16) ^ (((row >> 1) & 3) << 4));
            cp_async16(dst, Bm + (size_t)(n0 + row) * ldb + k0 + c * 8);
        }
    };

    float4 pa[4];
    auto ldga = [&](int kt) {
        const int k0 = kbase + kt * 32;
        #pragma unroll
        for (int q = 0; q < 4; q++) {
            const int i = tid + q * 256;
            int row = i >> 3, c = i & 7;
            pa[q] = *reinterpret_cast<const float4*>(
                Afp + (size_t)(m0 + row) * lda + k0 + c * 4);
        }
    };
    auto convert = [&](int kt) {
        char* ahb = smem + OFF_AH + (kt & 1) * 8192;
        #pragma unroll
        for (int q = 0; q < 4; q++) {
            const int i = tid + q * 256;
            int row = i >> 3, c = i & 7;
            uint2 p;
            p.x = pack2(pa[q].x, pa[q].y);
            p.y = pack2(pa[q].z, pa[q].w);
            uint32_t so = row * 64 + (((c >> 1) * 16) ^ (((row >> 1) & 3) << 4)) + (c & 1) * 8;
            *reinterpret_cast<uint2*>(ahb + so) = p;
        }
    };

    const int KT = Kz >> 5;
    loadB(0); cp_commit();
    loadB(1); cp_commit();
    ldga(0);
    convert(0);             // Ah[0] (own-thread regs; visibility via sync1 of iter 0)
    ldga(1);                // pa now holds stage 1

    const int li  = lane & 15;
    const int khb = (lane >> 4) << 4;
    const int swz = ((li >> 1) & 3) << 4;

    for (int kt = 0; kt < KT; kt++) {
        if (kt + 2 < KT) loadB(kt + 2);
        cp_commit();        // unconditional -> uniform group counting
        cp_wait1();         // B stages kt, kt+1 resident
        __syncthreads();    // sync1: Ah[kt&1] + B[kt%3] visible; all past HMMA(kt-1)

        if (kt + 1 < KT) {
            convert(kt + 1);                    // pa(stage kt+1) -> Ah[(kt+1)&1]
            if (kt + 2 < KT) ldga(kt + 2);      // refill pa (guarded: no OOB)
        }

        // HMMA(kt)
        {
            const uint32_t tAh = sbase + OFF_AH + (kt & 1) * 8192;
            const uint32_t tB  = sbase + (kt % 3) * B16S;
            #pragma unroll
            for (int kk = 0; kk < 2; kk++) {
                const int cb = kk * 32;
                const uint32_t coff = (uint32_t)((cb + khb) ^ swz);
                uint32_t ah[MF][4];
                #pragma unroll
                for (int mf = 0; mf < MF; mf++) {
                    uint32_t ro = (wm0 + mf * 16 + li) * 64 + coff;
                    ldsm4(ah[mf], tAh + ro);
                }
                uint32_t bh[NF][2];
                #pragma unroll
                for (int nf2 = 0; nf2 < NF / 2; nf2++) {
                    uint32_t ro = (wn0 + nf2 * 16 + li) * 64 + coff;
                    uint32_t t[4];
                    ldsm4(t, tB + ro);
                    bh[2 * nf2][0] = t[0]; bh[2 * nf2][1] = t[2];
                    bh[2 * nf2 + 1][0] = t[1]; bh[2 * nf2 + 1][1] = t[3];
                }
                #pragma unroll
                for (int mf = 0; mf < MF; mf++)
                    #pragma unroll
                    for (int nf = 0; nf < NF; nf++)
                        mma16816(acc[mf][nf], ah[mf], bh[nf]);
            }
        }
        __syncthreads();    // sync2: Ah[(kt+1)&1] committed; B[kt%3] reads done
    }

    // ---- epilogue: fp32 partials, coalesced ----
    float* st = reinterpret_cast<float*>(smem) + warp * (WM * 33);
    #pragma unroll
    for (int mf = 0; mf < MF; mf++)
        #pragma unroll
        for (int nf = 0; nf < NF; nf++)
            #pragma unroll
            for (int i = 0; i < 2; i++) {
                int r = mf * 16 + (lane >> 2) + 8 * i;
                int c = nf * 8 + 2 * (lane & 3);
                st[r * 33 + c]     = acc[mf][nf][2 * i];
                st[r * 33 + c + 1] = acc[mf][nf][2 * i + 1];
            }
    __syncwarp();
    #pragma unroll
    for (int rr = lane; rr < WM; rr += 32) {
        const int m = m0 + wm0 + rr;
        #pragma unroll
        for (int c4 = 0; c4 < WN; c4 += 4) {
            float4 v;
            v.x = st[rr * 33 + c4];     v.y = st[rr * 33 + c4 + 1];
            v.z = st[rr * 33 + c4 + 2]; v.w = st[rr * 33 + c4 + 3];
            *reinterpret_cast<float4*>(C + (size_t)m * ldc + n0 + wn0 + c4) = v;
        }
    }
}

// ---------------- generic fp16 GEMM (modes 1,2; 1 or 2 A terms) — R7 proven -
template<int BM, int BN, int WM, int WN, int MODE, int TERMS>
__global__ void __launch_bounds__((BM / WM) * (BN / WN) * 32)
mma_gemm(const __half* __restrict__ Ah, const __half* __restrict__ Al, int lda,
         const __half* __restrict__ Bm, int ldb, int K,
         float* __restrict__ C, int ldc,
         const float* __restrict__ bias,
         const float* __restrict__ srow, const float* __restrict__ ucol,
         __half* __restrict__ Ch)
{
    constexpr int NT = (BM / WM) * (BN / WN) * 32;
    constexpr int MF = WM / 16;
    constexpr int NF = WN / 8;
    constexpr int STAGE = (TERMS * BM + BN) * 64;
    constexpr int CHA = BM * 4;
    constexpr int CHB = BN * 4;
    constexpr int CHT = TERMS * CHA + CHB;

    extern __shared__ char smem[];
    const uint32_t sbase = smem_u32(smem);
    const int tid  = threadIdx.x;
    const int lane = tid & 31;
    const int warp = tid >> 5;
    const int wm0 = (warp / (BN / WN)) * WM;
    const int wn0 = (warp % (BN / WN)) * WN;
    const int m0 = blockIdx.y * BM;
    const int n0 = blockIdx.x * BN;

    float acc[MF][NF][4];
    #pragma unroll
    for (int i = 0; i < MF; i++)
        #pragma unroll
        for (int j = 0; j < NF; j++)
            #pragma unroll
            for (int q = 0; q < 4; q++) acc[i][j][q] = 0.f;

    auto load_stage = [&](int kt, int s) {
        const int k0 = kt * 32;
        const uint32_t tb = sbase + s * STAGE;
        #pragma unroll
        for (int q = 0; q < CHT / NT; q++) {
            const int i = tid + q * NT;
            const __half* src;
            int toff, rr;
            if (i < CHA) {
                rr = i >> 2; src = Ah + (size_t)(m0 + rr) * lda; toff = 0;
            } else if (TERMS == 2 && i < 2 * CHA) {
                int j = i - CHA; rr = j >> 2;
                src = Al + (size_t)(m0 + rr) * lda; toff = BM * 64;
            } else {
                int j = i - TERMS * CHA; rr = j >> 2;
                src = Bm + (size_t)(n0 + rr) * ldb; toff = TERMS * BM * 64;
            }
            const int c = i & 3;
            uint32_t dst = tb + toff + rr * 64 + ((c * 16) ^ (((rr >> 1) & 3) << 4));
            cp_async16(dst, src + k0 + c * 8);
        }
    };

    const int KT = K >> 5;
    load_stage(0, 0); cp_commit();
    load_stage(1, 1); cp_commit();

    const int li  = lane & 15;
    const int khb = (lane >> 4) << 4;
    const int swz = ((li >> 1) & 3) << 4;

    for (int kt = 0; kt < KT; kt++) {
        const int s = kt % 3;
        if (kt + 2 < KT) load_stage(kt + 2, (kt + 2) % 3);
        cp_commit();
        cp_wait2();
        __syncthreads();

        const uint32_t tA  = sbase + s * STAGE;
        const uint32_t tAl = tA + BM * 64;
        const uint32_t tB  = tA + TERMS * BM * 64;

        #pragma unroll
        for (int kk = 0; kk < 2; kk++) {
            const int cb = kk * 32;
            const uint32_t coff = (uint32_t)((cb + khb) ^ swz);
            uint32_t ah[MF][4], al_[MF][4];
            #pragma unroll
            for (int mf = 0; mf < MF; mf++) {
                uint32_t ro = (wm0 + mf * 16 + li) * 64 + coff;
                ldsm4(ah[mf], tA + ro);
                if (TERMS == 2) ldsm4(al_[mf], tAl + ro);
            }
            uint32_t bh[NF][2];
            #pragma unroll
            for (int nf2 = 0; nf2 < NF / 2; nf2++) {
                uint32_t ro = (wn0 + nf2 * 16 + li) * 64 + coff;
                uint32_t t[4];
                ldsm4(t, tB + ro);
                bh[2 * nf2][0] = t[0]; bh[2 * nf2][1] = t[2];
                bh[2 * nf2 + 1][0] = t[1]; bh[2 * nf2 + 1][1] = t[3];
            }
            #pragma unroll
            for (int mf = 0; mf < MF; mf++)
                #pragma unroll
                for (int nf = 0; nf < NF; nf++) {
                    mma16816(acc[mf][nf], ah[mf], bh[nf]);
                    if (TERMS == 2) mma16816(acc[mf][nf], al_[mf], bh[nf]);
                }
        }
        __syncthreads();
    }

    float* st = reinterpret_cast<float*>(smem) + warp * (WM * 33);
    #pragma unroll
    for (int mf = 0; mf < MF; mf++)
        #pragma unroll
        for (int nf = 0; nf < NF; nf++)
            #pragma unroll
            for (int i = 0; i < 2; i++) {
                int r = mf * 16 + (lane >> 2) + 8 * i;
                int c = nf * 8 + 2 * (lane & 3);
                st[r * 33 + c]     = acc[mf][nf][2 * i];
                st[r * 33 + c + 1] = acc[mf][nf][2 * i + 1];
            }
    __syncwarp();
    #pragma unroll
    for (int rr = lane; rr < WM; rr += 32) {
        const int m = m0 + wm0 + rr;
        const int nbase = n0 + wn0;
        if (MODE == 1) {
            const float tm = srow[m];
            #pragma unroll
            for (int c = 0; c < WN; c += 2) {
                int n = nbase + c;
                float v0 = st[rr * 33 + c]     + tm * ucol[n]     + bias[n];
                float v1 = st[rr * 33 + c + 1] + tm * ucol[n + 1] + bias[n + 1];
                __half2 ph;
                ph.x = __float2half_rn(v0); ph.y = __float2half_rn(v1);
                *reinterpret_cast<__half2*>(Ch + (size_t)m * ldc + n) = ph;
            }
        } else {
            #pragma unroll
            for (int c4 = 0; c4 < WN; c4 += 4) {
                float4 v;
                v.x = st[rr * 33 + c4];
                v.y = st[rr * 33 + c4 + 1];
                v.z = st[rr * 33 + c4 + 2];
                v.w = st[rr * 33 + c4 + 3];
                int n = nbase + c4;
                v.x += bias[n]; v.y += bias[n + 1];
                v.z += bias[n + 2]; v.w += bias[n + 3];
                *reinterpret_cast<float4*>(C + (size_t)m * ldc + nbase + c4) = v;
            }
        }
    }
}

// ---------------- persistent fused LSTM, BK=64 (steps 0..15) -----------------
// 128B-row SW128 tiles; 16 k-stages per step; same proven 2-sync/stage loop.
__global__ void __launch_bounds__(128)
lstm_persist(const __half* __restrict__ hhb, const __half* __restrict__ hlb,
             const __half* __restrict__ Bm,
             const float* __restrict__ xg, float* __restrict__ cstate,
             float* __restrict__ houtf,
             __half* __restrict__ hhw, __half* __restrict__ hlw)
{
    constexpr int BM = 32, BN = 64, NT = 128, NF = 4;
    constexpr int STAGE = (2 * BM + BN) * 128;   // 16384
    constexpr int CHA = BM * 8, CHB = BN * 8, CHT = 2 * CHA + CHB;  // 1024 chunks

    extern __shared__ char smem[];
    const uint32_t sbase = smem_u32(smem);
    const int tid  = threadIdx.x;
    const int lane = tid & 31;
    const int warp = tid >> 5;
    const int wm0 = (warp >> 1) * 16;
    const int wn0 = (warp & 1) * 32;
    const int m0 = blockIdx.y * BM;
    const int n0 = blockIdx.x * BN;
    const int li  = lane & 15;
    const int qhb = lane >> 4;                   // k-half chunk select

    // ---- step 0: h=c=0, gates = xg row ----
    {
        __half* Oh = hhw;
        __half* Ol = hlw;
        const float* xgl = xg;
        #pragma unroll
        for (int qsel = 0; qsel < NF / 2; qsel++) {
            const int nb = n0 + wn0 + qsel * 16;
            const int a  = lane & 3;
            const int j  = 4 * (nb >> 4) + a;
            #pragma unroll
            for (int i = 0; i < 2; i++) {
                const int m = m0 + wm0 + (lane >> 2) + 8 * i;
                const float* xrow = xgl + (size_t)m * (L_SZ * G4);
                float2 xif = *reinterpret_cast<const float2*>(xrow + nb + 2 * a);
                float2 xgo = *reinterpret_cast<const float2*>(xrow + nb + 8 + 2 * a);
                float ig = sigf(xif.x);
                float gg = tanhf(xgo.x), og = sigf(xgo.y);
                const int gi = (m << 10) + j;
                float cv = ig * gg;
                cstate[gi] = cv;
                float hv = og * tanhf(cv);
                __half hi, lo; split_h(hv, hi, lo);
                Oh[gi] = hi; Ol[gi] = lo;
            }
        }
        __threadfence();
        __syncthreads();
        if (tid == 0) {
            atomicAdd(&g_bar, 1u);
            volatile unsigned* vb = &g_bar;
            while (*vb < 256u) { }
        }
        __syncthreads();
    }

    for (int l = 1; l < L_SZ; l++) {
        const __half* Ah = hhb + (size_t)((l + 1) & 1) * (B_SZ * H_SZ);
        const __half* Al = hlb + (size_t)((l + 1) & 1) * (B_SZ * H_SZ);
        __half* Oh = hhw + (size_t)(l & 1) * (B_SZ * H_SZ);
        __half* Ol = hlw + (size_t)(l & 1) * (B_SZ * H_SZ);
        const float* xgl = xg + (size_t)l * G4;

        float acc[NF][4];
        #pragma unroll
        for (int j = 0; j < NF; j++)
            #pragma unroll
            for (int q = 0; q < 4; q++) acc[j][q] = 0.f;

        auto load_stage = [&](int kt, int s) {
            const int k0 = kt * 64;
            const uint32_t tb = sbase + s * STAGE;
            #pragma unroll
            for (int q = 0; q < CHT / NT; q++) {
                const int i = tid + q * NT;
                const __half* src;
                int toff, rr;
                if (i < CHA) {
                    rr = i >> 3; src = Ah + (size_t)(m0 + rr) * H_SZ; toff = 0;
                } else if (i < 2 * CHA) {
                    int j = i - CHA; rr = j >> 3;
                    src = Al + (size_t)(m0 + rr) * H_SZ; toff = BM * 128;
                } else {
                    int j = i - 2 * CHA; rr = j >> 3;
                    src = Bm + (size_t)(n0 + rr) * H_SZ; toff = 2 * BM * 128;
                }
                const int c = i & 7;
                uint32_t dst = tb + toff + rr * 128 + ((c ^ (rr & 7)) << 4);
                cp_async16(dst, src + k0 + c * 8);
            }
        };

        const int KT = H_SZ >> 6;   // 16
        load_stage(0, 0); cp_commit();
        load_stage(1, 1); cp_commit();

        for (int kt = 0; kt < KT; kt++) {
            const int s = kt % 3;
            if (kt + 2 < KT) load_stage(kt + 2, (kt + 2) % 3);
            cp_commit();
            cp_wait2();
            __syncthreads();

            const uint32_t tA  = sbase + s * STAGE;
            const uint32_t tAl = tA + BM * 128;
            const uint32_t tB  = tA + 2 * BM * 128;

            #pragma unroll
            for (int kk = 0; kk < 4; kk++) {
                const int q = kk * 2 + qhb;
                const uint32_t sw = (uint32_t)((q ^ (li & 7)) << 4);
                uint32_t ah[4], al_[4];
                {
                    uint32_t ro = (wm0 + li) * 128 + sw;
                    ldsm4(ah,  tA  + ro);
                    ldsm4(al_, tAl + ro);
                }
                uint32_t bh[NF][2];
                #pragma unroll
                for (int nf2 = 0; nf2 < NF / 2; nf2++) {
                    uint32_t ro = (wn0 + nf2 * 16 + li) * 128 + sw;
                    uint32_t t[4];
                    ldsm4(t, tB + ro);
                    bh[2 * nf2][0] = t[0]; bh[2 * nf2][1] = t[2];
                    bh[2 * nf2 + 1][0] = t[1]; bh[2 * nf2 + 1][1] = t[3];
                }
                #pragma unroll
                for (int nf = 0; nf < NF; nf++) {
                    mma16816(acc[nf], ah,  bh[nf]);
                    mma16816(acc[nf], al_, bh[nf]);
                }
            }
            __syncthreads();
        }

        // fused gate nonlinearity + state update
        #pragma unroll
        for (int qsel = 0; qsel < NF / 2; qsel++) {
            const int nb = n0 + wn0 + qsel * 16;
            const int a  = lane & 3;
            const int j  = 4 * (nb >> 4) + a;
            #pragma unroll
            for (int i = 0; i < 2; i++) {
                const int m = m0 + wm0 + (lane >> 2) + 8 * i;
                const float* xrow = xgl + (size_t)m * (L_SZ * G4);
                float2 xif = *reinterpret_cast<const float2*>(xrow + nb + 2 * a);
                float2 xgo = *reinterpret_cast<const float2*>(xrow + nb + 8 + 2 * a);
                float xi = acc[2 * qsel][2 * i]         + xif.x;
                float xf = acc[2 * qsel][2 * i + 1]     + xif.y;
                float xgv = acc[2 * qsel + 1][2 * i]    + xgo.x;
                float xo = acc[2 * qsel + 1][2 * i + 1] + xgo.y;
                float ig = sigf(xi), fg = sigf(xf);
                float gg = tanhf(xgv), og = sigf(xo);
                const int gi = (m << 10) + j;
                float cv = fg * cstate[gi] + ig * gg;
                cstate[gi] = cv;
                float hv = og * tanhf(cv);
                houtf[gi] = hv;
                __half hi, lo; split_h(hv, hi, lo);
                Oh[gi] = hi; Ol[gi] = lo;
            }
        }

        __threadfence();
        __syncthreads();
        if (tid == 0) {
            atomicAdd(&g_bar, 1u);
            volatile unsigned* vb = &g_bar;
            const unsigned target = 256u * (unsigned)(l + 1);
            while (*vb < target) { }
        }
        __syncthreads();
    }
}

// ---------------- converts (8 floats/thread, 16B stores) ---------------------
__global__ void conv_round(const float* __restrict__ src, int C, int srcld,
                           __half* __restrict__ dst)
{
    int c8 = (blockIdx.x * blockDim.x + threadIdx.x) * 8;
    int r = blockIdx.y;
    if (c8 >= C) return;
    float4 x0 = *reinterpret_cast<const float4*>(src + (size_t)r * srcld + c8);
    float4 x1 = *reinterpret_cast<const float4*>(src + (size_t)r * srcld + c8 + 4);
    uint4 p;
    p.x = pack2(x0.x, x0.y); p.y = pack2(x0.z, x0.w);
    p.z = pack2(x1.x, x1.y); p.w = pack2(x1.z, x1.w);
    *reinterpret_cast<uint4*>(dst + (size_t)r * C + c8) = p;
}

__global__ void conv_perm_round(const float* __restrict__ src, int cols,
                                __half* __restrict__ dst)
{
    int c8 = (blockIdx.x * blockDim.x + threadIdx.x) * 8;
    int r = blockIdx.y;
    if (c8 >= cols) return;
    int gate = ((r >> 3) & 1) * 2 + (r & 1);
    int cell = 4 * (r >> 4) + ((r >> 1) & 3);
    int orig = gate * 1024 + cell;
    float4 x0 = *reinterpret_cast<const float4*>(src + (size_t)orig * cols + c8);
    float4 x1 = *reinterpret_cast<const float4*>(src + (size_t)orig * cols + c8 + 4);
    uint4 p;
    p.x = pack2(x0.x, x0.y); p.y = pack2(x0.z, x0.w);
    p.z = pack2(x1.x, x1.y); p.w = pack2(x1.z, x1.w);
    *reinterpret_cast<uint4*>(dst + (size_t)r * cols + c8) = p;
}

__global__ void prep_kernel(const float* __restrict__ Wvt,
                            const float* __restrict__ wtw,
                            const float* __restrict__ wtb,
                            const float* __restrict__ bih,
                            const float* __restrict__ bhh)
{
    int i = blockIdx.x * blockDim.x + threadIdx.x;
    if (i == 0) g_bar = 0;
    if (i < HIN) {
        const float* row = Wvt + (size_t)i * (HIN + 128) + HIN;
        float u = 0.f, ub = 0.f;
        #pragma unroll 4
        for (int j = 0; j < 128; j++) { float w = row[j]; u += w * wtw[j]; ub += w * wtb[j]; }
        g_u[i] = u; g_ub[i] = ub;
    } else if (i < HIN + G4) {
        int r = i - HIN;
        int gate = ((r >> 3) & 1) * 2 + (r & 1);
        int cell = 4 * (r >> 4) + ((r >> 1) & 3);
        g_biasp[r] = bih[gate * 1024 + cell] + bhh[gate * 1024 + cell];
    } else if (i < HIN + G4 + HIN * HIN / 8) {
        int w = i - (HIN + G4);
        int r = w >> 6;                 // 64 groups of 8 per 512-col row
        int c8 = (w & 63) * 8;
        float4 x0 = *reinterpret_cast<const float4*>(Wvt + (size_t)r * (HIN + 128) + c8);
        float4 x1 = *reinterpret_cast<const float4*>(Wvt + (size_t)r * (HIN + 128) + c8 + 4);
        uint4 p;
        p.x = pack2(x0.x, x0.y); p.y = pack2(x0.z, x0.w);
        p.z = pack2(x1.x, x1.y); p.w = pack2(x1.z, x1.w);
        *reinterpret_cast<uint4*>(g_wvt + (size_t)r * HIN + c8) = p;
    }
}

__global__ void reduce_conv(void)
{
    int idx = blockIdx.x * 256 + threadIdx.x;
    float s = 0.f;
    #pragma unroll
    for (int z = 0; z < KSPLIT; z++) s += g_split[(size_t)z * ML * HIN + idx];
    __half hi, lo; split_h(s, hi, lo);
    g_vdh[idx] = hi; g_vdl[idx] = lo;
}

__global__ void pred_kernel(const float* __restrict__ lw,
                            const float* __restrict__ lb,
                            float* __restrict__ out)
{
    int b = blockIdx.x, tid = threadIdx.x;
    const float* hr = g_h + (size_t)b * H_SZ;
    float s = 0.f;
    for (int k = tid; k < H_SZ; k += 128) s += hr[k] * lw[k];
    __shared__ float red[128];
    red[tid] = s; __syncthreads();
    for (int off = 64; off > 0; off >>= 1) {
        if (tid < off) red[tid] += red[tid + off];
        __syncthreads();
    }
    if (tid == 0) out[b] = red[0] + lb[0];
}

// ---------------- launch -----------------------------------------------------
#define SMEM_G1   67584                          // max(pipeline 40960, epilogue 8*64*33*4)
#define SMEM_T2   ((2 * 128 + 128) * 64 * 3)     // 73728
#define SMEM_T1   67584
#define SMEM_LSTM ((2 * 32 + 64) * 128 * 3)      // 49152

extern "C" void kernel_launch(void* const* d_in, const int* in_sizes, int n_in,
                              void* d_out, int out_size)
{
    const float* v   = (const float*)d_in[0];
    const float* t   = (const float*)d_in[1];
    const float* Wd  = (const float*)d_in[2];
    const float* wtw = (const float*)d_in[3];
    const float* wtb = (const float*)d_in[4];
    const float* Wvt = (const float*)d_in[5];
    const float* Wih = (const float*)d_in[6];
    const float* Whh = (const float*)d_in[7];
    const float* bih = (const float*)d_in[8];
    const float* bhh = (const float*)d_in[9];
    const float* lw  = (const float*)d_in[10];
    const float* lb  = (const float*)d_in[11];
    float* out = (float*)d_out;

    __half *p_wd, *p_vdh, *p_vdl, *p_wvt, *p_ih, *p_wih, *p_whh, *p_hh, *p_hl;
    float *p_split, *p_xg, *p_h, *p_c, *p_u, *p_ub, *p_biasp;
    cudaGetSymbolAddress((void**)&p_wd, g_wd);
    cudaGetSymbolAddress((void**)&p_vdh, g_vdh); cudaGetSymbolAddress((void**)&p_vdl, g_vdl);
    cudaGetSymbolAddress((void**)&p_wvt, g_wvt);
    cudaGetSymbolAddress((void**)&p_ih, g_ih);
    cudaGetSymbolAddress((void**)&p_wih, g_wih); cudaGetSymbolAddress((void**)&p_whh, g_whh);
    cudaGetSymbolAddress((void**)&p_hh, g_hh);   cudaGetSymbolAddress((void**)&p_hl, g_hl);
    cudaGetSymbolAddress((void**)&p_split, g_split);
    cudaGetSymbolAddress((void**)&p_xg, g_xg);
    cudaGetSymbolAddress((void**)&p_h, g_h);     cudaGetSymbolAddress((void**)&p_c, g_c);
    cudaGetSymbolAddress((void**)&p_u, g_u);     cudaGetSymbolAddress((void**)&p_ub, g_ub);
    cudaGetSymbolAddress((void**)&p_biasp, g_biasp);

    cudaFuncSetAttribute(gemm1_fused, cudaFuncAttributeMaxDynamicSharedMemorySize, SMEM_G1);
    cudaFuncSetAttribute(mma_gemm<128, 128, 64, 32, 1, 2>, cudaFuncAttributeMaxDynamicSharedMemorySize, SMEM_T2);
    cudaFuncSetAttribute(mma_gemm<128, 128, 64, 32, 2, 1>, cudaFuncAttributeMaxDynamicSharedMemorySize, SMEM_T1);
    cudaFuncSetAttribute(lstm_persist, cudaFuncAttributeMaxDynamicSharedMemorySize, SMEM_LSTM);

    // 1) prep  2) W_down round  3) W_ih perm-round
    prep_kernel<<<(HIN + G4 + HIN * HIN / 8 + 255) / 256, 256>>>(Wvt, wtw, wtb, bih, bhh);
    conv_round<<<dim3((N_SZ / 8 + 255) / 256, HIN), 256>>>(Wd, N_SZ, N_SZ, p_wd);
    conv_perm_round<<<dim3(1, G4), 256>>>(Wih, HIN, p_wih);

    // 4) GEMM1 (LDG-reg convert, 1-term, split-K=4)
    gemm1_fused<<<dim3(HIN / 128, ML / 128, KSPLIT), 256, SMEM_G1>>>(
        v, N_SZ, p_wd, N_SZ, p_split, HIN, (size_t)ML * HIN);

    // 5) reduce partials -> vd fp16 split
    reduce_conv<<<(ML * HIN) / 256, 256>>>();

    // 6) GEMM2 (2-term): inputs = vd @ Wvt_s^T + t[m]*u[n] + ub[n] -> fp16 hi
    mma_gemm<128, 128, 64, 32, 1, 2><<<dim3(HIN / 128, ML / 128), 256, SMEM_T2>>>(
        p_vdh, p_vdl, HIN, p_wvt, HIN, HIN,
        nullptr, HIN, p_ub, t, p_u, p_ih);

    // 7) GEMM3 (1-term): xg = inputs_fp16 @ Wih_perm^T + bias_perm
    mma_gemm<128, 128, 64, 32, 2, 1><<<dim3(G4 / 128, ML / 128), 256, SMEM_T1>>>(
        p_ih, nullptr, HIN, p_wih, HIN, HIN,
        p_xg, G4, p_biasp, nullptr, nullptr, nullptr);

    // 8) W_hh perm-round  9) persistent LSTM steps 0..15 (BK=64)
    conv_perm_round<<<dim3(1, G4), 256>>>(Whh, H_SZ, p_whh);
    lstm_persist<<<dim3(G4 / 64, B_SZ / 32), 128, SMEM_LSTM>>>(
        p_hh, p_hl, p_whh, p_xg, p_c, p_h, p_hh, p_hl);

    // 10) pred
    pred_kernel<<<B_SZ, 128>>>(lw, lb, out);
}